// round 9
// baseline (speedup 1.0000x reference)
#include <cuda_runtime.h>
#include <cuda_bf16.h>
#include <cstdint>
#include <math.h>

#define D_MODEL 1024
#define N_HEADS 16
#define DH      64
#define BATCH   2
#define SEQ     2048
#define M_ROWS  (BATCH*SEQ)   // 4096

// ---------------- scratch (static device globals; no allocations) ----------
__device__ float g_Q  [M_ROWS*D_MODEL];   // aliased: Qh/Ql bf16
__device__ float g_K  [M_ROWS*D_MODEL];   // aliased: Kh/Kl bf16
__device__ float g_V  [M_ROWS*D_MODEL];   // aliased: VTh/VTl bf16 (transposed per head)
__device__ float g_U  [M_ROWS*D_MODEL];
__device__ float g_AO [M_ROWS*D_MODEL];
__device__ float g_O  [M_ROWS*D_MODEL];

__device__ __nv_bfloat16 g_A1h[M_ROWS*D_MODEL];
__device__ __nv_bfloat16 g_A1l[M_ROWS*D_MODEL];
__device__ __nv_bfloat16 g_A2h[M_ROWS*D_MODEL];
__device__ __nv_bfloat16 g_A2l[M_ROWS*D_MODEL];

__device__ __nv_bfloat16 g_WTh[8*1024*1024];
__device__ __nv_bfloat16 g_WTl[8*1024*1024];

#define W1M (1024*1024)

__device__ __forceinline__ float siluf(float z) {
    return z * (1.0f / (1.0f + __expf(-z)));
}

__device__ __forceinline__ uint32_t smem_u32(const void* p) {
    uint32_t a;
    asm("{ .reg .u64 t; cvta.to.shared.u64 t, %1; cvt.u32.u64 %0, t; }" : "=r"(a) : "l"(p));
    return a;
}

__device__ __forceinline__ void ldsm_x4(uint32_t* r, uint32_t a) {
    asm volatile("ldmatrix.sync.aligned.m8n8.x4.shared.b16 {%0,%1,%2,%3}, [%4];"
                 : "=r"(r[0]), "=r"(r[1]), "=r"(r[2]), "=r"(r[3]) : "r"(a));
}

__device__ __forceinline__ void mma16816(float* c, const uint32_t* a, uint32_t b0, uint32_t b1) {
    asm volatile("mma.sync.aligned.m16n8k16.row.col.f32.bf16.bf16.f32 "
                 "{%0,%1,%2,%3}, {%4,%5,%6,%7}, {%8,%9}, {%0,%1,%2,%3};"
                 : "+f"(c[0]), "+f"(c[1]), "+f"(c[2]), "+f"(c[3])
                 : "r"(a[0]), "r"(a[1]), "r"(a[2]), "r"(a[3]), "r"(b0), "r"(b1));
}

__device__ __forceinline__ void cp16(uint32_t dst, const void* src) {
    asm volatile("cp.async.cg.shared.global [%0], [%1], 16;" :: "r"(dst), "l"(src));
}
__device__ __forceinline__ void cp_commit() { asm volatile("cp.async.commit_group;"); }
__device__ __forceinline__ void cp_wait1()  { asm volatile("cp.async.wait_group 1;"); }
__device__ __forceinline__ void cp_wait0()  { asm volatile("cp.async.wait_group 0;"); }

__device__ __forceinline__ void split_bf16(float v, __nv_bfloat16& h, __nv_bfloat16& l) {
    h = __float2bfloat16(v);
    l = __float2bfloat16(v - __bfloat162float(h));
}

__device__ __forceinline__ uint32_t pack_bf16(__nv_bfloat16 a, __nv_bfloat16 b) {
    __nv_bfloat162 t(a, b);
    return *(uint32_t*)&t;
}

// ======= batched weight transpose + bf16 split (all 7 weights, 1 launch) ====
__global__ void __launch_bounds__(256)
wtsplit_all(const float* __restrict__ wq, const float* __restrict__ wk,
            const float* __restrict__ wv, const float* __restrict__ wu,
            const float* __restrict__ w0, const float* __restrict__ w2,
            const float* __restrict__ w1,
            __nv_bfloat16* __restrict__ WTh, __nv_bfloat16* __restrict__ WTl)
{
    __shared__ float t[32][33];
    int bid = blockIdx.x;
    const float* W; __nv_bfloat16 *Th, *Tl;
    int N, nx, ky;
    if (bid < 6144) {
        int w = bid >> 10, local = bid & 1023;
        switch (w) {
            case 0: W = wq; break; case 1: W = wk; break;
            case 2: W = wv; break; case 3: W = wu; break;
            case 4: W = w0; break; default: W = w2; break;
        }
        Th = WTh + (size_t)w * W1M; Tl = WTl + (size_t)w * W1M;
        N = 1024; nx = local & 31; ky = local >> 5;
    } else {
        int local = bid - 6144;
        W = w1; Th = WTh + (size_t)6 * W1M; Tl = WTl + (size_t)6 * W1M;
        N = 2048; nx = local & 63; ky = local >> 6;
    }
    const int K = 1024;
    int tx = threadIdx.x, ty = threadIdx.y;
    int n0 = nx * 32, k0 = ky * 32;
    #pragma unroll
    for (int i = 0; i < 4; i++)
        t[ty + i*8][tx] = W[(size_t)(k0 + ty + i*8) * N + n0 + tx];
    __syncthreads();
    #pragma unroll
    for (int i = 0; i < 4; i++) {
        float v = t[tx][ty + i*8];
        __nv_bfloat16 hi, lo;
        split_bf16(v, hi, lo);
        size_t off = (size_t)(n0 + ty + i*8) * K + k0 + tx;
        Th[off] = hi; Tl[off] = lo;
    }
}

// ---------------- RMSNorm -> bf16 hi/lo -------------------------------------
__global__ void __launch_bounds__(256)
rmsnorm_tc(const float* __restrict__ X, const float* __restrict__ g,
           __nv_bfloat16* __restrict__ Yh, __nv_bfloat16* __restrict__ Yl)
{
    int r = blockIdx.x, t = threadIdx.x;
    float4 v = ((const float4*)(X + (size_t)r * D_MODEL))[t];
    float ss = v.x*v.x + v.y*v.y + v.z*v.z + v.w*v.w;
    #pragma unroll
    for (int o = 16; o; o >>= 1) ss += __shfl_xor_sync(0xffffffffu, ss, o);
    __shared__ float ws[8]; __shared__ float s_inv;
    if ((t & 31) == 0) ws[t >> 5] = ss;
    __syncthreads();
    if (t == 0) {
        float tot = 0.f;
        #pragma unroll
        for (int i = 0; i < 8; i++) tot += ws[i];
        s_inv = rsqrtf(tot * (1.0f / D_MODEL) + 1e-8f);
    }
    __syncthreads();
    float iv = s_inv;
    float4 gv = ((const float4*)g)[t];
    float o[4] = {v.x*iv*gv.x, v.y*iv*gv.y, v.z*iv*gv.z, v.w*iv*gv.w};
    __nv_bfloat16 h[4], l[4];
    #pragma unroll
    for (int i = 0; i < 4; i++) split_bf16(o[i], h[i], l[i]);
    size_t base = (size_t)r * D_MODEL + t*4;
    *(__nv_bfloat162*)(Yh + base)     = __nv_bfloat162(h[0], h[1]);
    *(__nv_bfloat162*)(Yh + base + 2) = __nv_bfloat162(h[2], h[3]);
    *(__nv_bfloat162*)(Yl + base)     = __nv_bfloat162(l[0], l[1]);
    *(__nv_bfloat162*)(Yl + base + 2) = __nv_bfloat162(l[2], l[3]);
}

// -------- ams: out = rmsnorm(A, g) * U -> bf16 hi/lo ------------------------
__global__ void __launch_bounds__(256)
ams_tc(const float* __restrict__ A, const float* __restrict__ g,
       const float* __restrict__ U,
       __nv_bfloat16* __restrict__ Yh, __nv_bfloat16* __restrict__ Yl)
{
    int r = blockIdx.x, t = threadIdx.x;
    float4 v = ((const float4*)(A + (size_t)r * D_MODEL))[t];
    float ss = v.x*v.x + v.y*v.y + v.z*v.z + v.w*v.w;
    #pragma unroll
    for (int o = 16; o; o >>= 1) ss += __shfl_xor_sync(0xffffffffu, ss, o);
    __shared__ float ws[8]; __shared__ float s_inv;
    if ((t & 31) == 0) ws[t >> 5] = ss;
    __syncthreads();
    if (t == 0) {
        float tot = 0.f;
        #pragma unroll
        for (int i = 0; i < 8; i++) tot += ws[i];
        s_inv = rsqrtf(tot * (1.0f / D_MODEL) + 1e-8f);
    }
    __syncthreads();
    float iv = s_inv;
    float4 gv = ((const float4*)g)[t];
    float4 uv = ((const float4*)(U + (size_t)r * D_MODEL))[t];
    float o[4] = {v.x*iv*gv.x*uv.x, v.y*iv*gv.y*uv.y, v.z*iv*gv.z*uv.z, v.w*iv*gv.w*uv.w};
    __nv_bfloat16 h[4], l[4];
    #pragma unroll
    for (int i = 0; i < 4; i++) split_bf16(o[i], h[i], l[i]);
    size_t base = (size_t)r * D_MODEL + t*4;
    *(__nv_bfloat162*)(Yh + base)     = __nv_bfloat162(h[0], h[1]);
    *(__nv_bfloat162*)(Yh + base + 2) = __nv_bfloat162(h[2], h[3]);
    *(__nv_bfloat162*)(Yl + base)     = __nv_bfloat162(l[0], l[1]);
    *(__nv_bfloat162*)(Yl + base + 2) = __nv_bfloat162(l[2], l[3]);
}

// ============== HMMA GEMM (EPI 2 only): C = A@B^T + bias + R ================
#define SM_A_HI 0
#define SM_A_LO 16384
#define SM_B_HI 32768
#define SM_B_LO 65536
#define STAGE_B 98304

__global__ void __launch_bounds__(512, 1)
gemm_res(const __nv_bfloat16* __restrict__ Ah, const __nv_bfloat16* __restrict__ Al,
         const __nv_bfloat16* __restrict__ Bh, const __nv_bfloat16* __restrict__ Bl,
         const float* __restrict__ bias, const float* __restrict__ R,
         float* __restrict__ C, int M, int N, int K)
{
    extern __shared__ __align__(128) char sm[];
    uint32_t sb = smem_u32(sm);
    int tid  = threadIdx.x;
    int wid  = tid >> 5;
    int lane = tid & 31;
    int wm = wid & 1, wn = wid >> 1;
    int bm = blockIdx.y * 128, bn = blockIdx.x * 256;
    int m0 = wm * 64, n0 = wn * 32;

    int laneRow = lane & 15;
    int laneK   = (lane >> 4) * 16;
    uint32_t xorA = (uint32_t)((laneRow & 7) << 4);

    float acc[4][4][4];
    #pragma unroll
    for (int i = 0; i < 4; i++)
        #pragma unroll
        for (int j = 0; j < 4; j++)
            #pragma unroll
            for (int q = 0; q < 4; q++) acc[i][j][q] = 0.f;

    const int NCH = K >> 6;

    auto load_stage = [&](int s, int chunk) {
        uint32_t st = sb + s * STAGE_B;
        int k0 = chunk * 64;
        #pragma unroll
        for (int it = 0; it < 2; it++) {
            int idx = tid + it * 512;
            int row = idx >> 3, c = idx & 7;
            uint32_t d = st + row * 128 + (uint32_t)((c * 16) ^ ((row & 7) << 4));
            size_t go = (size_t)(bm + row) * K + k0 + c * 8;
            cp16(d + SM_A_HI, Ah + go);
            cp16(d + SM_A_LO, Al + go);
        }
        #pragma unroll
        for (int it = 0; it < 4; it++) {
            int idx = tid + it * 512;
            int row = idx >> 3, c = idx & 7;
            uint32_t d = st + row * 128 + (uint32_t)((c * 16) ^ ((row & 7) << 4));
            size_t go = (size_t)(bn + row) * K + k0 + c * 8;
            cp16(d + SM_B_HI, Bh + go);
            cp16(d + SM_B_LO, Bl + go);
        }
    };

    load_stage(0, 0);
    cp_commit();

    for (int chunk = 0; chunk < NCH; chunk++) {
        int s = chunk & 1;
        if (chunk + 1 < NCH) {
            load_stage(s ^ 1, chunk + 1);
            cp_commit();
            cp_wait1();
        } else {
            cp_wait0();
        }
        __syncthreads();

        uint32_t st = sb + s * STAGE_B;
        #pragma unroll
        for (int ks = 0; ks < 4; ks++) {
            uint32_t kb = (uint32_t)((ks * 32 + laneK) ^ xorA);
            uint32_t ah[4][4], bh[2][4];
            #pragma unroll
            for (int i = 0; i < 4; i++)
                ldsm_x4(ah[i], st + SM_A_HI + (uint32_t)(m0 + i*16 + laneRow) * 128 + kb);
            #pragma unroll
            for (int p = 0; p < 2; p++)
                ldsm_x4(bh[p], st + SM_B_HI + (uint32_t)(n0 + p*16 + laneRow) * 128 + kb);
            #pragma unroll
            for (int i = 0; i < 4; i++)
                #pragma unroll
                for (int j = 0; j < 4; j++)
                    mma16816(acc[i][j], ah[i], bh[j>>1][j&1], bh[j>>1][2 + (j&1)]);
            {
                uint32_t al[4][4];
                #pragma unroll
                for (int i = 0; i < 4; i++)
                    ldsm_x4(al[i], st + SM_A_LO + (uint32_t)(m0 + i*16 + laneRow) * 128 + kb);
                #pragma unroll
                for (int i = 0; i < 4; i++)
                    #pragma unroll
                    for (int j = 0; j < 4; j++)
                        mma16816(acc[i][j], al[i], bh[j>>1][j&1], bh[j>>1][2 + (j&1)]);
            }
            {
                uint32_t bl[2][4];
                #pragma unroll
                for (int p = 0; p < 2; p++)
                    ldsm_x4(bl[p], st + SM_B_LO + (uint32_t)(n0 + p*16 + laneRow) * 128 + kb);
                #pragma unroll
                for (int i = 0; i < 4; i++)
                    #pragma unroll
                    for (int j = 0; j < 4; j++)
                        mma16816(acc[i][j], ah[i], bl[j>>1][j&1], bl[j>>1][2 + (j&1)]);
            }
        }
        __syncthreads();
    }

    int group = lane >> 2, tq = lane & 3;
    #pragma unroll
    for (int j = 0; j < 4; j++) {
        int n = bn + n0 + j*8 + tq*2;
        float bv0 = bias[n], bv1 = bias[n+1];
        #pragma unroll
        for (int i = 0; i < 4; i++) {
            int m = bm + m0 + i*16 + group;
            size_t off0 = (size_t)m * N + n;
            size_t off1 = (size_t)(m + 8) * N + n;
            float2 r0 = *(const float2*)(R + off0);
            float2 r1 = *(const float2*)(R + off1);
            *(float2*)(C + off0) = make_float2(acc[i][j][0] + bv0 + r0.x, acc[i][j][1] + bv1 + r0.y);
            *(float2*)(C + off1) = make_float2(acc[i][j][2] + bv0 + r1.x, acc[i][j][3] + bv1 + r1.y);
        }
    }
}

// ====== fused Q/K/V/U projection: one launch, grid.z selects weight ========
__global__ void __launch_bounds__(512, 1)
proj4(const __nv_bfloat16* __restrict__ Ah, const __nv_bfloat16* __restrict__ Al,
      const __nv_bfloat16* __restrict__ WThG, const __nv_bfloat16* __restrict__ WTlG,
      const float* __restrict__ bq, const float* __restrict__ bk,
      const float* __restrict__ bv, const float* __restrict__ bu,
      __nv_bfloat16* __restrict__ Qh, __nv_bfloat16* __restrict__ Ql,
      __nv_bfloat16* __restrict__ Kh, __nv_bfloat16* __restrict__ Kl,
      __nv_bfloat16* __restrict__ VTh, __nv_bfloat16* __restrict__ VTl,
      float* __restrict__ Uf)
{
    extern __shared__ __align__(128) char sm[];
    uint32_t sb = smem_u32(sm);
    int tid  = threadIdx.x;
    int wid  = tid >> 5;
    int lane = tid & 31;
    int wm = wid & 1, wn = wid >> 1;
    int z  = blockIdx.z;
    int bm = blockIdx.y * 128, bn = blockIdx.x * 256;
    int m0 = wm * 64, n0 = wn * 32;
    const int K = 1024, N = 1024;

    const __nv_bfloat16* Bh = WThG + (size_t)z * W1M;
    const __nv_bfloat16* Bl = WTlG + (size_t)z * W1M;
    const float* bias = (z == 0) ? bq : (z == 1) ? bk : (z == 2) ? bv : bu;

    int laneRow = lane & 15;
    int laneK   = (lane >> 4) * 16;
    uint32_t xorA = (uint32_t)((laneRow & 7) << 4);

    float acc[4][4][4];
    #pragma unroll
    for (int i = 0; i < 4; i++)
        #pragma unroll
        for (int j = 0; j < 4; j++)
            #pragma unroll
            for (int q = 0; q < 4; q++) acc[i][j][q] = 0.f;

    const int NCH = K >> 6;

    auto load_stage = [&](int s, int chunk) {
        uint32_t st = sb + s * STAGE_B;
        int k0 = chunk * 64;
        #pragma unroll
        for (int it = 0; it < 2; it++) {
            int idx = tid + it * 512;
            int row = idx >> 3, c = idx & 7;
            uint32_t d = st + row * 128 + (uint32_t)((c * 16) ^ ((row & 7) << 4));
            size_t go = (size_t)(bm + row) * K + k0 + c * 8;
            cp16(d + SM_A_HI, Ah + go);
            cp16(d + SM_A_LO, Al + go);
        }
        #pragma unroll
        for (int it = 0; it < 4; it++) {
            int idx = tid + it * 512;
            int row = idx >> 3, c = idx & 7;
            uint32_t d = st + row * 128 + (uint32_t)((c * 16) ^ ((row & 7) << 4));
            size_t go = (size_t)(bn + row) * K + k0 + c * 8;
            cp16(d + SM_B_HI, Bh + go);
            cp16(d + SM_B_LO, Bl + go);
        }
    };

    load_stage(0, 0);
    cp_commit();

    for (int chunk = 0; chunk < NCH; chunk++) {
        int s = chunk & 1;
        if (chunk + 1 < NCH) {
            load_stage(s ^ 1, chunk + 1);
            cp_commit();
            cp_wait1();
        } else {
            cp_wait0();
        }
        __syncthreads();

        uint32_t st = sb + s * STAGE_B;
        #pragma unroll
        for (int ks = 0; ks < 4; ks++) {
            uint32_t kb = (uint32_t)((ks * 32 + laneK) ^ xorA);
            uint32_t ah[4][4], bh[2][4];
            #pragma unroll
            for (int i = 0; i < 4; i++)
                ldsm_x4(ah[i], st + SM_A_HI + (uint32_t)(m0 + i*16 + laneRow) * 128 + kb);
            #pragma unroll
            for (int p = 0; p < 2; p++)
                ldsm_x4(bh[p], st + SM_B_HI + (uint32_t)(n0 + p*16 + laneRow) * 128 + kb);
            #pragma unroll
            for (int i = 0; i < 4; i++)
                #pragma unroll
                for (int j = 0; j < 4; j++)
                    mma16816(acc[i][j], ah[i], bh[j>>1][j&1], bh[j>>1][2 + (j&1)]);
            {
                uint32_t al[4][4];
                #pragma unroll
                for (int i = 0; i < 4; i++)
                    ldsm_x4(al[i], st + SM_A_LO + (uint32_t)(m0 + i*16 + laneRow) * 128 + kb);
                #pragma unroll
                for (int i = 0; i < 4; i++)
                    #pragma unroll
                    for (int j = 0; j < 4; j++)
                        mma16816(acc[i][j], al[i], bh[j>>1][j&1], bh[j>>1][2 + (j&1)]);
            }
            {
                uint32_t bl[2][4];
                #pragma unroll
                for (int p = 0; p < 2; p++)
                    ldsm_x4(bl[p], st + SM_B_LO + (uint32_t)(n0 + p*16 + laneRow) * 128 + kb);
                #pragma unroll
                for (int i = 0; i < 4; i++)
                    #pragma unroll
                    for (int j = 0; j < 4; j++)
                        mma16816(acc[i][j], ah[i], bl[j>>1][j&1], bl[j>>1][2 + (j&1)]);
            }
        }
        __syncthreads();
    }

    int group = lane >> 2, tq = lane & 3;
    __nv_bfloat16* Yh = (z == 0) ? Qh : Kh;
    __nv_bfloat16* Yl = (z == 0) ? Ql : Kl;
    #pragma unroll
    for (int j = 0; j < 4; j++) {
        int n = bn + n0 + j*8 + tq*2;
        float bv0 = bias[n], bv1 = bias[n+1];
        #pragma unroll
        for (int i = 0; i < 4; i++) {
            int m = bm + m0 + i*16 + group;
            float v0 = acc[i][j][0] + bv0, v1 = acc[i][j][1] + bv1;
            float v2 = acc[i][j][2] + bv0, v3 = acc[i][j][3] + bv1;
            if (z <= 1) {
                __nv_bfloat16 h0,l0,h1,l1,h2,l2,h3,l3;
                split_bf16(v0,h0,l0); split_bf16(v1,h1,l1);
                split_bf16(v2,h2,l2); split_bf16(v3,h3,l3);
                size_t off0 = (size_t)m * N + n;
                size_t off1 = (size_t)(m + 8) * N + n;
                *(__nv_bfloat162*)(Yh + off0) = __nv_bfloat162(h0, h1);
                *(__nv_bfloat162*)(Yl + off0) = __nv_bfloat162(l0, l1);
                *(__nv_bfloat162*)(Yh + off1) = __nv_bfloat162(h2, h3);
                *(__nv_bfloat162*)(Yl + off1) = __nv_bfloat162(l2, l3);
            } else if (z == 2) {
                __nv_bfloat16 h0,l0,h1,l1,h2,l2,h3,l3;
                split_bf16(v0,h0,l0); split_bf16(v1,h1,l1);
                split_bf16(v2,h2,l2); split_bf16(v3,h3,l3);
                int bi = m >> 11, tt = m & 2047;
                int hh = n >> 6,  dd = n & 63;
                size_t vb = ((size_t)((bi*16 + hh)*64 + dd)) * 2048 + tt;
                VTh[vb]        = h0;  VTl[vb]        = l0;
                VTh[vb + 2048] = h1;  VTl[vb + 2048] = l1;
                VTh[vb + 8]    = h2;  VTl[vb + 8]    = l2;
                VTh[vb + 2056] = h3;  VTl[vb + 2056] = l3;
            } else {
                size_t off0 = (size_t)m * N + n;
                size_t off1 = (size_t)(m + 8) * N + n;
                *(float2*)(Uf + off0) = make_float2(siluf(v0), siluf(v1));
                *(float2*)(Uf + off1) = make_float2(siluf(v2), siluf(v3));
            }
        }
    }
}

// ====== w1 GEMM + swiglu fusion ============================================
#define W_A_HI  0
#define W_A_LO  16384
#define W_B1_HI 32768
#define W_B1_LO 49152
#define W_B2_HI 65536
#define W_B2_LO 81920
#define STAGE_W 98304

__global__ void __launch_bounds__(512, 1)
gemm_w1sg(const __nv_bfloat16* __restrict__ Ah, const __nv_bfloat16* __restrict__ Al,
          const __nv_bfloat16* __restrict__ Bh, const __nv_bfloat16* __restrict__ Bl,
          const float* __restrict__ b1,
          __nv_bfloat16* __restrict__ Yh, __nv_bfloat16* __restrict__ Yl)
{
    extern __shared__ __align__(128) char sm[];
    uint32_t sb = smem_u32(sm);
    int tid  = threadIdx.x;
    int wid  = tid >> 5;
    int lane = tid & 31;
    int wm = wid & 1, wn = wid >> 1;
    int bm = blockIdx.y * 128, bn = blockIdx.x * 128;
    int m0 = wm * 64, n0 = wn * 16;
    const int K = 1024;

    int laneRow = lane & 15;
    int laneK   = (lane >> 4) * 16;
    uint32_t xorA = (uint32_t)((laneRow & 7) << 4);

    float acc1[4][2][4], acc2[4][2][4];
    #pragma unroll
    for (int i = 0; i < 4; i++)
        #pragma unroll
        for (int j = 0; j < 2; j++)
            #pragma unroll
            for (int q = 0; q < 4; q++) { acc1[i][j][q] = 0.f; acc2[i][j][q] = 0.f; }

    const int NCH = K >> 6;

    auto load_stage = [&](int s, int chunk) {
        uint32_t st = sb + s * STAGE_W;
        int k0 = chunk * 64;
        #pragma unroll
        for (int it = 0; it < 2; it++) {
            int idx = tid + it * 512;
            int row = idx >> 3, c = idx & 7;
            uint32_t d = st + row * 128 + (uint32_t)((c * 16) ^ ((row & 7) << 4));
            size_t goA  = (size_t)(bm + row) * K + k0 + c * 8;
            size_t goB1 = (size_t)(bn + row) * K + k0 + c * 8;
            size_t goB2 = (size_t)(1024 + bn + row) * K + k0 + c * 8;
            cp16(d + W_A_HI,  Ah + goA);
            cp16(d + W_A_LO,  Al + goA);
            cp16(d + W_B1_HI, Bh + goB1);
            cp16(d + W_B1_LO, Bl + goB1);
            cp16(d + W_B2_HI, Bh + goB2);
            cp16(d + W_B2_LO, Bl + goB2);
        }
    };

    load_stage(0, 0);
    cp_commit();

    for (int chunk = 0; chunk < NCH; chunk++) {
        int s = chunk & 1;
        if (chunk + 1 < NCH) {
            load_stage(s ^ 1, chunk + 1);
            cp_commit();
            cp_wait1();
        } else {
            cp_wait0();
        }
        __syncthreads();

        uint32_t st = sb + s * STAGE_W;
        #pragma unroll
        for (int ks = 0; ks < 4; ks++) {
            uint32_t kb = (uint32_t)((ks * 32 + laneK) ^ xorA);
            uint32_t ah[4][4], b1h[4], b2h[4];
            #pragma unroll
            for (int i = 0; i < 4; i++)
                ldsm_x4(ah[i], st + W_A_HI + (uint32_t)(m0 + i*16 + laneRow) * 128 + kb);
            ldsm_x4(b1h, st + W_B1_HI + (uint32_t)(n0 + laneRow) * 128 + kb);
            ldsm_x4(b2h, st + W_B2_HI + (uint32_t)(n0 + laneRow) * 128 + kb);
            #pragma unroll
            for (int i = 0; i < 4; i++)
                #pragma unroll
                for (int j = 0; j < 2; j++) {
                    mma16816(acc1[i][j], ah[i], b1h[j], b1h[2 + j]);
                    mma16816(acc2[i][j], ah[i], b2h[j], b2h[2 + j]);
                }
            {
                uint32_t al[4][4];
                #pragma unroll
                for (int i = 0; i < 4; i++)
                    ldsm_x4(al[i], st + W_A_LO + (uint32_t)(m0 + i*16 + laneRow) * 128 + kb);
                #pragma unroll
                for (int i = 0; i < 4; i++)
                    #pragma unroll
                    for (int j = 0; j < 2; j++) {
                        mma16816(acc1[i][j], al[i], b1h[j], b1h[2 + j]);
                        mma16816(acc2[i][j], al[i], b2h[j], b2h[2 + j]);
                    }
            }
            {
                uint32_t b1l[4], b2l[4];
                ldsm_x4(b1l, st + W_B1_LO + (uint32_t)(n0 + laneRow) * 128 + kb);
                ldsm_x4(b2l, st + W_B2_LO + (uint32_t)(n0 + laneRow) * 128 + kb);
                #pragma unroll
                for (int i = 0; i < 4; i++)
                    #pragma unroll
                    for (int j = 0; j < 2; j++) {
                        mma16816(acc1[i][j], ah[i], b1l[j], b1l[2 + j]);
                        mma16816(acc2[i][j], ah[i], b2l[j], b2l[2 + j]);
                    }
            }
        }
        __syncthreads();
    }

    int group = lane >> 2, tq = lane & 3;
    #pragma unroll
    for (int j = 0; j < 2; j++) {
        int n = bn + n0 + j*8 + tq*2;
        float c10 = b1[n], c11 = b1[n+1];
        float c20 = b1[1024 + n], c21 = b1[1025 + n];
        #pragma unroll
        for (int i = 0; i < 4; i++) {
            int m = bm + m0 + i*16 + group;
            float y0 = siluf(acc1[i][j][0] + c10) * (acc2[i][j][0] + c20);
            float y1 = siluf(acc1[i][j][1] + c11) * (acc2[i][j][1] + c21);
            float y2 = siluf(acc1[i][j][2] + c10) * (acc2[i][j][2] + c20);
            float y3 = siluf(acc1[i][j][3] + c11) * (acc2[i][j][3] + c21);
            __nv_bfloat16 h0,l0,h1,l1,h2,l2,h3,l3;
            split_bf16(y0,h0,l0); split_bf16(y1,h1,l1);
            split_bf16(y2,h2,l2); split_bf16(y3,h3,l3);
            size_t off0 = (size_t)m * 1024 + n;
            size_t off1 = (size_t)(m + 8) * 1024 + n;
            *(__nv_bfloat162*)(Yh + off0) = __nv_bfloat162(h0, h1);
            *(__nv_bfloat162*)(Yl + off0) = __nv_bfloat162(l0, l1);
            *(__nv_bfloat162*)(Yh + off1) = __nv_bfloat162(h2, h3);
            *(__nv_bfloat162*)(Yl + off1) = __nv_bfloat162(l2, l3);
        }
    }
}

// ===== tensor-core fused SiLU-attention, register-resident S, batched issue ==
// 8 warps split q-tile by m. Per ks-slice: batch-load ALL K/V fragments, then
// issue MMA passes across all tiles -> dependent-MMA distance 16 (S) / 8 (SV).
// Bit-exact same accumulation order per accumulator as R8.
#define A_SQH 0u
#define A_SQL 16384u
#define A_SK  32768u       // + s*32768 : KH, KL(+16384)
#define A_SVT 98304u       // + s*32768 : VTH, VTL(+16384)
#define A_PB  163840u      // + s*512
#define ATT_SMEM 164864

__global__ void __launch_bounds__(256, 1)
attn_tc(const __nv_bfloat16* __restrict__ Qh, const __nv_bfloat16* __restrict__ Ql,
        const __nv_bfloat16* __restrict__ Kh, const __nv_bfloat16* __restrict__ Kl,
        const __nv_bfloat16* __restrict__ VTh, const __nv_bfloat16* __restrict__ VTl,
        const float* __restrict__ PB, float* __restrict__ O)
{
    extern __shared__ __align__(128) char sm[];
    uint32_t sb = smem_u32(sm);
    int tid  = threadIdx.x;
    int wid  = tid >> 5;
    int lane = tid & 31;
    int qt = blockIdx.x, h = blockIdx.y, b = blockIdx.z;
    int m0 = wid * 16;

    int laneRow = lane & 15;
    int laneK   = (lane >> 4) * 16;
    uint32_t xorA = (uint32_t)((laneRow & 7) << 4);
    int group = lane >> 2, tq = lane & 3;
    uint32_t rowbK = (uint32_t)laneRow * 128;   // K tile: 128B rows
    uint32_t rowbV = (uint32_t)laneRow * 256;   // VT tile: 256B rows

    auto load_q = [&]() {
        #pragma unroll
        for (int it = 0; it < 4; it++) {
            int idx = tid + it * 256;
            int row = idx >> 3, c = idx & 7;
            uint32_t d = row * 128 + (uint32_t)((c * 16) ^ ((row & 7) << 4));
            size_t go = ((size_t)(b*SEQ + qt*128 + row)) * D_MODEL + h*64 + c*8;
            cp16(sb + A_SQH + d, Qh + go);
            cp16(sb + A_SQL + d, Ql + go);
        }
    };
    auto load_kv = [&](int s, int kt) {
        uint32_t kbase = sb + A_SK + (uint32_t)s * 32768u;
        #pragma unroll
        for (int it = 0; it < 4; it++) {
            int idx = tid + it * 256;
            int row = idx >> 3, c = idx & 7;
            uint32_t d = row * 128 + (uint32_t)((c * 16) ^ ((row & 7) << 4));
            size_t go = ((size_t)(b*SEQ + kt*128 + row)) * D_MODEL + h*64 + c*8;
            cp16(kbase + d, Kh + go);
            cp16(kbase + 16384u + d, Kl + go);
        }
        uint32_t vbase = sb + A_SVT + (uint32_t)s * 32768u;
        #pragma unroll
        for (int it = 0; it < 4; it++) {
            int idx = tid + it * 256;
            int row = idx >> 4, c = idx & 15;
            uint32_t d = row * 256 + (uint32_t)((c * 16) ^ ((row & 7) << 4));
            size_t go = ((size_t)((b*16 + h)*64 + row)) * 2048 + kt*128 + c*8;
            cp16(vbase + d, VTh + go);
            cp16(vbase + 16384u + d, VTl + go);
        }
        if (tid < 128) {
            float v = PB[(size_t)(kt*128 + tid) * N_HEADS + h];
            *(float*)(sm + A_PB + (uint32_t)s * 512u + tid * 4) = v;
        }
    };

    float accO[8][4];
    #pragma unroll
    for (int f = 0; f < 8; f++)
        #pragma unroll
        for (int q = 0; q < 4; q++) accO[f][q] = 0.f;

    load_q(); cp_commit();
    load_kv(0, 0); cp_commit();
    cp_wait1();          // Q complete
    __syncthreads();

    // hoist Q fragments (loop-invariant)
    uint32_t qfh[4][4], qfl[4][4];
    #pragma unroll
    for (int ks = 0; ks < 4; ks++) {
        uint32_t kb = (uint32_t)((ks * 32 + laneK) ^ xorA);
        ldsm_x4(qfh[ks], sb + A_SQH + (uint32_t)m0 * 128 + rowbK + kb);
        ldsm_x4(qfl[ks], sb + A_SQL + (uint32_t)m0 * 128 + rowbK + kb);
    }

    for (int kt = 0; kt < SEQ/128; kt++) {
        int s = kt & 1;
        if (kt + 1 < SEQ/128) {
            load_kv(s ^ 1, kt + 1);
            cp_commit();
            cp_wait1();
        } else {
            cp_wait0();
        }
        __syncthreads();

        // ---- S = Q @ K^T, ks outer, batched fragment loads ----
        float sc[16][4];
        #pragma unroll
        for (int f = 0; f < 16; f++)
            #pragma unroll
            for (int q = 0; q < 4; q++) sc[f][q] = 0.f;

        uint32_t kst = sb + A_SK + (uint32_t)s * 32768u;
        #pragma unroll
        for (int ks = 0; ks < 4; ks++) {
            uint32_t kb = (uint32_t)((ks * 32 + laneK) ^ xorA);
            uint32_t kf[8][4];
            #pragma unroll
            for (int nt = 0; nt < 8; nt++)
                ldsm_x4(kf[nt], kst + (uint32_t)nt * 2048u + rowbK + kb);
            #pragma unroll
            for (int nt = 0; nt < 8; nt++) {
                mma16816(sc[2*nt],   qfh[ks], kf[nt][0], kf[nt][2]);
                mma16816(sc[2*nt+1], qfh[ks], kf[nt][1], kf[nt][3]);
            }
            #pragma unroll
            for (int nt = 0; nt < 8; nt++) {
                mma16816(sc[2*nt],   qfl[ks], kf[nt][0], kf[nt][2]);
                mma16816(sc[2*nt+1], qfl[ks], kf[nt][1], kf[nt][3]);
            }
            #pragma unroll
            for (int nt = 0; nt < 8; nt++)
                ldsm_x4(kf[nt], kst + 16384u + (uint32_t)nt * 2048u + rowbK + kb);
            #pragma unroll
            for (int nt = 0; nt < 8; nt++) {
                mma16816(sc[2*nt],   qfh[ks], kf[nt][0], kf[nt][2]);
                mma16816(sc[2*nt+1], qfh[ks], kf[nt][1], kf[nt][3]);
            }
        }

        // ---- silu(scale*S + pb), split hi/lo, repack as A-frags in regs ----
        uint32_t sfh[8][4], sfl[8][4];
        const float* pbs = (const float*)(sm + A_PB + (uint32_t)s * 512u);
        #pragma unroll
        for (int nt = 0; nt < 8; nt++) {
            #pragma unroll
            for (int half = 0; half < 2; half++) {
                int f = 2*nt + half;
                int tcol = nt*16 + half*8 + tq*2;
                float pb0 = pbs[tcol], pb1 = pbs[tcol + 1];
                float w0 = siluf(sc[f][0] * 0.125f + pb0);
                float w1 = siluf(sc[f][1] * 0.125f + pb1);
                float w2 = siluf(sc[f][2] * 0.125f + pb0);
                float w3 = siluf(sc[f][3] * 0.125f + pb1);
                __nv_bfloat16 h0,l0,h1,l1,h2,l2,h3,l3;
                split_bf16(w0,h0,l0); split_bf16(w1,h1,l1);
                split_bf16(w2,h2,l2); split_bf16(w3,h3,l3);
                sfh[nt][half*2]     = pack_bf16(h0, h1);
                sfh[nt][half*2 + 1] = pack_bf16(h2, h3);
                sfl[nt][half*2]     = pack_bf16(l0, l1);
                sfl[nt][half*2 + 1] = pack_bf16(l2, l3);
            }
        }

        // ---- O += S @ V, ks outer, batched fragment loads ----
        uint32_t vst = sb + A_SVT + (uint32_t)s * 32768u;
        #pragma unroll
        for (int ks = 0; ks < 8; ks++) {
            uint32_t kb = (uint32_t)((ks * 32 + laneK) ^ xorA);
            uint32_t vf[4][4];
            #pragma unroll
            for (int dn = 0; dn < 4; dn++)
                ldsm_x4(vf[dn], vst + (uint32_t)dn * 4096u + rowbV + kb);
            #pragma unroll
            for (int dn = 0; dn < 4; dn++) {
                mma16816(accO[2*dn],   sfh[ks], vf[dn][0], vf[dn][2]);
                mma16816(accO[2*dn+1], sfh[ks], vf[dn][1], vf[dn][3]);
            }
            #pragma unroll
            for (int dn = 0; dn < 4; dn++) {
                mma16816(accO[2*dn],   sfl[ks], vf[dn][0], vf[dn][2]);
                mma16816(accO[2*dn+1], sfl[ks], vf[dn][1], vf[dn][3]);
            }
            #pragma unroll
            for (int dn = 0; dn < 4; dn++)
                ldsm_x4(vf[dn], vst + 16384u + (uint32_t)dn * 4096u + rowbV + kb);
            #pragma unroll
            for (int dn = 0; dn < 4; dn++) {
                mma16816(accO[2*dn],   sfh[ks], vf[dn][0], vf[dn][2]);
                mma16816(accO[2*dn+1], sfh[ks], vf[dn][1], vf[dn][3]);
            }
        }
        __syncthreads();
    }

    // ---- write O ----
    #pragma unroll
    for (int dn = 0; dn < 4; dn++) {
        #pragma unroll
        for (int half = 0; half < 2; half++) {
            int f = 2*dn + half;
            int col = h*64 + dn*16 + half*8 + tq*2;
            int row = b*SEQ + qt*128 + m0 + group;
            *(float2*)(O + (size_t)row * D_MODEL + col) =
                make_float2(accO[f][0], accO[f][1]);
            *(float2*)(O + (size_t)(row + 8) * D_MODEL + col) =
                make_float2(accO[f][2], accO[f][3]);
        }
    }
}

// ---------------- launch ----------------------------------------------------
extern "C" void kernel_launch(void* const* d_in, const int* in_sizes, int n_in,
                              void* d_out, int out_size)
{
    const float* x      = (const float*)d_in[0];
    const float* pb     = (const float*)d_in[2];
    const float* wq     = (const float*)d_in[3];
    const float* bq     = (const float*)d_in[4];
    const float* wk     = (const float*)d_in[5];
    const float* bk_    = (const float*)d_in[6];
    const float* wv     = (const float*)d_in[7];
    const float* bv     = (const float*)d_in[8];
    const float* wu     = (const float*)d_in[9];
    const float* bu     = (const float*)d_in[10];
    const float* g_ams  = (const float*)d_in[11];
    const float* w0     = (const float*)d_in[12];
    const float* b0     = (const float*)d_in[13];
    const float* w1     = (const float*)d_in[14];
    const float* b1     = (const float*)d_in[15];
    const float* w2     = (const float*)d_in[16];
    const float* b2     = (const float*)d_in[17];
    const float* g_mffn = (const float*)d_in[18];
    float* out = (float*)d_out;

    float *Qf, *Kf, *Vf, *Uf, *AOf, *Of;
    __nv_bfloat16 *A1h, *A1l, *A2h, *A2l, *WTh, *WTl;
    cudaGetSymbolAddress((void**)&Qf,  g_Q);
    cudaGetSymbolAddress((void**)&Kf,  g_K);
    cudaGetSymbolAddress((void**)&Vf,  g_V);
    cudaGetSymbolAddress((void**)&Uf,  g_U);
    cudaGetSymbolAddress((void**)&AOf, g_AO);
    cudaGetSymbolAddress((void**)&Of,  g_O);
    cudaGetSymbolAddress((void**)&A1h, g_A1h);
    cudaGetSymbolAddress((void**)&A1l, g_A1l);
    cudaGetSymbolAddress((void**)&A2h, g_A2h);
    cudaGetSymbolAddress((void**)&A2l, g_A2l);
    cudaGetSymbolAddress((void**)&WTh, g_WTh);
    cudaGetSymbolAddress((void**)&WTl, g_WTl);

    const size_t NEL = (size_t)M_ROWS * D_MODEL;
    __nv_bfloat16 *Qhb = (__nv_bfloat16*)Qf,  *Qlb = Qhb + NEL;
    __nv_bfloat16 *Khb = (__nv_bfloat16*)Kf,  *Klb = Khb + NEL;
    __nv_bfloat16 *VTh = (__nv_bfloat16*)Vf,  *VTl = VTh + NEL;

    __nv_bfloat16 *T0_h = WTh + (size_t)4*W1M, *T0_l = WTl + (size_t)4*W1M;
    __nv_bfloat16 *T2_h = WTh + (size_t)5*W1M, *T2_l = WTl + (size_t)5*W1M;
    __nv_bfloat16 *T1_h = WTh + (size_t)6*W1M, *T1_l = WTl + (size_t)6*W1M;

    const int GSM = 2 * STAGE_B;
    cudaFuncSetAttribute(gemm_res,  cudaFuncAttributeMaxDynamicSharedMemorySize, GSM);
    cudaFuncSetAttribute(proj4,     cudaFuncAttributeMaxDynamicSharedMemorySize, GSM);
    cudaFuncSetAttribute(gemm_w1sg, cudaFuncAttributeMaxDynamicSharedMemorySize, 2*STAGE_W);
    cudaFuncSetAttribute(attn_tc,   cudaFuncAttributeMaxDynamicSharedMemorySize, ATT_SMEM);

    wtsplit_all<<<8192, dim3(32, 8)>>>(wq, wk, wv, wu, w0, w2, w1, WTh, WTl);
    rmsnorm_tc<<<M_ROWS, 256>>>(x, g_ams, A1h, A1l);
    proj4<<<dim3(4, 32, 4), 512, GSM>>>(A1h, A1l, WTh, WTl, bq, bk_, bv, bu,
                                        Qhb, Qlb, Khb, Klb, VTh, VTl, Uf);
    attn_tc<<<dim3(SEQ/128, N_HEADS, BATCH), 256, ATT_SMEM>>>(Qhb, Qlb, Khb, Klb, VTh, VTl, pb, AOf);
    ams_tc<<<M_ROWS, 256>>>(AOf, g_ams, Uf, A2h, A2l);
    gemm_res<<<dim3(4, 32), 512, GSM>>>(A2h, A2l, T0_h, T0_l, b0, x, Of, M_ROWS, 1024, 1024);
    rmsnorm_tc<<<M_ROWS, 256>>>(Of, g_mffn, A1h, A1l);
    gemm_w1sg<<<dim3(8, 32), 512, 2*STAGE_W>>>(A1h, A1l, T1_h, T1_l, b1, A2h, A2l);
    gemm_res<<<dim3(4, 32), 512, GSM>>>(A2h, A2l, T2_h, T2_l, b2, Of, out, M_ROWS, 1024, 1024);
}

// round 10
// speedup vs baseline: 1.1183x; 1.1183x over previous
#include <cuda_runtime.h>
#include <cuda_bf16.h>
#include <cstdint>
#include <math.h>

#define D_MODEL 1024
#define N_HEADS 16
#define DH      64
#define BATCH   2
#define SEQ     2048
#define M_ROWS  (BATCH*SEQ)   // 4096

// ---------------- scratch (static device globals; no allocations) ----------
__device__ float g_Q  [M_ROWS*D_MODEL];   // aliased: Qh/Ql bf16
__device__ float g_K  [M_ROWS*D_MODEL];   // aliased: Kh/Kl bf16
__device__ float g_V  [M_ROWS*D_MODEL];   // aliased: VTh/VTl bf16 (transposed per head)
__device__ float g_U  [M_ROWS*D_MODEL];
__device__ float g_AO [M_ROWS*D_MODEL];
__device__ float g_O  [M_ROWS*D_MODEL];

__device__ __nv_bfloat16 g_A1h[M_ROWS*D_MODEL];
__device__ __nv_bfloat16 g_A1l[M_ROWS*D_MODEL];
__device__ __nv_bfloat16 g_A2h[M_ROWS*D_MODEL];
__device__ __nv_bfloat16 g_A2l[M_ROWS*D_MODEL];

__device__ __nv_bfloat16 g_WTh[8*1024*1024];
__device__ __nv_bfloat16 g_WTl[8*1024*1024];

#define W1M (1024*1024)

__device__ __forceinline__ float siluf(float z) {
    return z * (1.0f / (1.0f + __expf(-z)));
}

__device__ __forceinline__ uint32_t smem_u32(const void* p) {
    uint32_t a;
    asm("{ .reg .u64 t; cvta.to.shared.u64 t, %1; cvt.u32.u64 %0, t; }" : "=r"(a) : "l"(p));
    return a;
}

__device__ __forceinline__ void ldsm_x4(uint32_t* r, uint32_t a) {
    asm volatile("ldmatrix.sync.aligned.m8n8.x4.shared.b16 {%0,%1,%2,%3}, [%4];"
                 : "=r"(r[0]), "=r"(r[1]), "=r"(r[2]), "=r"(r[3]) : "r"(a));
}

__device__ __forceinline__ void mma16816(float* c, const uint32_t* a, uint32_t b0, uint32_t b1) {
    asm volatile("mma.sync.aligned.m16n8k16.row.col.f32.bf16.bf16.f32 "
                 "{%0,%1,%2,%3}, {%4,%5,%6,%7}, {%8,%9}, {%0,%1,%2,%3};"
                 : "+f"(c[0]), "+f"(c[1]), "+f"(c[2]), "+f"(c[3])
                 : "r"(a[0]), "r"(a[1]), "r"(a[2]), "r"(a[3]), "r"(b0), "r"(b1));
}

__device__ __forceinline__ void cp16(uint32_t dst, const void* src) {
    asm volatile("cp.async.cg.shared.global [%0], [%1], 16;" :: "r"(dst), "l"(src));
}
__device__ __forceinline__ void cp_commit() { asm volatile("cp.async.commit_group;"); }
__device__ __forceinline__ void cp_wait1()  { asm volatile("cp.async.wait_group 1;"); }
__device__ __forceinline__ void cp_wait0()  { asm volatile("cp.async.wait_group 0;"); }

__device__ __forceinline__ void split_bf16(float v, __nv_bfloat16& h, __nv_bfloat16& l) {
    h = __float2bfloat16(v);
    l = __float2bfloat16(v - __bfloat162float(h));
}

__device__ __forceinline__ uint32_t pack_bf16(__nv_bfloat16 a, __nv_bfloat16 b) {
    __nv_bfloat162 t(a, b);
    return *(uint32_t*)&t;
}

// ======= batched weight transpose + bf16 split (all 7 weights, 1 launch) ====
__global__ void __launch_bounds__(256)
wtsplit_all(const float* __restrict__ wq, const float* __restrict__ wk,
            const float* __restrict__ wv, const float* __restrict__ wu,
            const float* __restrict__ w0, const float* __restrict__ w2,
            const float* __restrict__ w1,
            __nv_bfloat16* __restrict__ WTh, __nv_bfloat16* __restrict__ WTl)
{
    __shared__ float t[32][33];
    int bid = blockIdx.x;
    const float* W; __nv_bfloat16 *Th, *Tl;
    int N, nx, ky;
    if (bid < 6144) {
        int w = bid >> 10, local = bid & 1023;
        switch (w) {
            case 0: W = wq; break; case 1: W = wk; break;
            case 2: W = wv; break; case 3: W = wu; break;
            case 4: W = w0; break; default: W = w2; break;
        }
        Th = WTh + (size_t)w * W1M; Tl = WTl + (size_t)w * W1M;
        N = 1024; nx = local & 31; ky = local >> 5;
    } else {
        int local = bid - 6144;
        W = w1; Th = WTh + (size_t)6 * W1M; Tl = WTl + (size_t)6 * W1M;
        N = 2048; nx = local & 63; ky = local >> 6;
    }
    const int K = 1024;
    int tx = threadIdx.x, ty = threadIdx.y;
    int n0 = nx * 32, k0 = ky * 32;
    #pragma unroll
    for (int i = 0; i < 4; i++)
        t[ty + i*8][tx] = W[(size_t)(k0 + ty + i*8) * N + n0 + tx];
    __syncthreads();
    #pragma unroll
    for (int i = 0; i < 4; i++) {
        float v = t[tx][ty + i*8];
        __nv_bfloat16 hi, lo;
        split_bf16(v, hi, lo);
        size_t off = (size_t)(n0 + ty + i*8) * K + k0 + tx;
        Th[off] = hi; Tl[off] = lo;
    }
}

// ---------------- RMSNorm -> bf16 hi/lo -------------------------------------
__global__ void __launch_bounds__(256)
rmsnorm_tc(const float* __restrict__ X, const float* __restrict__ g,
           __nv_bfloat16* __restrict__ Yh, __nv_bfloat16* __restrict__ Yl)
{
    int r = blockIdx.x, t = threadIdx.x;
    float4 v = ((const float4*)(X + (size_t)r * D_MODEL))[t];
    float ss = v.x*v.x + v.y*v.y + v.z*v.z + v.w*v.w;
    #pragma unroll
    for (int o = 16; o; o >>= 1) ss += __shfl_xor_sync(0xffffffffu, ss, o);
    __shared__ float ws[8]; __shared__ float s_inv;
    if ((t & 31) == 0) ws[t >> 5] = ss;
    __syncthreads();
    if (t == 0) {
        float tot = 0.f;
        #pragma unroll
        for (int i = 0; i < 8; i++) tot += ws[i];
        s_inv = rsqrtf(tot * (1.0f / D_MODEL) + 1e-8f);
    }
    __syncthreads();
    float iv = s_inv;
    float4 gv = ((const float4*)g)[t];
    float o[4] = {v.x*iv*gv.x, v.y*iv*gv.y, v.z*iv*gv.z, v.w*iv*gv.w};
    __nv_bfloat16 h[4], l[4];
    #pragma unroll
    for (int i = 0; i < 4; i++) split_bf16(o[i], h[i], l[i]);
    size_t base = (size_t)r * D_MODEL + t*4;
    *(__nv_bfloat162*)(Yh + base)     = __nv_bfloat162(h[0], h[1]);
    *(__nv_bfloat162*)(Yh + base + 2) = __nv_bfloat162(h[2], h[3]);
    *(__nv_bfloat162*)(Yl + base)     = __nv_bfloat162(l[0], l[1]);
    *(__nv_bfloat162*)(Yl + base + 2) = __nv_bfloat162(l[2], l[3]);
}

// -------- ams: out = rmsnorm(A, g) * U -> bf16 hi/lo ------------------------
__global__ void __launch_bounds__(256)
ams_tc(const float* __restrict__ A, const float* __restrict__ g,
       const float* __restrict__ U,
       __nv_bfloat16* __restrict__ Yh, __nv_bfloat16* __restrict__ Yl)
{
    int r = blockIdx.x, t = threadIdx.x;
    float4 v = ((const float4*)(A + (size_t)r * D_MODEL))[t];
    float ss = v.x*v.x + v.y*v.y + v.z*v.z + v.w*v.w;
    #pragma unroll
    for (int o = 16; o; o >>= 1) ss += __shfl_xor_sync(0xffffffffu, ss, o);
    __shared__ float ws[8]; __shared__ float s_inv;
    if ((t & 31) == 0) ws[t >> 5] = ss;
    __syncthreads();
    if (t == 0) {
        float tot = 0.f;
        #pragma unroll
        for (int i = 0; i < 8; i++) tot += ws[i];
        s_inv = rsqrtf(tot * (1.0f / D_MODEL) + 1e-8f);
    }
    __syncthreads();
    float iv = s_inv;
    float4 gv = ((const float4*)g)[t];
    float4 uv = ((const float4*)(U + (size_t)r * D_MODEL))[t];
    float o[4] = {v.x*iv*gv.x*uv.x, v.y*iv*gv.y*uv.y, v.z*iv*gv.z*uv.z, v.w*iv*gv.w*uv.w};
    __nv_bfloat16 h[4], l[4];
    #pragma unroll
    for (int i = 0; i < 4; i++) split_bf16(o[i], h[i], l[i]);
    size_t base = (size_t)r * D_MODEL + t*4;
    *(__nv_bfloat162*)(Yh + base)     = __nv_bfloat162(h[0], h[1]);
    *(__nv_bfloat162*)(Yh + base + 2) = __nv_bfloat162(h[2], h[3]);
    *(__nv_bfloat162*)(Yl + base)     = __nv_bfloat162(l[0], l[1]);
    *(__nv_bfloat162*)(Yl + base + 2) = __nv_bfloat162(l[2], l[3]);
}

// ============== HMMA GEMM (EPI 2 only): C = A@B^T + bias + R ================
#define SM_A_HI 0
#define SM_A_LO 16384
#define SM_B_HI 32768
#define SM_B_LO 65536
#define STAGE_B 98304

__global__ void __launch_bounds__(512, 1)
gemm_res(const __nv_bfloat16* __restrict__ Ah, const __nv_bfloat16* __restrict__ Al,
         const __nv_bfloat16* __restrict__ Bh, const __nv_bfloat16* __restrict__ Bl,
         const float* __restrict__ bias, const float* __restrict__ R,
         float* __restrict__ C, int M, int N, int K)
{
    extern __shared__ __align__(128) char sm[];
    uint32_t sb = smem_u32(sm);
    int tid  = threadIdx.x;
    int wid  = tid >> 5;
    int lane = tid & 31;
    int wm = wid & 1, wn = wid >> 1;
    int bm = blockIdx.y * 128, bn = blockIdx.x * 256;
    int m0 = wm * 64, n0 = wn * 32;

    int laneRow = lane & 15;
    int laneK   = (lane >> 4) * 16;
    uint32_t xorA = (uint32_t)((laneRow & 7) << 4);

    float acc[4][4][4];
    #pragma unroll
    for (int i = 0; i < 4; i++)
        #pragma unroll
        for (int j = 0; j < 4; j++)
            #pragma unroll
            for (int q = 0; q < 4; q++) acc[i][j][q] = 0.f;

    const int NCH = K >> 6;

    auto load_stage = [&](int s, int chunk) {
        uint32_t st = sb + s * STAGE_B;
        int k0 = chunk * 64;
        #pragma unroll
        for (int it = 0; it < 2; it++) {
            int idx = tid + it * 512;
            int row = idx >> 3, c = idx & 7;
            uint32_t d = st + row * 128 + (uint32_t)((c * 16) ^ ((row & 7) << 4));
            size_t go = (size_t)(bm + row) * K + k0 + c * 8;
            cp16(d + SM_A_HI, Ah + go);
            cp16(d + SM_A_LO, Al + go);
        }
        #pragma unroll
        for (int it = 0; it < 4; it++) {
            int idx = tid + it * 512;
            int row = idx >> 3, c = idx & 7;
            uint32_t d = st + row * 128 + (uint32_t)((c * 16) ^ ((row & 7) << 4));
            size_t go = (size_t)(bn + row) * K + k0 + c * 8;
            cp16(d + SM_B_HI, Bh + go);
            cp16(d + SM_B_LO, Bl + go);
        }
    };

    load_stage(0, 0);
    cp_commit();

    for (int chunk = 0; chunk < NCH; chunk++) {
        int s = chunk & 1;
        if (chunk + 1 < NCH) {
            load_stage(s ^ 1, chunk + 1);
            cp_commit();
            cp_wait1();
        } else {
            cp_wait0();
        }
        __syncthreads();

        uint32_t st = sb + s * STAGE_B;
        #pragma unroll
        for (int ks = 0; ks < 4; ks++) {
            uint32_t kb = (uint32_t)((ks * 32 + laneK) ^ xorA);
            uint32_t ah[4][4], bh[2][4];
            #pragma unroll
            for (int i = 0; i < 4; i++)
                ldsm_x4(ah[i], st + SM_A_HI + (uint32_t)(m0 + i*16 + laneRow) * 128 + kb);
            #pragma unroll
            for (int p = 0; p < 2; p++)
                ldsm_x4(bh[p], st + SM_B_HI + (uint32_t)(n0 + p*16 + laneRow) * 128 + kb);
            #pragma unroll
            for (int i = 0; i < 4; i++)
                #pragma unroll
                for (int j = 0; j < 4; j++)
                    mma16816(acc[i][j], ah[i], bh[j>>1][j&1], bh[j>>1][2 + (j&1)]);
            {
                uint32_t al[4][4];
                #pragma unroll
                for (int i = 0; i < 4; i++)
                    ldsm_x4(al[i], st + SM_A_LO + (uint32_t)(m0 + i*16 + laneRow) * 128 + kb);
                #pragma unroll
                for (int i = 0; i < 4; i++)
                    #pragma unroll
                    for (int j = 0; j < 4; j++)
                        mma16816(acc[i][j], al[i], bh[j>>1][j&1], bh[j>>1][2 + (j&1)]);
            }
            {
                uint32_t bl[2][4];
                #pragma unroll
                for (int p = 0; p < 2; p++)
                    ldsm_x4(bl[p], st + SM_B_LO + (uint32_t)(n0 + p*16 + laneRow) * 128 + kb);
                #pragma unroll
                for (int i = 0; i < 4; i++)
                    #pragma unroll
                    for (int j = 0; j < 4; j++)
                        mma16816(acc[i][j], ah[i], bl[j>>1][j&1], bl[j>>1][2 + (j&1)]);
            }
        }
        __syncthreads();
    }

    int group = lane >> 2, tq = lane & 3;
    #pragma unroll
    for (int j = 0; j < 4; j++) {
        int n = bn + n0 + j*8 + tq*2;
        float bv0 = bias[n], bv1 = bias[n+1];
        #pragma unroll
        for (int i = 0; i < 4; i++) {
            int m = bm + m0 + i*16 + group;
            size_t off0 = (size_t)m * N + n;
            size_t off1 = (size_t)(m + 8) * N + n;
            float2 r0 = *(const float2*)(R + off0);
            float2 r1 = *(const float2*)(R + off1);
            *(float2*)(C + off0) = make_float2(acc[i][j][0] + bv0 + r0.x, acc[i][j][1] + bv1 + r0.y);
            *(float2*)(C + off1) = make_float2(acc[i][j][2] + bv0 + r1.x, acc[i][j][3] + bv1 + r1.y);
        }
    }
}

// ====== fused Q/K/V/U projection: one launch, grid.z selects weight ========
__global__ void __launch_bounds__(512, 1)
proj4(const __nv_bfloat16* __restrict__ Ah, const __nv_bfloat16* __restrict__ Al,
      const __nv_bfloat16* __restrict__ WThG, const __nv_bfloat16* __restrict__ WTlG,
      const float* __restrict__ bq, const float* __restrict__ bk,
      const float* __restrict__ bv, const float* __restrict__ bu,
      __nv_bfloat16* __restrict__ Qh, __nv_bfloat16* __restrict__ Ql,
      __nv_bfloat16* __restrict__ Kh, __nv_bfloat16* __restrict__ Kl,
      __nv_bfloat16* __restrict__ VTh, __nv_bfloat16* __restrict__ VTl,
      float* __restrict__ Uf)
{
    extern __shared__ __align__(128) char sm[];
    uint32_t sb = smem_u32(sm);
    int tid  = threadIdx.x;
    int wid  = tid >> 5;
    int lane = tid & 31;
    int wm = wid & 1, wn = wid >> 1;
    int z  = blockIdx.z;
    int bm = blockIdx.y * 128, bn = blockIdx.x * 256;
    int m0 = wm * 64, n0 = wn * 32;
    const int K = 1024, N = 1024;

    const __nv_bfloat16* Bh = WThG + (size_t)z * W1M;
    const __nv_bfloat16* Bl = WTlG + (size_t)z * W1M;
    const float* bias = (z == 0) ? bq : (z == 1) ? bk : (z == 2) ? bv : bu;

    int laneRow = lane & 15;
    int laneK   = (lane >> 4) * 16;
    uint32_t xorA = (uint32_t)((laneRow & 7) << 4);

    float acc[4][4][4];
    #pragma unroll
    for (int i = 0; i < 4; i++)
        #pragma unroll
        for (int j = 0; j < 4; j++)
            #pragma unroll
            for (int q = 0; q < 4; q++) acc[i][j][q] = 0.f;

    const int NCH = K >> 6;

    auto load_stage = [&](int s, int chunk) {
        uint32_t st = sb + s * STAGE_B;
        int k0 = chunk * 64;
        #pragma unroll
        for (int it = 0; it < 2; it++) {
            int idx = tid + it * 512;
            int row = idx >> 3, c = idx & 7;
            uint32_t d = st + row * 128 + (uint32_t)((c * 16) ^ ((row & 7) << 4));
            size_t go = (size_t)(bm + row) * K + k0 + c * 8;
            cp16(d + SM_A_HI, Ah + go);
            cp16(d + SM_A_LO, Al + go);
        }
        #pragma unroll
        for (int it = 0; it < 4; it++) {
            int idx = tid + it * 512;
            int row = idx >> 3, c = idx & 7;
            uint32_t d = st + row * 128 + (uint32_t)((c * 16) ^ ((row & 7) << 4));
            size_t go = (size_t)(bn + row) * K + k0 + c * 8;
            cp16(d + SM_B_HI, Bh + go);
            cp16(d + SM_B_LO, Bl + go);
        }
    };

    load_stage(0, 0);
    cp_commit();

    for (int chunk = 0; chunk < NCH; chunk++) {
        int s = chunk & 1;
        if (chunk + 1 < NCH) {
            load_stage(s ^ 1, chunk + 1);
            cp_commit();
            cp_wait1();
        } else {
            cp_wait0();
        }
        __syncthreads();

        uint32_t st = sb + s * STAGE_B;
        #pragma unroll
        for (int ks = 0; ks < 4; ks++) {
            uint32_t kb = (uint32_t)((ks * 32 + laneK) ^ xorA);
            uint32_t ah[4][4], bh[2][4];
            #pragma unroll
            for (int i = 0; i < 4; i++)
                ldsm_x4(ah[i], st + SM_A_HI + (uint32_t)(m0 + i*16 + laneRow) * 128 + kb);
            #pragma unroll
            for (int p = 0; p < 2; p++)
                ldsm_x4(bh[p], st + SM_B_HI + (uint32_t)(n0 + p*16 + laneRow) * 128 + kb);
            #pragma unroll
            for (int i = 0; i < 4; i++)
                #pragma unroll
                for (int j = 0; j < 4; j++)
                    mma16816(acc[i][j], ah[i], bh[j>>1][j&1], bh[j>>1][2 + (j&1)]);
            {
                uint32_t al[4][4];
                #pragma unroll
                for (int i = 0; i < 4; i++)
                    ldsm_x4(al[i], st + SM_A_LO + (uint32_t)(m0 + i*16 + laneRow) * 128 + kb);
                #pragma unroll
                for (int i = 0; i < 4; i++)
                    #pragma unroll
                    for (int j = 0; j < 4; j++)
                        mma16816(acc[i][j], al[i], bh[j>>1][j&1], bh[j>>1][2 + (j&1)]);
            }
            {
                uint32_t bl[2][4];
                #pragma unroll
                for (int p = 0; p < 2; p++)
                    ldsm_x4(bl[p], st + SM_B_LO + (uint32_t)(n0 + p*16 + laneRow) * 128 + kb);
                #pragma unroll
                for (int i = 0; i < 4; i++)
                    #pragma unroll
                    for (int j = 0; j < 4; j++)
                        mma16816(acc[i][j], ah[i], bl[j>>1][j&1], bl[j>>1][2 + (j&1)]);
            }
        }
        __syncthreads();
    }

    int group = lane >> 2, tq = lane & 3;
    __nv_bfloat16* Yh = (z == 0) ? Qh : Kh;
    __nv_bfloat16* Yl = (z == 0) ? Ql : Kl;
    #pragma unroll
    for (int j = 0; j < 4; j++) {
        int n = bn + n0 + j*8 + tq*2;
        float bv0 = bias[n], bv1 = bias[n+1];
        #pragma unroll
        for (int i = 0; i < 4; i++) {
            int m = bm + m0 + i*16 + group;
            float v0 = acc[i][j][0] + bv0, v1 = acc[i][j][1] + bv1;
            float v2 = acc[i][j][2] + bv0, v3 = acc[i][j][3] + bv1;
            if (z <= 1) {
                __nv_bfloat16 h0,l0,h1,l1,h2,l2,h3,l3;
                split_bf16(v0,h0,l0); split_bf16(v1,h1,l1);
                split_bf16(v2,h2,l2); split_bf16(v3,h3,l3);
                size_t off0 = (size_t)m * N + n;
                size_t off1 = (size_t)(m + 8) * N + n;
                *(__nv_bfloat162*)(Yh + off0) = __nv_bfloat162(h0, h1);
                *(__nv_bfloat162*)(Yl + off0) = __nv_bfloat162(l0, l1);
                *(__nv_bfloat162*)(Yh + off1) = __nv_bfloat162(h2, h3);
                *(__nv_bfloat162*)(Yl + off1) = __nv_bfloat162(l2, l3);
            } else if (z == 2) {
                __nv_bfloat16 h0,l0,h1,l1,h2,l2,h3,l3;
                split_bf16(v0,h0,l0); split_bf16(v1,h1,l1);
                split_bf16(v2,h2,l2); split_bf16(v3,h3,l3);
                int bi = m >> 11, tt = m & 2047;
                int hh = n >> 6,  dd = n & 63;
                size_t vb = ((size_t)((bi*16 + hh)*64 + dd)) * 2048 + tt;
                VTh[vb]        = h0;  VTl[vb]        = l0;
                VTh[vb + 2048] = h1;  VTl[vb + 2048] = l1;
                VTh[vb + 8]    = h2;  VTl[vb + 8]    = l2;
                VTh[vb + 2056] = h3;  VTl[vb + 2056] = l3;
            } else {
                size_t off0 = (size_t)m * N + n;
                size_t off1 = (size_t)(m + 8) * N + n;
                *(float2*)(Uf + off0) = make_float2(siluf(v0), siluf(v1));
                *(float2*)(Uf + off1) = make_float2(siluf(v2), siluf(v3));
            }
        }
    }
}

// ====== w1 GEMM + swiglu fusion ============================================
#define W_A_HI  0
#define W_A_LO  16384
#define W_B1_HI 32768
#define W_B1_LO 49152
#define W_B2_HI 65536
#define W_B2_LO 81920
#define STAGE_W 98304

__global__ void __launch_bounds__(512, 1)
gemm_w1sg(const __nv_bfloat16* __restrict__ Ah, const __nv_bfloat16* __restrict__ Al,
          const __nv_bfloat16* __restrict__ Bh, const __nv_bfloat16* __restrict__ Bl,
          const float* __restrict__ b1,
          __nv_bfloat16* __restrict__ Yh, __nv_bfloat16* __restrict__ Yl)
{
    extern __shared__ __align__(128) char sm[];
    uint32_t sb = smem_u32(sm);
    int tid  = threadIdx.x;
    int wid  = tid >> 5;
    int lane = tid & 31;
    int wm = wid & 1, wn = wid >> 1;
    int bm = blockIdx.y * 128, bn = blockIdx.x * 128;
    int m0 = wm * 64, n0 = wn * 16;
    const int K = 1024;

    int laneRow = lane & 15;
    int laneK   = (lane >> 4) * 16;
    uint32_t xorA = (uint32_t)((laneRow & 7) << 4);

    float acc1[4][2][4], acc2[4][2][4];
    #pragma unroll
    for (int i = 0; i < 4; i++)
        #pragma unroll
        for (int j = 0; j < 2; j++)
            #pragma unroll
            for (int q = 0; q < 4; q++) { acc1[i][j][q] = 0.f; acc2[i][j][q] = 0.f; }

    const int NCH = K >> 6;

    auto load_stage = [&](int s, int chunk) {
        uint32_t st = sb + s * STAGE_W;
        int k0 = chunk * 64;
        #pragma unroll
        for (int it = 0; it < 2; it++) {
            int idx = tid + it * 512;
            int row = idx >> 3, c = idx & 7;
            uint32_t d = st + row * 128 + (uint32_t)((c * 16) ^ ((row & 7) << 4));
            size_t goA  = (size_t)(bm + row) * K + k0 + c * 8;
            size_t goB1 = (size_t)(bn + row) * K + k0 + c * 8;
            size_t goB2 = (size_t)(1024 + bn + row) * K + k0 + c * 8;
            cp16(d + W_A_HI,  Ah + goA);
            cp16(d + W_A_LO,  Al + goA);
            cp16(d + W_B1_HI, Bh + goB1);
            cp16(d + W_B1_LO, Bl + goB1);
            cp16(d + W_B2_HI, Bh + goB2);
            cp16(d + W_B2_LO, Bl + goB2);
        }
    };

    load_stage(0, 0);
    cp_commit();

    for (int chunk = 0; chunk < NCH; chunk++) {
        int s = chunk & 1;
        if (chunk + 1 < NCH) {
            load_stage(s ^ 1, chunk + 1);
            cp_commit();
            cp_wait1();
        } else {
            cp_wait0();
        }
        __syncthreads();

        uint32_t st = sb + s * STAGE_W;
        #pragma unroll
        for (int ks = 0; ks < 4; ks++) {
            uint32_t kb = (uint32_t)((ks * 32 + laneK) ^ xorA);
            uint32_t ah[4][4], b1h[4], b2h[4];
            #pragma unroll
            for (int i = 0; i < 4; i++)
                ldsm_x4(ah[i], st + W_A_HI + (uint32_t)(m0 + i*16 + laneRow) * 128 + kb);
            ldsm_x4(b1h, st + W_B1_HI + (uint32_t)(n0 + laneRow) * 128 + kb);
            ldsm_x4(b2h, st + W_B2_HI + (uint32_t)(n0 + laneRow) * 128 + kb);
            #pragma unroll
            for (int i = 0; i < 4; i++)
                #pragma unroll
                for (int j = 0; j < 2; j++) {
                    mma16816(acc1[i][j], ah[i], b1h[j], b1h[2 + j]);
                    mma16816(acc2[i][j], ah[i], b2h[j], b2h[2 + j]);
                }
            {
                uint32_t al[4][4];
                #pragma unroll
                for (int i = 0; i < 4; i++)
                    ldsm_x4(al[i], st + W_A_LO + (uint32_t)(m0 + i*16 + laneRow) * 128 + kb);
                #pragma unroll
                for (int i = 0; i < 4; i++)
                    #pragma unroll
                    for (int j = 0; j < 2; j++) {
                        mma16816(acc1[i][j], al[i], b1h[j], b1h[2 + j]);
                        mma16816(acc2[i][j], al[i], b2h[j], b2h[2 + j]);
                    }
            }
            {
                uint32_t b1l[4], b2l[4];
                ldsm_x4(b1l, st + W_B1_LO + (uint32_t)(n0 + laneRow) * 128 + kb);
                ldsm_x4(b2l, st + W_B2_LO + (uint32_t)(n0 + laneRow) * 128 + kb);
                #pragma unroll
                for (int i = 0; i < 4; i++)
                    #pragma unroll
                    for (int j = 0; j < 2; j++) {
                        mma16816(acc1[i][j], ah[i], b1l[j], b1l[2 + j]);
                        mma16816(acc2[i][j], ah[i], b2l[j], b2l[2 + j]);
                    }
            }
        }
        __syncthreads();
    }

    int group = lane >> 2, tq = lane & 3;
    #pragma unroll
    for (int j = 0; j < 2; j++) {
        int n = bn + n0 + j*8 + tq*2;
        float c10 = b1[n], c11 = b1[n+1];
        float c20 = b1[1024 + n], c21 = b1[1025 + n];
        #pragma unroll
        for (int i = 0; i < 4; i++) {
            int m = bm + m0 + i*16 + group;
            float y0 = siluf(acc1[i][j][0] + c10) * (acc2[i][j][0] + c20);
            float y1 = siluf(acc1[i][j][1] + c11) * (acc2[i][j][1] + c21);
            float y2 = siluf(acc1[i][j][2] + c10) * (acc2[i][j][2] + c20);
            float y3 = siluf(acc1[i][j][3] + c11) * (acc2[i][j][3] + c21);
            __nv_bfloat16 h0,l0,h1,l1,h2,l2,h3,l3;
            split_bf16(y0,h0,l0); split_bf16(y1,h1,l1);
            split_bf16(y2,h2,l2); split_bf16(y3,h3,l3);
            size_t off0 = (size_t)m * 1024 + n;
            size_t off1 = (size_t)(m + 8) * 1024 + n;
            *(__nv_bfloat162*)(Yh + off0) = __nv_bfloat162(h0, h1);
            *(__nv_bfloat162*)(Yl + off0) = __nv_bfloat162(l0, l1);
            *(__nv_bfloat162*)(Yh + off1) = __nv_bfloat162(h2, h3);
            *(__nv_bfloat162*)(Yl + off1) = __nv_bfloat162(l2, l3);
        }
    }
}

// ===== tensor-core fused SiLU-attention: 16 warps, key-dimension split ======
// Warp w: m-rows (w&7)*16..+16, key half (w>>3). Each warp keeps a partial O
// accumulator over its 64 keys; pairs merge via smem once at the end.
#define A_SQH 0u
#define A_SQL 16384u
#define A_SK  32768u       // + s*32768 : KH, KL(+16384)
#define A_SVT 98304u       // + s*32768 : VTH, VTL(+16384)
#define A_PB  163840u      // + s*512
#define A_RED A_SK         // reduction area reuses K stage 0 (32KB)
#define ATT_SMEM 164864

__global__ void __launch_bounds__(512, 1)
attn_tc(const __nv_bfloat16* __restrict__ Qh, const __nv_bfloat16* __restrict__ Ql,
        const __nv_bfloat16* __restrict__ Kh, const __nv_bfloat16* __restrict__ Kl,
        const __nv_bfloat16* __restrict__ VTh, const __nv_bfloat16* __restrict__ VTl,
        const float* __restrict__ PB, float* __restrict__ O)
{
    extern __shared__ __align__(128) char sm[];
    uint32_t sb = smem_u32(sm);
    int tid  = threadIdx.x;
    int wid  = tid >> 5;
    int lane = tid & 31;
    int qt = blockIdx.x, h = blockIdx.y, b = blockIdx.z;
    int mw = wid & 7;           // m-tile
    int kw = wid >> 3;          // key half (0/1)
    int m0 = mw * 16;
    int ntb = kw * 4;           // key sub-tile base (16-key tiles)

    int laneRow = lane & 15;
    int laneK   = (lane >> 4) * 16;
    uint32_t xorA = (uint32_t)((laneRow & 7) << 4);
    int group = lane >> 2, tq = lane & 3;
    uint32_t rowbK = (uint32_t)laneRow * 128;
    uint32_t rowbV = (uint32_t)laneRow * 256;

    auto load_q = [&]() {
        #pragma unroll
        for (int it = 0; it < 2; it++) {
            int idx = tid + it * 512;
            int row = idx >> 3, c = idx & 7;
            uint32_t d = row * 128 + (uint32_t)((c * 16) ^ ((row & 7) << 4));
            size_t go = ((size_t)(b*SEQ + qt*128 + row)) * D_MODEL + h*64 + c*8;
            cp16(sb + A_SQH + d, Qh + go);
            cp16(sb + A_SQL + d, Ql + go);
        }
    };
    auto load_kv = [&](int s, int kt) {
        uint32_t kbase = sb + A_SK + (uint32_t)s * 32768u;
        #pragma unroll
        for (int it = 0; it < 2; it++) {
            int idx = tid + it * 512;
            int row = idx >> 3, c = idx & 7;
            uint32_t d = row * 128 + (uint32_t)((c * 16) ^ ((row & 7) << 4));
            size_t go = ((size_t)(b*SEQ + kt*128 + row)) * D_MODEL + h*64 + c*8;
            cp16(kbase + d, Kh + go);
            cp16(kbase + 16384u + d, Kl + go);
        }
        uint32_t vbase = sb + A_SVT + (uint32_t)s * 32768u;
        #pragma unroll
        for (int it = 0; it < 2; it++) {
            int idx = tid + it * 512;
            int row = idx >> 4, c = idx & 15;
            uint32_t d = row * 256 + (uint32_t)((c * 16) ^ ((row & 7) << 4));
            size_t go = ((size_t)((b*16 + h)*64 + row)) * 2048 + kt*128 + c*8;
            cp16(vbase + d, VTh + go);
            cp16(vbase + 16384u + d, VTl + go);
        }
        if (tid < 128) {
            float v = PB[(size_t)(kt*128 + tid) * N_HEADS + h];
            *(float*)(sm + A_PB + (uint32_t)s * 512u + tid * 4) = v;
        }
    };

    float accO[8][4];
    #pragma unroll
    for (int f = 0; f < 8; f++)
        #pragma unroll
        for (int q = 0; q < 4; q++) accO[f][q] = 0.f;

    load_q(); cp_commit();
    load_kv(0, 0); cp_commit();
    cp_wait1();
    __syncthreads();

    // hoist Q-hi fragments (loop-invariant); Q-lo re-loaded per use
    uint32_t qfh[4][4];
    #pragma unroll
    for (int ks = 0; ks < 4; ks++) {
        uint32_t kb = (uint32_t)((ks * 32 + laneK) ^ xorA);
        ldsm_x4(qfh[ks], sb + A_SQH + (uint32_t)m0 * 128 + rowbK + kb);
    }

    for (int kt = 0; kt < SEQ/128; kt++) {
        int s = kt & 1;
        if (kt + 1 < SEQ/128) {
            load_kv(s ^ 1, kt + 1);
            cp_commit();
            cp_wait1();
        } else {
            cp_wait0();
        }
        __syncthreads();

        // ---- S = Q @ K^T over this warp's 4 key sub-tiles ----
        float sc[8][4];
        #pragma unroll
        for (int f = 0; f < 8; f++)
            #pragma unroll
            for (int q = 0; q < 4; q++) sc[f][q] = 0.f;

        uint32_t kst = sb + A_SK + (uint32_t)s * 32768u + (uint32_t)ntb * 2048u;
        #pragma unroll
        for (int ks = 0; ks < 4; ks++) {
            uint32_t kb = (uint32_t)((ks * 32 + laneK) ^ xorA);
            uint32_t qfl[4];
            ldsm_x4(qfl, sb + A_SQL + (uint32_t)m0 * 128 + rowbK + kb);
            #pragma unroll
            for (int nt = 0; nt < 4; nt++) {
                uint32_t kf[4];
                ldsm_x4(kf, kst + (uint32_t)nt * 2048u + rowbK + kb);
                mma16816(sc[2*nt],   qfh[ks], kf[0], kf[2]);
                mma16816(sc[2*nt+1], qfh[ks], kf[1], kf[3]);
                mma16816(sc[2*nt],   qfl,     kf[0], kf[2]);
                mma16816(sc[2*nt+1], qfl,     kf[1], kf[3]);
                uint32_t kl[4];
                ldsm_x4(kl, kst + 16384u + (uint32_t)nt * 2048u + rowbK + kb);
                mma16816(sc[2*nt],   qfh[ks], kl[0], kl[2]);
                mma16816(sc[2*nt+1], qfh[ks], kl[1], kl[3]);
            }
        }

        // ---- silu(scale*S + pb), split hi/lo, repack as A-frags ----
        uint32_t sfh[4][4], sfl[4][4];
        const float* pbs = (const float*)(sm + A_PB + (uint32_t)s * 512u);
        #pragma unroll
        for (int nt = 0; nt < 4; nt++) {
            #pragma unroll
            for (int half = 0; half < 2; half++) {
                int f = 2*nt + half;
                int tcol = ntb*16 + nt*16 + half*8 + tq*2;
                float pb0 = pbs[tcol], pb1 = pbs[tcol + 1];
                float w0 = siluf(sc[f][0] * 0.125f + pb0);
                float w1 = siluf(sc[f][1] * 0.125f + pb1);
                float w2 = siluf(sc[f][2] * 0.125f + pb0);
                float w3 = siluf(sc[f][3] * 0.125f + pb1);
                __nv_bfloat16 h0,l0,h1,l1,h2,l2,h3,l3;
                split_bf16(w0,h0,l0); split_bf16(w1,h1,l1);
                split_bf16(w2,h2,l2); split_bf16(w3,h3,l3);
                sfh[nt][half*2]     = pack_bf16(h0, h1);
                sfh[nt][half*2 + 1] = pack_bf16(h2, h3);
                sfl[nt][half*2]     = pack_bf16(l0, l1);
                sfl[nt][half*2 + 1] = pack_bf16(l2, l3);
            }
        }

        // ---- O += S @ V over this warp's 4 key slices ----
        uint32_t vst = sb + A_SVT + (uint32_t)s * 32768u;
        #pragma unroll
        for (int ks = 0; ks < 4; ks++) {
            int gks = ntb + ks;   // global key slice 0..7
            uint32_t kb = (uint32_t)((gks * 32 + laneK) ^ xorA);
            #pragma unroll
            for (int dn = 0; dn < 4; dn++) {
                uint32_t vf[4];
                ldsm_x4(vf, vst + (uint32_t)dn * 4096u + rowbV + kb);
                mma16816(accO[2*dn],   sfh[ks], vf[0], vf[2]);
                mma16816(accO[2*dn+1], sfh[ks], vf[1], vf[3]);
                mma16816(accO[2*dn],   sfl[ks], vf[0], vf[2]);
                mma16816(accO[2*dn+1], sfl[ks], vf[1], vf[3]);
                uint32_t vl[4];
                ldsm_x4(vl, vst + 16384u + (uint32_t)dn * 4096u + rowbV + kb);
                mma16816(accO[2*dn],   sfh[ks], vl[0], vl[2]);
                mma16816(accO[2*dn+1], sfh[ks], vl[1], vl[3]);
            }
        }
        __syncthreads();
    }

    // ---- merge key-half partials: warps 8-15 stash, warps 0-7 add + store ----
    if (kw == 1) {
        float* red = (float*)(sm + A_RED) + ((size_t)mw * 32 + lane) * 32;
        #pragma unroll
        for (int f = 0; f < 8; f++) {
            red[f*4+0] = accO[f][0]; red[f*4+1] = accO[f][1];
            red[f*4+2] = accO[f][2]; red[f*4+3] = accO[f][3];
        }
    }
    __syncthreads();
    if (kw == 0) {
        const float* red = (const float*)(sm + A_RED) + ((size_t)mw * 32 + lane) * 32;
        #pragma unroll
        for (int dn = 0; dn < 4; dn++) {
            #pragma unroll
            for (int half = 0; half < 2; half++) {
                int f = 2*dn + half;
                float o0 = accO[f][0] + red[f*4+0];
                float o1 = accO[f][1] + red[f*4+1];
                float o2 = accO[f][2] + red[f*4+2];
                float o3 = accO[f][3] + red[f*4+3];
                int col = h*64 + dn*16 + half*8 + tq*2;
                int row = b*SEQ + qt*128 + m0 + group;
                *(float2*)(O + (size_t)row * D_MODEL + col) = make_float2(o0, o1);
                *(float2*)(O + (size_t)(row + 8) * D_MODEL + col) = make_float2(o2, o3);
            }
        }
    }
}

// ---------------- launch ----------------------------------------------------
extern "C" void kernel_launch(void* const* d_in, const int* in_sizes, int n_in,
                              void* d_out, int out_size)
{
    const float* x      = (const float*)d_in[0];
    const float* pb     = (const float*)d_in[2];
    const float* wq     = (const float*)d_in[3];
    const float* bq     = (const float*)d_in[4];
    const float* wk     = (const float*)d_in[5];
    const float* bk_    = (const float*)d_in[6];
    const float* wv     = (const float*)d_in[7];
    const float* bv     = (const float*)d_in[8];
    const float* wu     = (const float*)d_in[9];
    const float* bu     = (const float*)d_in[10];
    const float* g_ams  = (const float*)d_in[11];
    const float* w0     = (const float*)d_in[12];
    const float* b0     = (const float*)d_in[13];
    const float* w1     = (const float*)d_in[14];
    const float* b1     = (const float*)d_in[15];
    const float* w2     = (const float*)d_in[16];
    const float* b2     = (const float*)d_in[17];
    const float* g_mffn = (const float*)d_in[18];
    float* out = (float*)d_out;

    float *Qf, *Kf, *Vf, *Uf, *AOf, *Of;
    __nv_bfloat16 *A1h, *A1l, *A2h, *A2l, *WTh, *WTl;
    cudaGetSymbolAddress((void**)&Qf,  g_Q);
    cudaGetSymbolAddress((void**)&Kf,  g_K);
    cudaGetSymbolAddress((void**)&Vf,  g_V);
    cudaGetSymbolAddress((void**)&Uf,  g_U);
    cudaGetSymbolAddress((void**)&AOf, g_AO);
    cudaGetSymbolAddress((void**)&Of,  g_O);
    cudaGetSymbolAddress((void**)&A1h, g_A1h);
    cudaGetSymbolAddress((void**)&A1l, g_A1l);
    cudaGetSymbolAddress((void**)&A2h, g_A2h);
    cudaGetSymbolAddress((void**)&A2l, g_A2l);
    cudaGetSymbolAddress((void**)&WTh, g_WTh);
    cudaGetSymbolAddress((void**)&WTl, g_WTl);

    const size_t NEL = (size_t)M_ROWS * D_MODEL;
    __nv_bfloat16 *Qhb = (__nv_bfloat16*)Qf,  *Qlb = Qhb + NEL;
    __nv_bfloat16 *Khb = (__nv_bfloat16*)Kf,  *Klb = Khb + NEL;
    __nv_bfloat16 *VTh = (__nv_bfloat16*)Vf,  *VTl = VTh + NEL;

    __nv_bfloat16 *T0_h = WTh + (size_t)4*W1M, *T0_l = WTl + (size_t)4*W1M;
    __nv_bfloat16 *T2_h = WTh + (size_t)5*W1M, *T2_l = WTl + (size_t)5*W1M;
    __nv_bfloat16 *T1_h = WTh + (size_t)6*W1M, *T1_l = WTl + (size_t)6*W1M;

    const int GSM = 2 * STAGE_B;
    cudaFuncSetAttribute(gemm_res,  cudaFuncAttributeMaxDynamicSharedMemorySize, GSM);
    cudaFuncSetAttribute(proj4,     cudaFuncAttributeMaxDynamicSharedMemorySize, GSM);
    cudaFuncSetAttribute(gemm_w1sg, cudaFuncAttributeMaxDynamicSharedMemorySize, 2*STAGE_W);
    cudaFuncSetAttribute(attn_tc,   cudaFuncAttributeMaxDynamicSharedMemorySize, ATT_SMEM);

    wtsplit_all<<<8192, dim3(32, 8)>>>(wq, wk, wv, wu, w0, w2, w1, WTh, WTl);
    rmsnorm_tc<<<M_ROWS, 256>>>(x, g_ams, A1h, A1l);
    proj4<<<dim3(4, 32, 4), 512, GSM>>>(A1h, A1l, WTh, WTl, bq, bk_, bv, bu,
                                        Qhb, Qlb, Khb, Klb, VTh, VTl, Uf);
    attn_tc<<<dim3(SEQ/128, N_HEADS, BATCH), 512, ATT_SMEM>>>(Qhb, Qlb, Khb, Klb, VTh, VTl, pb, AOf);
    ams_tc<<<M_ROWS, 256>>>(AOf, g_ams, Uf, A2h, A2l);
    gemm_res<<<dim3(4, 32), 512, GSM>>>(A2h, A2l, T0_h, T0_l, b0, x, Of, M_ROWS, 1024, 1024);
    rmsnorm_tc<<<M_ROWS, 256>>>(Of, g_mffn, A1h, A1l);
    gemm_w1sg<<<dim3(8, 32), 512, 2*STAGE_W>>>(A1h, A1l, T1_h, T1_l, b1, A2h, A2l);
    gemm_res<<<dim3(4, 32), 512, GSM>>>(A2h, A2l, T2_h, T2_l, b2, Of, out, M_ROWS, 1024, 1024);
}

// round 11
// speedup vs baseline: 1.1293x; 1.0098x over previous
#include <cuda_runtime.h>
#include <cuda_bf16.h>
#include <cstdint>
#include <math.h>

#define D_MODEL 1024
#define N_HEADS 16
#define DH      64
#define BATCH   2
#define SEQ     2048
#define M_ROWS  (BATCH*SEQ)   // 4096

// ---------------- scratch (static device globals; no allocations) ----------
__device__ float g_Q  [M_ROWS*D_MODEL];   // aliased: Qh/Ql bf16
__device__ float g_K  [M_ROWS*D_MODEL];   // aliased: Kh/Kl bf16
__device__ float g_V  [M_ROWS*D_MODEL];   // aliased: VTh/VTl bf16 (transposed per head)
__device__ float g_U  [M_ROWS*D_MODEL];
__device__ float g_AO [M_ROWS*D_MODEL];
__device__ float g_O  [M_ROWS*D_MODEL];

__device__ __nv_bfloat16 g_A1h[M_ROWS*D_MODEL];
__device__ __nv_bfloat16 g_A1l[M_ROWS*D_MODEL];
__device__ __nv_bfloat16 g_A2h[M_ROWS*D_MODEL];
__device__ __nv_bfloat16 g_A2l[M_ROWS*D_MODEL];

__device__ __nv_bfloat16 g_WTh[8*1024*1024];
__device__ __nv_bfloat16 g_WTl[8*1024*1024];

#define W1M (1024*1024)

__device__ __forceinline__ float siluf(float z) {
    return z * (1.0f / (1.0f + __expf(-z)));
}

__device__ __forceinline__ uint32_t smem_u32(const void* p) {
    uint32_t a;
    asm("{ .reg .u64 t; cvta.to.shared.u64 t, %1; cvt.u32.u64 %0, t; }" : "=r"(a) : "l"(p));
    return a;
}

__device__ __forceinline__ void ldsm_x4(uint32_t* r, uint32_t a) {
    asm volatile("ldmatrix.sync.aligned.m8n8.x4.shared.b16 {%0,%1,%2,%3}, [%4];"
                 : "=r"(r[0]), "=r"(r[1]), "=r"(r[2]), "=r"(r[3]) : "r"(a));
}

__device__ __forceinline__ void mma16816(float* c, const uint32_t* a, uint32_t b0, uint32_t b1) {
    asm volatile("mma.sync.aligned.m16n8k16.row.col.f32.bf16.bf16.f32 "
                 "{%0,%1,%2,%3}, {%4,%5,%6,%7}, {%8,%9}, {%0,%1,%2,%3};"
                 : "+f"(c[0]), "+f"(c[1]), "+f"(c[2]), "+f"(c[3])
                 : "r"(a[0]), "r"(a[1]), "r"(a[2]), "r"(a[3]), "r"(b0), "r"(b1));
}

__device__ __forceinline__ void cp16(uint32_t dst, const void* src) {
    asm volatile("cp.async.cg.shared.global [%0], [%1], 16;" :: "r"(dst), "l"(src));
}
__device__ __forceinline__ void cp_commit() { asm volatile("cp.async.commit_group;"); }
__device__ __forceinline__ void cp_wait1()  { asm volatile("cp.async.wait_group 1;"); }
__device__ __forceinline__ void cp_wait0()  { asm volatile("cp.async.wait_group 0;"); }

__device__ __forceinline__ void split_bf16(float v, __nv_bfloat16& h, __nv_bfloat16& l) {
    h = __float2bfloat16(v);
    l = __float2bfloat16(v - __bfloat162float(h));
}

__device__ __forceinline__ uint32_t pack_bf16(__nv_bfloat16 a, __nv_bfloat16 b) {
    __nv_bfloat162 t(a, b);
    return *(uint32_t*)&t;
}

// ======= batched weight transpose + bf16 split (all 7 weights, 1 launch) ====
__global__ void __launch_bounds__(256)
wtsplit_all(const float* __restrict__ wq, const float* __restrict__ wk,
            const float* __restrict__ wv, const float* __restrict__ wu,
            const float* __restrict__ w0, const float* __restrict__ w2,
            const float* __restrict__ w1,
            __nv_bfloat16* __restrict__ WTh, __nv_bfloat16* __restrict__ WTl)
{
    __shared__ float t[32][33];
    int bid = blockIdx.x;
    const float* W; __nv_bfloat16 *Th, *Tl;
    int N, nx, ky;
    if (bid < 6144) {
        int w = bid >> 10, local = bid & 1023;
        switch (w) {
            case 0: W = wq; break; case 1: W = wk; break;
            case 2: W = wv; break; case 3: W = wu; break;
            case 4: W = w0; break; default: W = w2; break;
        }
        Th = WTh + (size_t)w * W1M; Tl = WTl + (size_t)w * W1M;
        N = 1024; nx = local & 31; ky = local >> 5;
    } else {
        int local = bid - 6144;
        W = w1; Th = WTh + (size_t)6 * W1M; Tl = WTl + (size_t)6 * W1M;
        N = 2048; nx = local & 63; ky = local >> 6;
    }
    const int K = 1024;
    int tx = threadIdx.x, ty = threadIdx.y;
    int n0 = nx * 32, k0 = ky * 32;
    #pragma unroll
    for (int i = 0; i < 4; i++)
        t[ty + i*8][tx] = W[(size_t)(k0 + ty + i*8) * N + n0 + tx];
    __syncthreads();
    #pragma unroll
    for (int i = 0; i < 4; i++) {
        float v = t[tx][ty + i*8];
        __nv_bfloat16 hi, lo;
        split_bf16(v, hi, lo);
        size_t off = (size_t)(n0 + ty + i*8) * K + k0 + tx;
        Th[off] = hi; Tl[off] = lo;
    }
}

// ---------------- RMSNorm -> bf16 hi/lo -------------------------------------
__global__ void __launch_bounds__(256)
rmsnorm_tc(const float* __restrict__ X, const float* __restrict__ g,
           __nv_bfloat16* __restrict__ Yh, __nv_bfloat16* __restrict__ Yl)
{
    int r = blockIdx.x, t = threadIdx.x;
    float4 v = ((const float4*)(X + (size_t)r * D_MODEL))[t];
    float ss = v.x*v.x + v.y*v.y + v.z*v.z + v.w*v.w;
    #pragma unroll
    for (int o = 16; o; o >>= 1) ss += __shfl_xor_sync(0xffffffffu, ss, o);
    __shared__ float ws[8]; __shared__ float s_inv;
    if ((t & 31) == 0) ws[t >> 5] = ss;
    __syncthreads();
    if (t == 0) {
        float tot = 0.f;
        #pragma unroll
        for (int i = 0; i < 8; i++) tot += ws[i];
        s_inv = rsqrtf(tot * (1.0f / D_MODEL) + 1e-8f);
    }
    __syncthreads();
    float iv = s_inv;
    float4 gv = ((const float4*)g)[t];
    float o[4] = {v.x*iv*gv.x, v.y*iv*gv.y, v.z*iv*gv.z, v.w*iv*gv.w};
    __nv_bfloat16 h[4], l[4];
    #pragma unroll
    for (int i = 0; i < 4; i++) split_bf16(o[i], h[i], l[i]);
    size_t base = (size_t)r * D_MODEL + t*4;
    *(__nv_bfloat162*)(Yh + base)     = __nv_bfloat162(h[0], h[1]);
    *(__nv_bfloat162*)(Yh + base + 2) = __nv_bfloat162(h[2], h[3]);
    *(__nv_bfloat162*)(Yl + base)     = __nv_bfloat162(l[0], l[1]);
    *(__nv_bfloat162*)(Yl + base + 2) = __nv_bfloat162(l[2], l[3]);
}

// -------- ams: out = rmsnorm(A, g) * U -> bf16 hi/lo ------------------------
__global__ void __launch_bounds__(256)
ams_tc(const float* __restrict__ A, const float* __restrict__ g,
       const float* __restrict__ U,
       __nv_bfloat16* __restrict__ Yh, __nv_bfloat16* __restrict__ Yl)
{
    int r = blockIdx.x, t = threadIdx.x;
    float4 v = ((const float4*)(A + (size_t)r * D_MODEL))[t];
    float ss = v.x*v.x + v.y*v.y + v.z*v.z + v.w*v.w;
    #pragma unroll
    for (int o = 16; o; o >>= 1) ss += __shfl_xor_sync(0xffffffffu, ss, o);
    __shared__ float ws[8]; __shared__ float s_inv;
    if ((t & 31) == 0) ws[t >> 5] = ss;
    __syncthreads();
    if (t == 0) {
        float tot = 0.f;
        #pragma unroll
        for (int i = 0; i < 8; i++) tot += ws[i];
        s_inv = rsqrtf(tot * (1.0f / D_MODEL) + 1e-8f);
    }
    __syncthreads();
    float iv = s_inv;
    float4 gv = ((const float4*)g)[t];
    float4 uv = ((const float4*)(U + (size_t)r * D_MODEL))[t];
    float o[4] = {v.x*iv*gv.x*uv.x, v.y*iv*gv.y*uv.y, v.z*iv*gv.z*uv.z, v.w*iv*gv.w*uv.w};
    __nv_bfloat16 h[4], l[4];
    #pragma unroll
    for (int i = 0; i < 4; i++) split_bf16(o[i], h[i], l[i]);
    size_t base = (size_t)r * D_MODEL + t*4;
    *(__nv_bfloat162*)(Yh + base)     = __nv_bfloat162(h[0], h[1]);
    *(__nv_bfloat162*)(Yh + base + 2) = __nv_bfloat162(h[2], h[3]);
    *(__nv_bfloat162*)(Yl + base)     = __nv_bfloat162(l[0], l[1]);
    *(__nv_bfloat162*)(Yl + base + 2) = __nv_bfloat162(l[2], l[3]);
}

// ============== HMMA GEMM (EPI 2 only): C = A@B^T + bias + R ================
#define SM_A_HI 0
#define SM_A_LO 16384
#define SM_B_HI 32768
#define SM_B_LO 65536
#define STAGE_B 98304

__global__ void __launch_bounds__(512, 1)
gemm_res(const __nv_bfloat16* __restrict__ Ah, const __nv_bfloat16* __restrict__ Al,
         const __nv_bfloat16* __restrict__ Bh, const __nv_bfloat16* __restrict__ Bl,
         const float* __restrict__ bias, const float* __restrict__ R,
         float* __restrict__ C, int M, int N, int K)
{
    extern __shared__ __align__(128) char sm[];
    uint32_t sb = smem_u32(sm);
    int tid  = threadIdx.x;
    int wid  = tid >> 5;
    int lane = tid & 31;
    int wm = wid & 1, wn = wid >> 1;
    int bm = blockIdx.y * 128, bn = blockIdx.x * 256;
    int m0 = wm * 64, n0 = wn * 32;

    int laneRow = lane & 15;
    int laneK   = (lane >> 4) * 16;
    uint32_t xorA = (uint32_t)((laneRow & 7) << 4);

    float acc[4][4][4];
    #pragma unroll
    for (int i = 0; i < 4; i++)
        #pragma unroll
        for (int j = 0; j < 4; j++)
            #pragma unroll
            for (int q = 0; q < 4; q++) acc[i][j][q] = 0.f;

    const int NCH = K >> 6;

    auto load_stage = [&](int s, int chunk) {
        uint32_t st = sb + s * STAGE_B;
        int k0 = chunk * 64;
        #pragma unroll
        for (int it = 0; it < 2; it++) {
            int idx = tid + it * 512;
            int row = idx >> 3, c = idx & 7;
            uint32_t d = st + row * 128 + (uint32_t)((c * 16) ^ ((row & 7) << 4));
            size_t go = (size_t)(bm + row) * K + k0 + c * 8;
            cp16(d + SM_A_HI, Ah + go);
            cp16(d + SM_A_LO, Al + go);
        }
        #pragma unroll
        for (int it = 0; it < 4; it++) {
            int idx = tid + it * 512;
            int row = idx >> 3, c = idx & 7;
            uint32_t d = st + row * 128 + (uint32_t)((c * 16) ^ ((row & 7) << 4));
            size_t go = (size_t)(bn + row) * K + k0 + c * 8;
            cp16(d + SM_B_HI, Bh + go);
            cp16(d + SM_B_LO, Bl + go);
        }
    };

    load_stage(0, 0);
    cp_commit();

    for (int chunk = 0; chunk < NCH; chunk++) {
        int s = chunk & 1;
        if (chunk + 1 < NCH) {
            load_stage(s ^ 1, chunk + 1);
            cp_commit();
            cp_wait1();
        } else {
            cp_wait0();
        }
        __syncthreads();

        uint32_t st = sb + s * STAGE_B;
        #pragma unroll
        for (int ks = 0; ks < 4; ks++) {
            uint32_t kb = (uint32_t)((ks * 32 + laneK) ^ xorA);
            uint32_t ah[4][4], bh[2][4];
            #pragma unroll
            for (int i = 0; i < 4; i++)
                ldsm_x4(ah[i], st + SM_A_HI + (uint32_t)(m0 + i*16 + laneRow) * 128 + kb);
            #pragma unroll
            for (int p = 0; p < 2; p++)
                ldsm_x4(bh[p], st + SM_B_HI + (uint32_t)(n0 + p*16 + laneRow) * 128 + kb);
            #pragma unroll
            for (int i = 0; i < 4; i++)
                #pragma unroll
                for (int j = 0; j < 4; j++)
                    mma16816(acc[i][j], ah[i], bh[j>>1][j&1], bh[j>>1][2 + (j&1)]);
            {
                uint32_t al[4][4];
                #pragma unroll
                for (int i = 0; i < 4; i++)
                    ldsm_x4(al[i], st + SM_A_LO + (uint32_t)(m0 + i*16 + laneRow) * 128 + kb);
                #pragma unroll
                for (int i = 0; i < 4; i++)
                    #pragma unroll
                    for (int j = 0; j < 4; j++)
                        mma16816(acc[i][j], al[i], bh[j>>1][j&1], bh[j>>1][2 + (j&1)]);
            }
            {
                uint32_t bl[2][4];
                #pragma unroll
                for (int p = 0; p < 2; p++)
                    ldsm_x4(bl[p], st + SM_B_LO + (uint32_t)(n0 + p*16 + laneRow) * 128 + kb);
                #pragma unroll
                for (int i = 0; i < 4; i++)
                    #pragma unroll
                    for (int j = 0; j < 4; j++)
                        mma16816(acc[i][j], ah[i], bl[j>>1][j&1], bl[j>>1][2 + (j&1)]);
            }
        }
        __syncthreads();
    }

    int group = lane >> 2, tq = lane & 3;
    #pragma unroll
    for (int j = 0; j < 4; j++) {
        int n = bn + n0 + j*8 + tq*2;
        float bv0 = bias[n], bv1 = bias[n+1];
        #pragma unroll
        for (int i = 0; i < 4; i++) {
            int m = bm + m0 + i*16 + group;
            size_t off0 = (size_t)m * N + n;
            size_t off1 = (size_t)(m + 8) * N + n;
            float2 r0 = *(const float2*)(R + off0);
            float2 r1 = *(const float2*)(R + off1);
            *(float2*)(C + off0) = make_float2(acc[i][j][0] + bv0 + r0.x, acc[i][j][1] + bv1 + r0.y);
            *(float2*)(C + off1) = make_float2(acc[i][j][2] + bv0 + r1.x, acc[i][j][3] + bv1 + r1.y);
        }
    }
}

// ====== fused Q/K/V/U projection: one launch, grid.z selects weight ========
__global__ void __launch_bounds__(512, 1)
proj4(const __nv_bfloat16* __restrict__ Ah, const __nv_bfloat16* __restrict__ Al,
      const __nv_bfloat16* __restrict__ WThG, const __nv_bfloat16* __restrict__ WTlG,
      const float* __restrict__ bq, const float* __restrict__ bk,
      const float* __restrict__ bv, const float* __restrict__ bu,
      __nv_bfloat16* __restrict__ Qh, __nv_bfloat16* __restrict__ Ql,
      __nv_bfloat16* __restrict__ Kh, __nv_bfloat16* __restrict__ Kl,
      __nv_bfloat16* __restrict__ VTh, __nv_bfloat16* __restrict__ VTl,
      float* __restrict__ Uf)
{
    extern __shared__ __align__(128) char sm[];
    uint32_t sb = smem_u32(sm);
    int tid  = threadIdx.x;
    int wid  = tid >> 5;
    int lane = tid & 31;
    int wm = wid & 1, wn = wid >> 1;
    int z  = blockIdx.z;
    int bm = blockIdx.y * 128, bn = blockIdx.x * 256;
    int m0 = wm * 64, n0 = wn * 32;
    const int K = 1024, N = 1024;

    const __nv_bfloat16* Bh = WThG + (size_t)z * W1M;
    const __nv_bfloat16* Bl = WTlG + (size_t)z * W1M;
    const float* bias = (z == 0) ? bq : (z == 1) ? bk : (z == 2) ? bv : bu;

    int laneRow = lane & 15;
    int laneK   = (lane >> 4) * 16;
    uint32_t xorA = (uint32_t)((laneRow & 7) << 4);

    float acc[4][4][4];
    #pragma unroll
    for (int i = 0; i < 4; i++)
        #pragma unroll
        for (int j = 0; j < 4; j++)
            #pragma unroll
            for (int q = 0; q < 4; q++) acc[i][j][q] = 0.f;

    const int NCH = K >> 6;

    auto load_stage = [&](int s, int chunk) {
        uint32_t st = sb + s * STAGE_B;
        int k0 = chunk * 64;
        #pragma unroll
        for (int it = 0; it < 2; it++) {
            int idx = tid + it * 512;
            int row = idx >> 3, c = idx & 7;
            uint32_t d = st + row * 128 + (uint32_t)((c * 16) ^ ((row & 7) << 4));
            size_t go = (size_t)(bm + row) * K + k0 + c * 8;
            cp16(d + SM_A_HI, Ah + go);
            cp16(d + SM_A_LO, Al + go);
        }
        #pragma unroll
        for (int it = 0; it < 4; it++) {
            int idx = tid + it * 512;
            int row = idx >> 3, c = idx & 7;
            uint32_t d = st + row * 128 + (uint32_t)((c * 16) ^ ((row & 7) << 4));
            size_t go = (size_t)(bn + row) * K + k0 + c * 8;
            cp16(d + SM_B_HI, Bh + go);
            cp16(d + SM_B_LO, Bl + go);
        }
    };

    load_stage(0, 0);
    cp_commit();

    for (int chunk = 0; chunk < NCH; chunk++) {
        int s = chunk & 1;
        if (chunk + 1 < NCH) {
            load_stage(s ^ 1, chunk + 1);
            cp_commit();
            cp_wait1();
        } else {
            cp_wait0();
        }
        __syncthreads();

        uint32_t st = sb + s * STAGE_B;
        #pragma unroll
        for (int ks = 0; ks < 4; ks++) {
            uint32_t kb = (uint32_t)((ks * 32 + laneK) ^ xorA);
            uint32_t ah[4][4], bh[2][4];
            #pragma unroll
            for (int i = 0; i < 4; i++)
                ldsm_x4(ah[i], st + SM_A_HI + (uint32_t)(m0 + i*16 + laneRow) * 128 + kb);
            #pragma unroll
            for (int p = 0; p < 2; p++)
                ldsm_x4(bh[p], st + SM_B_HI + (uint32_t)(n0 + p*16 + laneRow) * 128 + kb);
            #pragma unroll
            for (int i = 0; i < 4; i++)
                #pragma unroll
                for (int j = 0; j < 4; j++)
                    mma16816(acc[i][j], ah[i], bh[j>>1][j&1], bh[j>>1][2 + (j&1)]);
            {
                uint32_t al[4][4];
                #pragma unroll
                for (int i = 0; i < 4; i++)
                    ldsm_x4(al[i], st + SM_A_LO + (uint32_t)(m0 + i*16 + laneRow) * 128 + kb);
                #pragma unroll
                for (int i = 0; i < 4; i++)
                    #pragma unroll
                    for (int j = 0; j < 4; j++)
                        mma16816(acc[i][j], al[i], bh[j>>1][j&1], bh[j>>1][2 + (j&1)]);
            }
            {
                uint32_t bl[2][4];
                #pragma unroll
                for (int p = 0; p < 2; p++)
                    ldsm_x4(bl[p], st + SM_B_LO + (uint32_t)(n0 + p*16 + laneRow) * 128 + kb);
                #pragma unroll
                for (int i = 0; i < 4; i++)
                    #pragma unroll
                    for (int j = 0; j < 4; j++)
                        mma16816(acc[i][j], ah[i], bl[j>>1][j&1], bl[j>>1][2 + (j&1)]);
            }
        }
        __syncthreads();
    }

    int group = lane >> 2, tq = lane & 3;
    __nv_bfloat16* Yh = (z == 0) ? Qh : Kh;
    __nv_bfloat16* Yl = (z == 0) ? Ql : Kl;
    #pragma unroll
    for (int j = 0; j < 4; j++) {
        int n = bn + n0 + j*8 + tq*2;
        float bv0 = bias[n], bv1 = bias[n+1];
        #pragma unroll
        for (int i = 0; i < 4; i++) {
            int m = bm + m0 + i*16 + group;
            float v0 = acc[i][j][0] + bv0, v1 = acc[i][j][1] + bv1;
            float v2 = acc[i][j][2] + bv0, v3 = acc[i][j][3] + bv1;
            if (z <= 1) {
                __nv_bfloat16 h0,l0,h1,l1,h2,l2,h3,l3;
                split_bf16(v0,h0,l0); split_bf16(v1,h1,l1);
                split_bf16(v2,h2,l2); split_bf16(v3,h3,l3);
                size_t off0 = (size_t)m * N + n;
                size_t off1 = (size_t)(m + 8) * N + n;
                *(__nv_bfloat162*)(Yh + off0) = __nv_bfloat162(h0, h1);
                *(__nv_bfloat162*)(Yl + off0) = __nv_bfloat162(l0, l1);
                *(__nv_bfloat162*)(Yh + off1) = __nv_bfloat162(h2, h3);
                *(__nv_bfloat162*)(Yl + off1) = __nv_bfloat162(l2, l3);
            } else if (z == 2) {
                __nv_bfloat16 h0,l0,h1,l1,h2,l2,h3,l3;
                split_bf16(v0,h0,l0); split_bf16(v1,h1,l1);
                split_bf16(v2,h2,l2); split_bf16(v3,h3,l3);
                int bi = m >> 11, tt = m & 2047;
                int hh = n >> 6,  dd = n & 63;
                size_t vb = ((size_t)((bi*16 + hh)*64 + dd)) * 2048 + tt;
                VTh[vb]        = h0;  VTl[vb]        = l0;
                VTh[vb + 2048] = h1;  VTl[vb + 2048] = l1;
                VTh[vb + 8]    = h2;  VTl[vb + 8]    = l2;
                VTh[vb + 2056] = h3;  VTl[vb + 2056] = l3;
            } else {
                size_t off0 = (size_t)m * N + n;
                size_t off1 = (size_t)(m + 8) * N + n;
                *(float2*)(Uf + off0) = make_float2(siluf(v0), siluf(v1));
                *(float2*)(Uf + off1) = make_float2(siluf(v2), siluf(v3));
            }
        }
    }
}

// ====== w1 GEMM + swiglu fusion ============================================
#define W_A_HI  0
#define W_A_LO  16384
#define W_B1_HI 32768
#define W_B1_LO 49152
#define W_B2_HI 65536
#define W_B2_LO 81920
#define STAGE_W 98304

__global__ void __launch_bounds__(512, 1)
gemm_w1sg(const __nv_bfloat16* __restrict__ Ah, const __nv_bfloat16* __restrict__ Al,
          const __nv_bfloat16* __restrict__ Bh, const __nv_bfloat16* __restrict__ Bl,
          const float* __restrict__ b1,
          __nv_bfloat16* __restrict__ Yh, __nv_bfloat16* __restrict__ Yl)
{
    extern __shared__ __align__(128) char sm[];
    uint32_t sb = smem_u32(sm);
    int tid  = threadIdx.x;
    int wid  = tid >> 5;
    int lane = tid & 31;
    int wm = wid & 1, wn = wid >> 1;
    int bm = blockIdx.y * 128, bn = blockIdx.x * 128;
    int m0 = wm * 64, n0 = wn * 16;
    const int K = 1024;

    int laneRow = lane & 15;
    int laneK   = (lane >> 4) * 16;
    uint32_t xorA = (uint32_t)((laneRow & 7) << 4);

    float acc1[4][2][4], acc2[4][2][4];
    #pragma unroll
    for (int i = 0; i < 4; i++)
        #pragma unroll
        for (int j = 0; j < 2; j++)
            #pragma unroll
            for (int q = 0; q < 4; q++) { acc1[i][j][q] = 0.f; acc2[i][j][q] = 0.f; }

    const int NCH = K >> 6;

    auto load_stage = [&](int s, int chunk) {
        uint32_t st = sb + s * STAGE_W;
        int k0 = chunk * 64;
        #pragma unroll
        for (int it = 0; it < 2; it++) {
            int idx = tid + it * 512;
            int row = idx >> 3, c = idx & 7;
            uint32_t d = st + row * 128 + (uint32_t)((c * 16) ^ ((row & 7) << 4));
            size_t goA  = (size_t)(bm + row) * K + k0 + c * 8;
            size_t goB1 = (size_t)(bn + row) * K + k0 + c * 8;
            size_t goB2 = (size_t)(1024 + bn + row) * K + k0 + c * 8;
            cp16(d + W_A_HI,  Ah + goA);
            cp16(d + W_A_LO,  Al + goA);
            cp16(d + W_B1_HI, Bh + goB1);
            cp16(d + W_B1_LO, Bl + goB1);
            cp16(d + W_B2_HI, Bh + goB2);
            cp16(d + W_B2_LO, Bl + goB2);
        }
    };

    load_stage(0, 0);
    cp_commit();

    for (int chunk = 0; chunk < NCH; chunk++) {
        int s = chunk & 1;
        if (chunk + 1 < NCH) {
            load_stage(s ^ 1, chunk + 1);
            cp_commit();
            cp_wait1();
        } else {
            cp_wait0();
        }
        __syncthreads();

        uint32_t st = sb + s * STAGE_W;
        #pragma unroll
        for (int ks = 0; ks < 4; ks++) {
            uint32_t kb = (uint32_t)((ks * 32 + laneK) ^ xorA);
            uint32_t ah[4][4], b1h[4], b2h[4];
            #pragma unroll
            for (int i = 0; i < 4; i++)
                ldsm_x4(ah[i], st + W_A_HI + (uint32_t)(m0 + i*16 + laneRow) * 128 + kb);
            ldsm_x4(b1h, st + W_B1_HI + (uint32_t)(n0 + laneRow) * 128 + kb);
            ldsm_x4(b2h, st + W_B2_HI + (uint32_t)(n0 + laneRow) * 128 + kb);
            #pragma unroll
            for (int i = 0; i < 4; i++)
                #pragma unroll
                for (int j = 0; j < 2; j++) {
                    mma16816(acc1[i][j], ah[i], b1h[j], b1h[2 + j]);
                    mma16816(acc2[i][j], ah[i], b2h[j], b2h[2 + j]);
                }
            {
                uint32_t al[4][4];
                #pragma unroll
                for (int i = 0; i < 4; i++)
                    ldsm_x4(al[i], st + W_A_LO + (uint32_t)(m0 + i*16 + laneRow) * 128 + kb);
                #pragma unroll
                for (int i = 0; i < 4; i++)
                    #pragma unroll
                    for (int j = 0; j < 2; j++) {
                        mma16816(acc1[i][j], al[i], b1h[j], b1h[2 + j]);
                        mma16816(acc2[i][j], al[i], b2h[j], b2h[2 + j]);
                    }
            }
            {
                uint32_t b1l[4], b2l[4];
                ldsm_x4(b1l, st + W_B1_LO + (uint32_t)(n0 + laneRow) * 128 + kb);
                ldsm_x4(b2l, st + W_B2_LO + (uint32_t)(n0 + laneRow) * 128 + kb);
                #pragma unroll
                for (int i = 0; i < 4; i++)
                    #pragma unroll
                    for (int j = 0; j < 2; j++) {
                        mma16816(acc1[i][j], ah[i], b1l[j], b1l[2 + j]);
                        mma16816(acc2[i][j], ah[i], b2l[j], b2l[2 + j]);
                    }
            }
        }
        __syncthreads();
    }

    int group = lane >> 2, tq = lane & 3;
    #pragma unroll
    for (int j = 0; j < 2; j++) {
        int n = bn + n0 + j*8 + tq*2;
        float c10 = b1[n], c11 = b1[n+1];
        float c20 = b1[1024 + n], c21 = b1[1025 + n];
        #pragma unroll
        for (int i = 0; i < 4; i++) {
            int m = bm + m0 + i*16 + group;
            float y0 = siluf(acc1[i][j][0] + c10) * (acc2[i][j][0] + c20);
            float y1 = siluf(acc1[i][j][1] + c11) * (acc2[i][j][1] + c21);
            float y2 = siluf(acc1[i][j][2] + c10) * (acc2[i][j][2] + c20);
            float y3 = siluf(acc1[i][j][3] + c11) * (acc2[i][j][3] + c21);
            __nv_bfloat16 h0,l0,h1,l1,h2,l2,h3,l3;
            split_bf16(y0,h0,l0); split_bf16(y1,h1,l1);
            split_bf16(y2,h2,l2); split_bf16(y3,h3,l3);
            size_t off0 = (size_t)m * 1024 + n;
            size_t off1 = (size_t)(m + 8) * 1024 + n;
            *(__nv_bfloat162*)(Yh + off0) = __nv_bfloat162(h0, h1);
            *(__nv_bfloat162*)(Yl + off0) = __nv_bfloat162(l0, l1);
            *(__nv_bfloat162*)(Yh + off1) = __nv_bfloat162(h2, h3);
            *(__nv_bfloat162*)(Yl + off1) = __nv_bfloat162(l2, l3);
        }
    }
}

// ===== attention: 16 warps, key-split, Q hi+lo hoisted, S/SV interleaved ====
// Warp w: m-rows (w&7)*16, key half (w>>3). Per kt: two chunks of 2 key
// sub-tiles each: S (chunk) -> repack -> SV (chunk). Bit-exact vs R10.
#define A_SQH 0u
#define A_SQL 16384u
#define A_SK  32768u       // + s*32768 : KH, KL(+16384)
#define A_SVT 98304u       // + s*32768 : VTH, VTL(+16384)
#define A_PB  163840u      // + s*512
#define A_RED A_SK         // reduction area reuses K stage 0 (32KB)
#define ATT_SMEM 164864

__global__ void __launch_bounds__(512, 1)
attn_tc(const __nv_bfloat16* __restrict__ Qh, const __nv_bfloat16* __restrict__ Ql,
        const __nv_bfloat16* __restrict__ Kh, const __nv_bfloat16* __restrict__ Kl,
        const __nv_bfloat16* __restrict__ VTh, const __nv_bfloat16* __restrict__ VTl,
        const float* __restrict__ PB, float* __restrict__ O)
{
    extern __shared__ __align__(128) char sm[];
    uint32_t sb = smem_u32(sm);
    int tid  = threadIdx.x;
    int wid  = tid >> 5;
    int lane = tid & 31;
    int qt = blockIdx.x, h = blockIdx.y, b = blockIdx.z;
    int mw = wid & 7;
    int kw = wid >> 3;
    int m0 = mw * 16;
    int ntb = kw * 4;

    int laneRow = lane & 15;
    int laneK   = (lane >> 4) * 16;
    uint32_t xorA = (uint32_t)((laneRow & 7) << 4);
    int group = lane >> 2, tq = lane & 3;
    uint32_t rowbK = (uint32_t)laneRow * 128;
    uint32_t rowbV = (uint32_t)laneRow * 256;

    auto load_q = [&]() {
        #pragma unroll
        for (int it = 0; it < 2; it++) {
            int idx = tid + it * 512;
            int row = idx >> 3, c = idx & 7;
            uint32_t d = row * 128 + (uint32_t)((c * 16) ^ ((row & 7) << 4));
            size_t go = ((size_t)(b*SEQ + qt*128 + row)) * D_MODEL + h*64 + c*8;
            cp16(sb + A_SQH + d, Qh + go);
            cp16(sb + A_SQL + d, Ql + go);
        }
    };
    auto load_kv = [&](int s, int kt) {
        uint32_t kbase = sb + A_SK + (uint32_t)s * 32768u;
        #pragma unroll
        for (int it = 0; it < 2; it++) {
            int idx = tid + it * 512;
            int row = idx >> 3, c = idx & 7;
            uint32_t d = row * 128 + (uint32_t)((c * 16) ^ ((row & 7) << 4));
            size_t go = ((size_t)(b*SEQ + kt*128 + row)) * D_MODEL + h*64 + c*8;
            cp16(kbase + d, Kh + go);
            cp16(kbase + 16384u + d, Kl + go);
        }
        uint32_t vbase = sb + A_SVT + (uint32_t)s * 32768u;
        #pragma unroll
        for (int it = 0; it < 2; it++) {
            int idx = tid + it * 512;
            int row = idx >> 4, c = idx & 15;
            uint32_t d = row * 256 + (uint32_t)((c * 16) ^ ((row & 7) << 4));
            size_t go = ((size_t)((b*16 + h)*64 + row)) * 2048 + kt*128 + c*8;
            cp16(vbase + d, VTh + go);
            cp16(vbase + 16384u + d, VTl + go);
        }
        if (tid < 128) {
            float v = PB[(size_t)(kt*128 + tid) * N_HEADS + h];
            *(float*)(sm + A_PB + (uint32_t)s * 512u + tid * 4) = v;
        }
    };

    float accO[8][4];
    #pragma unroll
    for (int f = 0; f < 8; f++)
        #pragma unroll
        for (int q = 0; q < 4; q++) accO[f][q] = 0.f;

    load_q(); cp_commit();
    load_kv(0, 0); cp_commit();
    cp_wait1();
    __syncthreads();

    // hoist Q hi + lo fragments (loop-invariant)
    uint32_t qfh[4][4], qfl[4][4];
    #pragma unroll
    for (int ks = 0; ks < 4; ks++) {
        uint32_t kb = (uint32_t)((ks * 32 + laneK) ^ xorA);
        ldsm_x4(qfh[ks], sb + A_SQH + (uint32_t)m0 * 128 + rowbK + kb);
        ldsm_x4(qfl[ks], sb + A_SQL + (uint32_t)m0 * 128 + rowbK + kb);
    }

    for (int kt = 0; kt < SEQ/128; kt++) {
        int s = kt & 1;
        if (kt + 1 < SEQ/128) {
            load_kv(s ^ 1, kt + 1);
            cp_commit();
            cp_wait1();
        } else {
            cp_wait0();
        }
        __syncthreads();

        uint32_t kst = sb + A_SK + (uint32_t)s * 32768u + (uint32_t)ntb * 2048u;
        uint32_t vst = sb + A_SVT + (uint32_t)s * 32768u;
        const float* pbs = (const float*)(sm + A_PB + (uint32_t)s * 512u);

        #pragma unroll
        for (int c = 0; c < 2; c++) {
            // ---- S for key sub-tiles {2c, 2c+1} ----
            float sc[4][4];
            #pragma unroll
            for (int f = 0; f < 4; f++)
                #pragma unroll
                for (int q = 0; q < 4; q++) sc[f][q] = 0.f;

            #pragma unroll
            for (int ks = 0; ks < 4; ks++) {
                uint32_t kb = (uint32_t)((ks * 32 + laneK) ^ xorA);
                #pragma unroll
                for (int t = 0; t < 2; t++) {
                    int nt = 2*c + t;
                    uint32_t kf[4];
                    ldsm_x4(kf, kst + (uint32_t)nt * 2048u + rowbK + kb);
                    mma16816(sc[2*t],   qfh[ks], kf[0], kf[2]);
                    mma16816(sc[2*t+1], qfh[ks], kf[1], kf[3]);
                    mma16816(sc[2*t],   qfl[ks], kf[0], kf[2]);
                    mma16816(sc[2*t+1], qfl[ks], kf[1], kf[3]);
                    uint32_t kl[4];
                    ldsm_x4(kl, kst + 16384u + (uint32_t)nt * 2048u + rowbK + kb);
                    mma16816(sc[2*t],   qfh[ks], kl[0], kl[2]);
                    mma16816(sc[2*t+1], qfh[ks], kl[1], kl[3]);
                }
            }

            // ---- silu + split + repack ----
            uint32_t sfh[2][4], sfl[2][4];
            #pragma unroll
            for (int t = 0; t < 2; t++) {
                int nt = 2*c + t;
                #pragma unroll
                for (int half = 0; half < 2; half++) {
                    int f = 2*t + half;
                    int tcol = ntb*16 + nt*16 + half*8 + tq*2;
                    float pb0 = pbs[tcol], pb1 = pbs[tcol + 1];
                    float w0 = siluf(sc[f][0] * 0.125f + pb0);
                    float w1 = siluf(sc[f][1] * 0.125f + pb1);
                    float w2 = siluf(sc[f][2] * 0.125f + pb0);
                    float w3 = siluf(sc[f][3] * 0.125f + pb1);
                    __nv_bfloat16 h0,l0,h1,l1,h2,l2,h3,l3;
                    split_bf16(w0,h0,l0); split_bf16(w1,h1,l1);
                    split_bf16(w2,h2,l2); split_bf16(w3,h3,l3);
                    sfh[t][half*2]     = pack_bf16(h0, h1);
                    sfh[t][half*2 + 1] = pack_bf16(h2, h3);
                    sfl[t][half*2]     = pack_bf16(l0, l1);
                    sfl[t][half*2 + 1] = pack_bf16(l2, l3);
                }
            }

            // ---- SV for key groups {2c, 2c+1} ----
            #pragma unroll
            for (int t = 0; t < 2; t++) {
                int gks = ntb + 2*c + t;
                uint32_t kb = (uint32_t)((gks * 32 + laneK) ^ xorA);
                #pragma unroll
                for (int dn = 0; dn < 4; dn++) {
                    uint32_t vf[4];
                    ldsm_x4(vf, vst + (uint32_t)dn * 4096u + rowbV + kb);
                    mma16816(accO[2*dn],   sfh[t], vf[0], vf[2]);
                    mma16816(accO[2*dn+1], sfh[t], vf[1], vf[3]);
                    mma16816(accO[2*dn],   sfl[t], vf[0], vf[2]);
                    mma16816(accO[2*dn+1], sfl[t], vf[1], vf[3]);
                    uint32_t vl[4];
                    ldsm_x4(vl, vst + 16384u + (uint32_t)dn * 4096u + rowbV + kb);
                    mma16816(accO[2*dn],   sfh[t], vl[0], vl[2]);
                    mma16816(accO[2*dn+1], sfh[t], vl[1], vl[3]);
                }
            }
        }
        __syncthreads();
    }

    // ---- merge key-half partials ----
    if (kw == 1) {
        float* red = (float*)(sm + A_RED) + ((size_t)mw * 32 + lane) * 32;
        #pragma unroll
        for (int f = 0; f < 8; f++) {
            red[f*4+0] = accO[f][0]; red[f*4+1] = accO[f][1];
            red[f*4+2] = accO[f][2]; red[f*4+3] = accO[f][3];
        }
    }
    __syncthreads();
    if (kw == 0) {
        const float* red = (const float*)(sm + A_RED) + ((size_t)mw * 32 + lane) * 32;
        #pragma unroll
        for (int dn = 0; dn < 4; dn++) {
            #pragma unroll
            for (int half = 0; half < 2; half++) {
                int f = 2*dn + half;
                float o0 = accO[f][0] + red[f*4+0];
                float o1 = accO[f][1] + red[f*4+1];
                float o2 = accO[f][2] + red[f*4+2];
                float o3 = accO[f][3] + red[f*4+3];
                int col = h*64 + dn*16 + half*8 + tq*2;
                int row = b*SEQ + qt*128 + m0 + group;
                *(float2*)(O + (size_t)row * D_MODEL + col) = make_float2(o0, o1);
                *(float2*)(O + (size_t)(row + 8) * D_MODEL + col) = make_float2(o2, o3);
            }
        }
    }
}

// ---------------- launch ----------------------------------------------------
extern "C" void kernel_launch(void* const* d_in, const int* in_sizes, int n_in,
                              void* d_out, int out_size)
{
    const float* x      = (const float*)d_in[0];
    const float* pb     = (const float*)d_in[2];
    const float* wq     = (const float*)d_in[3];
    const float* bq     = (const float*)d_in[4];
    const float* wk     = (const float*)d_in[5];
    const float* bk_    = (const float*)d_in[6];
    const float* wv     = (const float*)d_in[7];
    const float* bv     = (const float*)d_in[8];
    const float* wu     = (const float*)d_in[9];
    const float* bu     = (const float*)d_in[10];
    const float* g_ams  = (const float*)d_in[11];
    const float* w0     = (const float*)d_in[12];
    const float* b0     = (const float*)d_in[13];
    const float* w1     = (const float*)d_in[14];
    const float* b1     = (const float*)d_in[15];
    const float* w2     = (const float*)d_in[16];
    const float* b2     = (const float*)d_in[17];
    const float* g_mffn = (const float*)d_in[18];
    float* out = (float*)d_out;

    float *Qf, *Kf, *Vf, *Uf, *AOf, *Of;
    __nv_bfloat16 *A1h, *A1l, *A2h, *A2l, *WTh, *WTl;
    cudaGetSymbolAddress((void**)&Qf,  g_Q);
    cudaGetSymbolAddress((void**)&Kf,  g_K);
    cudaGetSymbolAddress((void**)&Vf,  g_V);
    cudaGetSymbolAddress((void**)&Uf,  g_U);
    cudaGetSymbolAddress((void**)&AOf, g_AO);
    cudaGetSymbolAddress((void**)&Of,  g_O);
    cudaGetSymbolAddress((void**)&A1h, g_A1h);
    cudaGetSymbolAddress((void**)&A1l, g_A1l);
    cudaGetSymbolAddress((void**)&A2h, g_A2h);
    cudaGetSymbolAddress((void**)&A2l, g_A2l);
    cudaGetSymbolAddress((void**)&WTh, g_WTh);
    cudaGetSymbolAddress((void**)&WTl, g_WTl);

    const size_t NEL = (size_t)M_ROWS * D_MODEL;
    __nv_bfloat16 *Qhb = (__nv_bfloat16*)Qf,  *Qlb = Qhb + NEL;
    __nv_bfloat16 *Khb = (__nv_bfloat16*)Kf,  *Klb = Khb + NEL;
    __nv_bfloat16 *VTh = (__nv_bfloat16*)Vf,  *VTl = VTh + NEL;

    __nv_bfloat16 *T0_h = WTh + (size_t)4*W1M, *T0_l = WTl + (size_t)4*W1M;
    __nv_bfloat16 *T2_h = WTh + (size_t)5*W1M, *T2_l = WTl + (size_t)5*W1M;
    __nv_bfloat16 *T1_h = WTh + (size_t)6*W1M, *T1_l = WTl + (size_t)6*W1M;

    const int GSM = 2 * STAGE_B;
    cudaFuncSetAttribute(gemm_res,  cudaFuncAttributeMaxDynamicSharedMemorySize, GSM);
    cudaFuncSetAttribute(proj4,     cudaFuncAttributeMaxDynamicSharedMemorySize, GSM);
    cudaFuncSetAttribute(gemm_w1sg, cudaFuncAttributeMaxDynamicSharedMemorySize, 2*STAGE_W);
    cudaFuncSetAttribute(attn_tc,   cudaFuncAttributeMaxDynamicSharedMemorySize, ATT_SMEM);

    wtsplit_all<<<8192, dim3(32, 8)>>>(wq, wk, wv, wu, w0, w2, w1, WTh, WTl);
    rmsnorm_tc<<<M_ROWS, 256>>>(x, g_ams, A1h, A1l);
    proj4<<<dim3(4, 32, 4), 512, GSM>>>(A1h, A1l, WTh, WTl, bq, bk_, bv, bu,
                                        Qhb, Qlb, Khb, Klb, VTh, VTl, Uf);
    attn_tc<<<dim3(SEQ/128, N_HEADS, BATCH), 512, ATT_SMEM>>>(Qhb, Qlb, Khb, Klb, VTh, VTl, pb, AOf);
    ams_tc<<<M_ROWS, 256>>>(AOf, g_ams, Uf, A2h, A2l);
    gemm_res<<<dim3(4, 32), 512, GSM>>>(A2h, A2l, T0_h, T0_l, b0, x, Of, M_ROWS, 1024, 1024);
    rmsnorm_tc<<<M_ROWS, 256>>>(Of, g_mffn, A1h, A1l);
    gemm_w1sg<<<dim3(8, 32), 512, 2*STAGE_W>>>(A1h, A1l, T1_h, T1_l, b1, A2h, A2l);
    gemm_res<<<dim3(4, 32), 512, GSM>>>(A2h, A2l, T2_h, T2_l, b2, Of, out, M_ROWS, 1024, 1024);
}

// round 12
// speedup vs baseline: 1.1670x; 1.0334x over previous
#include <cuda_runtime.h>
#include <cuda_bf16.h>
#include <cstdint>
#include <math.h>

#define D_MODEL 1024
#define N_HEADS 16
#define DH      64
#define BATCH   2
#define SEQ     2048
#define M_ROWS  (BATCH*SEQ)   // 4096

// ---------------- scratch (static device globals; no allocations) ----------
__device__ float g_Q  [M_ROWS*D_MODEL];   // aliased: Qh/Ql bf16
__device__ float g_K  [M_ROWS*D_MODEL];   // aliased: Kh/Kl bf16
__device__ float g_V  [M_ROWS*D_MODEL];   // aliased: VTh/VTl bf16 (transposed per head)
__device__ float g_U  [M_ROWS*D_MODEL];
__device__ float g_AO [M_ROWS*D_MODEL];   // attention partial 0
__device__ float g_P2 [M_ROWS*D_MODEL];   // attention partial 1
__device__ float g_O  [M_ROWS*D_MODEL];

__device__ __nv_bfloat16 g_A1h[M_ROWS*D_MODEL];
__device__ __nv_bfloat16 g_A1l[M_ROWS*D_MODEL];
__device__ __nv_bfloat16 g_A2h[M_ROWS*D_MODEL];
__device__ __nv_bfloat16 g_A2l[M_ROWS*D_MODEL];

__device__ __nv_bfloat16 g_WTh[8*1024*1024];
__device__ __nv_bfloat16 g_WTl[8*1024*1024];

#define W1M (1024*1024)

__device__ __forceinline__ float siluf(float z) {
    return z * (1.0f / (1.0f + __expf(-z)));
}

__device__ __forceinline__ uint32_t smem_u32(const void* p) {
    uint32_t a;
    asm("{ .reg .u64 t; cvta.to.shared.u64 t, %1; cvt.u32.u64 %0, t; }" : "=r"(a) : "l"(p));
    return a;
}

__device__ __forceinline__ void ldsm_x4(uint32_t* r, uint32_t a) {
    asm volatile("ldmatrix.sync.aligned.m8n8.x4.shared.b16 {%0,%1,%2,%3}, [%4];"
                 : "=r"(r[0]), "=r"(r[1]), "=r"(r[2]), "=r"(r[3]) : "r"(a));
}

__device__ __forceinline__ void mma16816(float* c, const uint32_t* a, uint32_t b0, uint32_t b1) {
    asm volatile("mma.sync.aligned.m16n8k16.row.col.f32.bf16.bf16.f32 "
                 "{%0,%1,%2,%3}, {%4,%5,%6,%7}, {%8,%9}, {%0,%1,%2,%3};"
                 : "+f"(c[0]), "+f"(c[1]), "+f"(c[2]), "+f"(c[3])
                 : "r"(a[0]), "r"(a[1]), "r"(a[2]), "r"(a[3]), "r"(b0), "r"(b1));
}

__device__ __forceinline__ void cp16(uint32_t dst, const void* src) {
    asm volatile("cp.async.cg.shared.global [%0], [%1], 16;" :: "r"(dst), "l"(src));
}
__device__ __forceinline__ void cp_commit() { asm volatile("cp.async.commit_group;"); }
__device__ __forceinline__ void cp_wait1()  { asm volatile("cp.async.wait_group 1;"); }
__device__ __forceinline__ void cp_wait0()  { asm volatile("cp.async.wait_group 0;"); }

__device__ __forceinline__ void split_bf16(float v, __nv_bfloat16& h, __nv_bfloat16& l) {
    h = __float2bfloat16(v);
    l = __float2bfloat16(v - __bfloat162float(h));
}

__device__ __forceinline__ uint32_t pack_bf16(__nv_bfloat16 a, __nv_bfloat16 b) {
    __nv_bfloat162 t(a, b);
    return *(uint32_t*)&t;
}

// ======= batched weight transpose + bf16 split (all 7 weights, 1 launch) ====
__global__ void __launch_bounds__(256)
wtsplit_all(const float* __restrict__ wq, const float* __restrict__ wk,
            const float* __restrict__ wv, const float* __restrict__ wu,
            const float* __restrict__ w0, const float* __restrict__ w2,
            const float* __restrict__ w1,
            __nv_bfloat16* __restrict__ WTh, __nv_bfloat16* __restrict__ WTl)
{
    __shared__ float t[32][33];
    int bid = blockIdx.x;
    const float* W; __nv_bfloat16 *Th, *Tl;
    int N, nx, ky;
    if (bid < 6144) {
        int w = bid >> 10, local = bid & 1023;
        switch (w) {
            case 0: W = wq; break; case 1: W = wk; break;
            case 2: W = wv; break; case 3: W = wu; break;
            case 4: W = w0; break; default: W = w2; break;
        }
        Th = WTh + (size_t)w * W1M; Tl = WTl + (size_t)w * W1M;
        N = 1024; nx = local & 31; ky = local >> 5;
    } else {
        int local = bid - 6144;
        W = w1; Th = WTh + (size_t)6 * W1M; Tl = WTl + (size_t)6 * W1M;
        N = 2048; nx = local & 63; ky = local >> 6;
    }
    const int K = 1024;
    int tx = threadIdx.x, ty = threadIdx.y;
    int n0 = nx * 32, k0 = ky * 32;
    #pragma unroll
    for (int i = 0; i < 4; i++)
        t[ty + i*8][tx] = W[(size_t)(k0 + ty + i*8) * N + n0 + tx];
    __syncthreads();
    #pragma unroll
    for (int i = 0; i < 4; i++) {
        float v = t[tx][ty + i*8];
        __nv_bfloat16 hi, lo;
        split_bf16(v, hi, lo);
        size_t off = (size_t)(n0 + ty + i*8) * K + k0 + tx;
        Th[off] = hi; Tl[off] = lo;
    }
}

// ---------------- RMSNorm -> bf16 hi/lo -------------------------------------
__global__ void __launch_bounds__(256)
rmsnorm_tc(const float* __restrict__ X, const float* __restrict__ g,
           __nv_bfloat16* __restrict__ Yh, __nv_bfloat16* __restrict__ Yl)
{
    int r = blockIdx.x, t = threadIdx.x;
    float4 v = ((const float4*)(X + (size_t)r * D_MODEL))[t];
    float ss = v.x*v.x + v.y*v.y + v.z*v.z + v.w*v.w;
    #pragma unroll
    for (int o = 16; o; o >>= 1) ss += __shfl_xor_sync(0xffffffffu, ss, o);
    __shared__ float ws[8]; __shared__ float s_inv;
    if ((t & 31) == 0) ws[t >> 5] = ss;
    __syncthreads();
    if (t == 0) {
        float tot = 0.f;
        #pragma unroll
        for (int i = 0; i < 8; i++) tot += ws[i];
        s_inv = rsqrtf(tot * (1.0f / D_MODEL) + 1e-8f);
    }
    __syncthreads();
    float iv = s_inv;
    float4 gv = ((const float4*)g)[t];
    float o[4] = {v.x*iv*gv.x, v.y*iv*gv.y, v.z*iv*gv.z, v.w*iv*gv.w};
    __nv_bfloat16 h[4], l[4];
    #pragma unroll
    for (int i = 0; i < 4; i++) split_bf16(o[i], h[i], l[i]);
    size_t base = (size_t)r * D_MODEL + t*4;
    *(__nv_bfloat162*)(Yh + base)     = __nv_bfloat162(h[0], h[1]);
    *(__nv_bfloat162*)(Yh + base + 2) = __nv_bfloat162(h[2], h[3]);
    *(__nv_bfloat162*)(Yl + base)     = __nv_bfloat162(l[0], l[1]);
    *(__nv_bfloat162*)(Yl + base + 2) = __nv_bfloat162(l[2], l[3]);
}

// -------- merge attention partials + ams: rmsnorm(P0+P1, g) * U -> bf16 -----
__global__ void __launch_bounds__(256)
merge_ams(const float* __restrict__ P0, const float* __restrict__ P1,
          const float* __restrict__ g, const float* __restrict__ U,
          __nv_bfloat16* __restrict__ Yh, __nv_bfloat16* __restrict__ Yl)
{
    int r = blockIdx.x, t = threadIdx.x;
    float4 a = ((const float4*)(P0 + (size_t)r * D_MODEL))[t];
    float4 bb = ((const float4*)(P1 + (size_t)r * D_MODEL))[t];
    float4 v;
    v.x = a.x + bb.x; v.y = a.y + bb.y; v.z = a.z + bb.z; v.w = a.w + bb.w;
    float ss = v.x*v.x + v.y*v.y + v.z*v.z + v.w*v.w;
    #pragma unroll
    for (int o = 16; o; o >>= 1) ss += __shfl_xor_sync(0xffffffffu, ss, o);
    __shared__ float ws[8]; __shared__ float s_inv;
    if ((t & 31) == 0) ws[t >> 5] = ss;
    __syncthreads();
    if (t == 0) {
        float tot = 0.f;
        #pragma unroll
        for (int i = 0; i < 8; i++) tot += ws[i];
        s_inv = rsqrtf(tot * (1.0f / D_MODEL) + 1e-8f);
    }
    __syncthreads();
    float iv = s_inv;
    float4 gv = ((const float4*)g)[t];
    float4 uv = ((const float4*)(U + (size_t)r * D_MODEL))[t];
    float o[4] = {v.x*iv*gv.x*uv.x, v.y*iv*gv.y*uv.y, v.z*iv*gv.z*uv.z, v.w*iv*gv.w*uv.w};
    __nv_bfloat16 h[4], l[4];
    #pragma unroll
    for (int i = 0; i < 4; i++) split_bf16(o[i], h[i], l[i]);
    size_t base = (size_t)r * D_MODEL + t*4;
    *(__nv_bfloat162*)(Yh + base)     = __nv_bfloat162(h[0], h[1]);
    *(__nv_bfloat162*)(Yh + base + 2) = __nv_bfloat162(h[2], h[3]);
    *(__nv_bfloat162*)(Yl + base)     = __nv_bfloat162(l[0], l[1]);
    *(__nv_bfloat162*)(Yl + base + 2) = __nv_bfloat162(l[2], l[3]);
}

// ============== HMMA GEMM (EPI 2 only): C = A@B^T + bias + R ================
#define SM_A_HI 0
#define SM_A_LO 16384
#define SM_B_HI 32768
#define SM_B_LO 65536
#define STAGE_B 98304

__global__ void __launch_bounds__(512, 1)
gemm_res(const __nv_bfloat16* __restrict__ Ah, const __nv_bfloat16* __restrict__ Al,
         const __nv_bfloat16* __restrict__ Bh, const __nv_bfloat16* __restrict__ Bl,
         const float* __restrict__ bias, const float* __restrict__ R,
         float* __restrict__ C, int M, int N, int K)
{
    extern __shared__ __align__(128) char sm[];
    uint32_t sb = smem_u32(sm);
    int tid  = threadIdx.x;
    int wid  = tid >> 5;
    int lane = tid & 31;
    int wm = wid & 1, wn = wid >> 1;
    int bm = blockIdx.y * 128, bn = blockIdx.x * 256;
    int m0 = wm * 64, n0 = wn * 32;

    int laneRow = lane & 15;
    int laneK   = (lane >> 4) * 16;
    uint32_t xorA = (uint32_t)((laneRow & 7) << 4);

    float acc[4][4][4];
    #pragma unroll
    for (int i = 0; i < 4; i++)
        #pragma unroll
        for (int j = 0; j < 4; j++)
            #pragma unroll
            for (int q = 0; q < 4; q++) acc[i][j][q] = 0.f;

    const int NCH = K >> 6;

    auto load_stage = [&](int s, int chunk) {
        uint32_t st = sb + s * STAGE_B;
        int k0 = chunk * 64;
        #pragma unroll
        for (int it = 0; it < 2; it++) {
            int idx = tid + it * 512;
            int row = idx >> 3, c = idx & 7;
            uint32_t d = st + row * 128 + (uint32_t)((c * 16) ^ ((row & 7) << 4));
            size_t go = (size_t)(bm + row) * K + k0 + c * 8;
            cp16(d + SM_A_HI, Ah + go);
            cp16(d + SM_A_LO, Al + go);
        }
        #pragma unroll
        for (int it = 0; it < 4; it++) {
            int idx = tid + it * 512;
            int row = idx >> 3, c = idx & 7;
            uint32_t d = st + row * 128 + (uint32_t)((c * 16) ^ ((row & 7) << 4));
            size_t go = (size_t)(bn + row) * K + k0 + c * 8;
            cp16(d + SM_B_HI, Bh + go);
            cp16(d + SM_B_LO, Bl + go);
        }
    };

    load_stage(0, 0);
    cp_commit();

    for (int chunk = 0; chunk < NCH; chunk++) {
        int s = chunk & 1;
        if (chunk + 1 < NCH) {
            load_stage(s ^ 1, chunk + 1);
            cp_commit();
            cp_wait1();
        } else {
            cp_wait0();
        }
        __syncthreads();

        uint32_t st = sb + s * STAGE_B;
        #pragma unroll
        for (int ks = 0; ks < 4; ks++) {
            uint32_t kb = (uint32_t)((ks * 32 + laneK) ^ xorA);
            uint32_t ah[4][4], bh[2][4];
            #pragma unroll
            for (int i = 0; i < 4; i++)
                ldsm_x4(ah[i], st + SM_A_HI + (uint32_t)(m0 + i*16 + laneRow) * 128 + kb);
            #pragma unroll
            for (int p = 0; p < 2; p++)
                ldsm_x4(bh[p], st + SM_B_HI + (uint32_t)(n0 + p*16 + laneRow) * 128 + kb);
            #pragma unroll
            for (int i = 0; i < 4; i++)
                #pragma unroll
                for (int j = 0; j < 4; j++)
                    mma16816(acc[i][j], ah[i], bh[j>>1][j&1], bh[j>>1][2 + (j&1)]);
            {
                uint32_t al[4][4];
                #pragma unroll
                for (int i = 0; i < 4; i++)
                    ldsm_x4(al[i], st + SM_A_LO + (uint32_t)(m0 + i*16 + laneRow) * 128 + kb);
                #pragma unroll
                for (int i = 0; i < 4; i++)
                    #pragma unroll
                    for (int j = 0; j < 4; j++)
                        mma16816(acc[i][j], al[i], bh[j>>1][j&1], bh[j>>1][2 + (j&1)]);
            }
            {
                uint32_t bl[2][4];
                #pragma unroll
                for (int p = 0; p < 2; p++)
                    ldsm_x4(bl[p], st + SM_B_LO + (uint32_t)(n0 + p*16 + laneRow) * 128 + kb);
                #pragma unroll
                for (int i = 0; i < 4; i++)
                    #pragma unroll
                    for (int j = 0; j < 4; j++)
                        mma16816(acc[i][j], ah[i], bl[j>>1][j&1], bl[j>>1][2 + (j&1)]);
            }
        }
        __syncthreads();
    }

    int group = lane >> 2, tq = lane & 3;
    #pragma unroll
    for (int j = 0; j < 4; j++) {
        int n = bn + n0 + j*8 + tq*2;
        float bv0 = bias[n], bv1 = bias[n+1];
        #pragma unroll
        for (int i = 0; i < 4; i++) {
            int m = bm + m0 + i*16 + group;
            size_t off0 = (size_t)m * N + n;
            size_t off1 = (size_t)(m + 8) * N + n;
            float2 r0 = *(const float2*)(R + off0);
            float2 r1 = *(const float2*)(R + off1);
            *(float2*)(C + off0) = make_float2(acc[i][j][0] + bv0 + r0.x, acc[i][j][1] + bv1 + r0.y);
            *(float2*)(C + off1) = make_float2(acc[i][j][2] + bv0 + r1.x, acc[i][j][3] + bv1 + r1.y);
        }
    }
}

// ====== fused Q/K/V/U projection: one launch, grid.z selects weight ========
__global__ void __launch_bounds__(512, 1)
proj4(const __nv_bfloat16* __restrict__ Ah, const __nv_bfloat16* __restrict__ Al,
      const __nv_bfloat16* __restrict__ WThG, const __nv_bfloat16* __restrict__ WTlG,
      const float* __restrict__ bq, const float* __restrict__ bk,
      const float* __restrict__ bv, const float* __restrict__ bu,
      __nv_bfloat16* __restrict__ Qh, __nv_bfloat16* __restrict__ Ql,
      __nv_bfloat16* __restrict__ Kh, __nv_bfloat16* __restrict__ Kl,
      __nv_bfloat16* __restrict__ VTh, __nv_bfloat16* __restrict__ VTl,
      float* __restrict__ Uf)
{
    extern __shared__ __align__(128) char sm[];
    uint32_t sb = smem_u32(sm);
    int tid  = threadIdx.x;
    int wid  = tid >> 5;
    int lane = tid & 31;
    int wm = wid & 1, wn = wid >> 1;
    int z  = blockIdx.z;
    int bm = blockIdx.y * 128, bn = blockIdx.x * 256;
    int m0 = wm * 64, n0 = wn * 32;
    const int K = 1024, N = 1024;

    const __nv_bfloat16* Bh = WThG + (size_t)z * W1M;
    const __nv_bfloat16* Bl = WTlG + (size_t)z * W1M;
    const float* bias = (z == 0) ? bq : (z == 1) ? bk : (z == 2) ? bv : bu;

    int laneRow = lane & 15;
    int laneK   = (lane >> 4) * 16;
    uint32_t xorA = (uint32_t)((laneRow & 7) << 4);

    float acc[4][4][4];
    #pragma unroll
    for (int i = 0; i < 4; i++)
        #pragma unroll
        for (int j = 0; j < 4; j++)
            #pragma unroll
            for (int q = 0; q < 4; q++) acc[i][j][q] = 0.f;

    const int NCH = K >> 6;

    auto load_stage = [&](int s, int chunk) {
        uint32_t st = sb + s * STAGE_B;
        int k0 = chunk * 64;
        #pragma unroll
        for (int it = 0; it < 2; it++) {
            int idx = tid + it * 512;
            int row = idx >> 3, c = idx & 7;
            uint32_t d = st + row * 128 + (uint32_t)((c * 16) ^ ((row & 7) << 4));
            size_t go = (size_t)(bm + row) * K + k0 + c * 8;
            cp16(d + SM_A_HI, Ah + go);
            cp16(d + SM_A_LO, Al + go);
        }
        #pragma unroll
        for (int it = 0; it < 4; it++) {
            int idx = tid + it * 512;
            int row = idx >> 3, c = idx & 7;
            uint32_t d = st + row * 128 + (uint32_t)((c * 16) ^ ((row & 7) << 4));
            size_t go = (size_t)(bn + row) * K + k0 + c * 8;
            cp16(d + SM_B_HI, Bh + go);
            cp16(d + SM_B_LO, Bl + go);
        }
    };

    load_stage(0, 0);
    cp_commit();

    for (int chunk = 0; chunk < NCH; chunk++) {
        int s = chunk & 1;
        if (chunk + 1 < NCH) {
            load_stage(s ^ 1, chunk + 1);
            cp_commit();
            cp_wait1();
        } else {
            cp_wait0();
        }
        __syncthreads();

        uint32_t st = sb + s * STAGE_B;
        #pragma unroll
        for (int ks = 0; ks < 4; ks++) {
            uint32_t kb = (uint32_t)((ks * 32 + laneK) ^ xorA);
            uint32_t ah[4][4], bh[2][4];
            #pragma unroll
            for (int i = 0; i < 4; i++)
                ldsm_x4(ah[i], st + SM_A_HI + (uint32_t)(m0 + i*16 + laneRow) * 128 + kb);
            #pragma unroll
            for (int p = 0; p < 2; p++)
                ldsm_x4(bh[p], st + SM_B_HI + (uint32_t)(n0 + p*16 + laneRow) * 128 + kb);
            #pragma unroll
            for (int i = 0; i < 4; i++)
                #pragma unroll
                for (int j = 0; j < 4; j++)
                    mma16816(acc[i][j], ah[i], bh[j>>1][j&1], bh[j>>1][2 + (j&1)]);
            {
                uint32_t al[4][4];
                #pragma unroll
                for (int i = 0; i < 4; i++)
                    ldsm_x4(al[i], st + SM_A_LO + (uint32_t)(m0 + i*16 + laneRow) * 128 + kb);
                #pragma unroll
                for (int i = 0; i < 4; i++)
                    #pragma unroll
                    for (int j = 0; j < 4; j++)
                        mma16816(acc[i][j], al[i], bh[j>>1][j&1], bh[j>>1][2 + (j&1)]);
            }
            {
                uint32_t bl[2][4];
                #pragma unroll
                for (int p = 0; p < 2; p++)
                    ldsm_x4(bl[p], st + SM_B_LO + (uint32_t)(n0 + p*16 + laneRow) * 128 + kb);
                #pragma unroll
                for (int i = 0; i < 4; i++)
                    #pragma unroll
                    for (int j = 0; j < 4; j++)
                        mma16816(acc[i][j], ah[i], bl[j>>1][j&1], bl[j>>1][2 + (j&1)]);
            }
        }
        __syncthreads();
    }

    int group = lane >> 2, tq = lane & 3;
    __nv_bfloat16* Yh = (z == 0) ? Qh : Kh;
    __nv_bfloat16* Yl = (z == 0) ? Ql : Kl;
    #pragma unroll
    for (int j = 0; j < 4; j++) {
        int n = bn + n0 + j*8 + tq*2;
        float bv0 = bias[n], bv1 = bias[n+1];
        #pragma unroll
        for (int i = 0; i < 4; i++) {
            int m = bm + m0 + i*16 + group;
            float v0 = acc[i][j][0] + bv0, v1 = acc[i][j][1] + bv1;
            float v2 = acc[i][j][2] + bv0, v3 = acc[i][j][3] + bv1;
            if (z <= 1) {
                __nv_bfloat16 h0,l0,h1,l1,h2,l2,h3,l3;
                split_bf16(v0,h0,l0); split_bf16(v1,h1,l1);
                split_bf16(v2,h2,l2); split_bf16(v3,h3,l3);
                size_t off0 = (size_t)m * N + n;
                size_t off1 = (size_t)(m + 8) * N + n;
                *(__nv_bfloat162*)(Yh + off0) = __nv_bfloat162(h0, h1);
                *(__nv_bfloat162*)(Yl + off0) = __nv_bfloat162(l0, l1);
                *(__nv_bfloat162*)(Yh + off1) = __nv_bfloat162(h2, h3);
                *(__nv_bfloat162*)(Yl + off1) = __nv_bfloat162(l2, l3);
            } else if (z == 2) {
                __nv_bfloat16 h0,l0,h1,l1,h2,l2,h3,l3;
                split_bf16(v0,h0,l0); split_bf16(v1,h1,l1);
                split_bf16(v2,h2,l2); split_bf16(v3,h3,l3);
                int bi = m >> 11, tt = m & 2047;
                int hh = n >> 6,  dd = n & 63;
                size_t vb = ((size_t)((bi*16 + hh)*64 + dd)) * 2048 + tt;
                VTh[vb]        = h0;  VTl[vb]        = l0;
                VTh[vb + 2048] = h1;  VTl[vb + 2048] = l1;
                VTh[vb + 8]    = h2;  VTl[vb + 8]    = l2;
                VTh[vb + 2056] = h3;  VTl[vb + 2056] = l3;
            } else {
                size_t off0 = (size_t)m * N + n;
                size_t off1 = (size_t)(m + 8) * N + n;
                *(float2*)(Uf + off0) = make_float2(siluf(v0), siluf(v1));
                *(float2*)(Uf + off1) = make_float2(siluf(v2), siluf(v3));
            }
        }
    }
}

// ====== w1 GEMM + swiglu fusion ============================================
#define W_A_HI  0
#define W_A_LO  16384
#define W_B1_HI 32768
#define W_B1_LO 49152
#define W_B2_HI 65536
#define W_B2_LO 81920
#define STAGE_W 98304

__global__ void __launch_bounds__(512, 1)
gemm_w1sg(const __nv_bfloat16* __restrict__ Ah, const __nv_bfloat16* __restrict__ Al,
          const __nv_bfloat16* __restrict__ Bh, const __nv_bfloat16* __restrict__ Bl,
          const float* __restrict__ b1,
          __nv_bfloat16* __restrict__ Yh, __nv_bfloat16* __restrict__ Yl)
{
    extern __shared__ __align__(128) char sm[];
    uint32_t sb = smem_u32(sm);
    int tid  = threadIdx.x;
    int wid  = tid >> 5;
    int lane = tid & 31;
    int wm = wid & 1, wn = wid >> 1;
    int bm = blockIdx.y * 128, bn = blockIdx.x * 128;
    int m0 = wm * 64, n0 = wn * 16;
    const int K = 1024;

    int laneRow = lane & 15;
    int laneK   = (lane >> 4) * 16;
    uint32_t xorA = (uint32_t)((laneRow & 7) << 4);

    float acc1[4][2][4], acc2[4][2][4];
    #pragma unroll
    for (int i = 0; i < 4; i++)
        #pragma unroll
        for (int j = 0; j < 2; j++)
            #pragma unroll
            for (int q = 0; q < 4; q++) { acc1[i][j][q] = 0.f; acc2[i][j][q] = 0.f; }

    const int NCH = K >> 6;

    auto load_stage = [&](int s, int chunk) {
        uint32_t st = sb + s * STAGE_W;
        int k0 = chunk * 64;
        #pragma unroll
        for (int it = 0; it < 2; it++) {
            int idx = tid + it * 512;
            int row = idx >> 3, c = idx & 7;
            uint32_t d = st + row * 128 + (uint32_t)((c * 16) ^ ((row & 7) << 4));
            size_t goA  = (size_t)(bm + row) * K + k0 + c * 8;
            size_t goB1 = (size_t)(bn + row) * K + k0 + c * 8;
            size_t goB2 = (size_t)(1024 + bn + row) * K + k0 + c * 8;
            cp16(d + W_A_HI,  Ah + goA);
            cp16(d + W_A_LO,  Al + goA);
            cp16(d + W_B1_HI, Bh + goB1);
            cp16(d + W_B1_LO, Bl + goB1);
            cp16(d + W_B2_HI, Bh + goB2);
            cp16(d + W_B2_LO, Bl + goB2);
        }
    };

    load_stage(0, 0);
    cp_commit();

    for (int chunk = 0; chunk < NCH; chunk++) {
        int s = chunk & 1;
        if (chunk + 1 < NCH) {
            load_stage(s ^ 1, chunk + 1);
            cp_commit();
            cp_wait1();
        } else {
            cp_wait0();
        }
        __syncthreads();

        uint32_t st = sb + s * STAGE_W;
        #pragma unroll
        for (int ks = 0; ks < 4; ks++) {
            uint32_t kb = (uint32_t)((ks * 32 + laneK) ^ xorA);
            uint32_t ah[4][4], b1h[4], b2h[4];
            #pragma unroll
            for (int i = 0; i < 4; i++)
                ldsm_x4(ah[i], st + W_A_HI + (uint32_t)(m0 + i*16 + laneRow) * 128 + kb);
            ldsm_x4(b1h, st + W_B1_HI + (uint32_t)(n0 + laneRow) * 128 + kb);
            ldsm_x4(b2h, st + W_B2_HI + (uint32_t)(n0 + laneRow) * 128 + kb);
            #pragma unroll
            for (int i = 0; i < 4; i++)
                #pragma unroll
                for (int j = 0; j < 2; j++) {
                    mma16816(acc1[i][j], ah[i], b1h[j], b1h[2 + j]);
                    mma16816(acc2[i][j], ah[i], b2h[j], b2h[2 + j]);
                }
            {
                uint32_t al[4][4];
                #pragma unroll
                for (int i = 0; i < 4; i++)
                    ldsm_x4(al[i], st + W_A_LO + (uint32_t)(m0 + i*16 + laneRow) * 128 + kb);
                #pragma unroll
                for (int i = 0; i < 4; i++)
                    #pragma unroll
                    for (int j = 0; j < 2; j++) {
                        mma16816(acc1[i][j], al[i], b1h[j], b1h[2 + j]);
                        mma16816(acc2[i][j], al[i], b2h[j], b2h[2 + j]);
                    }
            }
            {
                uint32_t b1l[4], b2l[4];
                ldsm_x4(b1l, st + W_B1_LO + (uint32_t)(n0 + laneRow) * 128 + kb);
                ldsm_x4(b2l, st + W_B2_LO + (uint32_t)(n0 + laneRow) * 128 + kb);
                #pragma unroll
                for (int i = 0; i < 4; i++)
                    #pragma unroll
                    for (int j = 0; j < 2; j++) {
                        mma16816(acc1[i][j], ah[i], b1l[j], b1l[2 + j]);
                        mma16816(acc2[i][j], ah[i], b2l[j], b2l[2 + j]);
                    }
            }
        }
        __syncthreads();
    }

    int group = lane >> 2, tq = lane & 3;
    #pragma unroll
    for (int j = 0; j < 2; j++) {
        int n = bn + n0 + j*8 + tq*2;
        float c10 = b1[n], c11 = b1[n+1];
        float c20 = b1[1024 + n], c21 = b1[1025 + n];
        #pragma unroll
        for (int i = 0; i < 4; i++) {
            int m = bm + m0 + i*16 + group;
            float y0 = siluf(acc1[i][j][0] + c10) * (acc2[i][j][0] + c20);
            float y1 = siluf(acc1[i][j][1] + c11) * (acc2[i][j][1] + c21);
            float y2 = siluf(acc1[i][j][2] + c10) * (acc2[i][j][2] + c20);
            float y3 = siluf(acc1[i][j][3] + c11) * (acc2[i][j][3] + c21);
            __nv_bfloat16 h0,l0,h1,l1,h2,l2,h3,l3;
            split_bf16(y0,h0,l0); split_bf16(y1,h1,l1);
            split_bf16(y2,h2,l2); split_bf16(y3,h3,l3);
            size_t off0 = (size_t)m * 1024 + n;
            size_t off1 = (size_t)(m + 8) * 1024 + n;
            *(__nv_bfloat162*)(Yh + off0) = __nv_bfloat162(h0, h1);
            *(__nv_bfloat162*)(Yl + off0) = __nv_bfloat162(l0, l1);
            *(__nv_bfloat162*)(Yh + off1) = __nv_bfloat162(h2, h3);
            *(__nv_bfloat162*)(Yl + off1) = __nv_bfloat162(l2, l3);
        }
    }
}

// ===== attention: 16 warps, key-split intra-CTA, kv-split across CTAs =======
// grid (16, 16, 4): z = b + 2*kv. Each CTA does kt in [kv*8, kv*8+8) and
// writes fp32 partial O to P[kv]. merge_ams sums partials + rmsnorm*U.
#define A_SQH 0u
#define A_SQL 16384u
#define A_SK  32768u       // + s*32768 : KH, KL(+16384)
#define A_SVT 98304u       // + s*32768 : VTH, VTL(+16384)
#define A_PB  163840u      // + s*512
#define A_RED A_SK         // reduction area reuses K stage 0 (32KB)
#define ATT_SMEM 164864

__global__ void __launch_bounds__(512, 1)
attn_tc(const __nv_bfloat16* __restrict__ Qh, const __nv_bfloat16* __restrict__ Ql,
        const __nv_bfloat16* __restrict__ Kh, const __nv_bfloat16* __restrict__ Kl,
        const __nv_bfloat16* __restrict__ VTh, const __nv_bfloat16* __restrict__ VTl,
        const float* __restrict__ PB, float* __restrict__ P0, float* __restrict__ P1)
{
    extern __shared__ __align__(128) char sm[];
    uint32_t sb = smem_u32(sm);
    int tid  = threadIdx.x;
    int wid  = tid >> 5;
    int lane = tid & 31;
    int qt = blockIdx.x, h = blockIdx.y;
    int b  = blockIdx.z & 1;
    int kv = blockIdx.z >> 1;
    float* P = kv ? P1 : P0;
    int ktBeg = kv * (SEQ/256);          // 8 iters each
    int mw = wid & 7;
    int kw = wid >> 3;
    int m0 = mw * 16;
    int ntb = kw * 4;

    int laneRow = lane & 15;
    int laneK   = (lane >> 4) * 16;
    uint32_t xorA = (uint32_t)((laneRow & 7) << 4);
    int group = lane >> 2, tq = lane & 3;
    uint32_t rowbK = (uint32_t)laneRow * 128;
    uint32_t rowbV = (uint32_t)laneRow * 256;

    auto load_q = [&]() {
        #pragma unroll
        for (int it = 0; it < 2; it++) {
            int idx = tid + it * 512;
            int row = idx >> 3, c = idx & 7;
            uint32_t d = row * 128 + (uint32_t)((c * 16) ^ ((row & 7) << 4));
            size_t go = ((size_t)(b*SEQ + qt*128 + row)) * D_MODEL + h*64 + c*8;
            cp16(sb + A_SQH + d, Qh + go);
            cp16(sb + A_SQL + d, Ql + go);
        }
    };
    auto load_kv = [&](int s, int kt) {
        uint32_t kbase = sb + A_SK + (uint32_t)s * 32768u;
        #pragma unroll
        for (int it = 0; it < 2; it++) {
            int idx = tid + it * 512;
            int row = idx >> 3, c = idx & 7;
            uint32_t d = row * 128 + (uint32_t)((c * 16) ^ ((row & 7) << 4));
            size_t go = ((size_t)(b*SEQ + kt*128 + row)) * D_MODEL + h*64 + c*8;
            cp16(kbase + d, Kh + go);
            cp16(kbase + 16384u + d, Kl + go);
        }
        uint32_t vbase = sb + A_SVT + (uint32_t)s * 32768u;
        #pragma unroll
        for (int it = 0; it < 2; it++) {
            int idx = tid + it * 512;
            int row = idx >> 4, c = idx & 15;
            uint32_t d = row * 256 + (uint32_t)((c * 16) ^ ((row & 7) << 4));
            size_t go = ((size_t)((b*16 + h)*64 + row)) * 2048 + kt*128 + c*8;
            cp16(vbase + d, VTh + go);
            cp16(vbase + 16384u + d, VTl + go);
        }
        if (tid < 128) {
            float v = PB[(size_t)(kt*128 + tid) * N_HEADS + h];
            *(float*)(sm + A_PB + (uint32_t)s * 512u + tid * 4) = v;
        }
    };

    float accO[8][4];
    #pragma unroll
    for (int f = 0; f < 8; f++)
        #pragma unroll
        for (int q = 0; q < 4; q++) accO[f][q] = 0.f;

    load_q(); cp_commit();
    load_kv(0, ktBeg); cp_commit();
    cp_wait1();
    __syncthreads();

    // hoist Q hi + lo fragments (loop-invariant)
    uint32_t qfh[4][4], qfl[4][4];
    #pragma unroll
    for (int ks = 0; ks < 4; ks++) {
        uint32_t kb = (uint32_t)((ks * 32 + laneK) ^ xorA);
        ldsm_x4(qfh[ks], sb + A_SQH + (uint32_t)m0 * 128 + rowbK + kb);
        ldsm_x4(qfl[ks], sb + A_SQL + (uint32_t)m0 * 128 + rowbK + kb);
    }

    const int NIT = SEQ/256;   // 8
    for (int it = 0; it < NIT; it++) {
        int kt = ktBeg + it;
        int s = it & 1;
        if (it + 1 < NIT) {
            load_kv(s ^ 1, kt + 1);
            cp_commit();
            cp_wait1();
        } else {
            cp_wait0();
        }
        __syncthreads();

        uint32_t kst = sb + A_SK + (uint32_t)s * 32768u + (uint32_t)ntb * 2048u;
        uint32_t vst = sb + A_SVT + (uint32_t)s * 32768u;
        const float* pbs = (const float*)(sm + A_PB + (uint32_t)s * 512u);

        #pragma unroll
        for (int c = 0; c < 2; c++) {
            float sc[4][4];
            #pragma unroll
            for (int f = 0; f < 4; f++)
                #pragma unroll
                for (int q = 0; q < 4; q++) sc[f][q] = 0.f;

            #pragma unroll
            for (int ks = 0; ks < 4; ks++) {
                uint32_t kb = (uint32_t)((ks * 32 + laneK) ^ xorA);
                #pragma unroll
                for (int t = 0; t < 2; t++) {
                    int nt = 2*c + t;
                    uint32_t kf[4];
                    ldsm_x4(kf, kst + (uint32_t)nt * 2048u + rowbK + kb);
                    mma16816(sc[2*t],   qfh[ks], kf[0], kf[2]);
                    mma16816(sc[2*t+1], qfh[ks], kf[1], kf[3]);
                    mma16816(sc[2*t],   qfl[ks], kf[0], kf[2]);
                    mma16816(sc[2*t+1], qfl[ks], kf[1], kf[3]);
                    uint32_t kl[4];
                    ldsm_x4(kl, kst + 16384u + (uint32_t)nt * 2048u + rowbK + kb);
                    mma16816(sc[2*t],   qfh[ks], kl[0], kl[2]);
                    mma16816(sc[2*t+1], qfh[ks], kl[1], kl[3]);
                }
            }

            uint32_t sfh[2][4], sfl[2][4];
            #pragma unroll
            for (int t = 0; t < 2; t++) {
                int nt = 2*c + t;
                #pragma unroll
                for (int half = 0; half < 2; half++) {
                    int f = 2*t + half;
                    int tcol = ntb*16 + nt*16 + half*8 + tq*2;
                    float pb0 = pbs[tcol], pb1 = pbs[tcol + 1];
                    float w0 = siluf(sc[f][0] * 0.125f + pb0);
                    float w1 = siluf(sc[f][1] * 0.125f + pb1);
                    float w2 = siluf(sc[f][2] * 0.125f + pb0);
                    float w3 = siluf(sc[f][3] * 0.125f + pb1);
                    __nv_bfloat16 h0,l0,h1,l1,h2,l2,h3,l3;
                    split_bf16(w0,h0,l0); split_bf16(w1,h1,l1);
                    split_bf16(w2,h2,l2); split_bf16(w3,h3,l3);
                    sfh[t][half*2]     = pack_bf16(h0, h1);
                    sfh[t][half*2 + 1] = pack_bf16(h2, h3);
                    sfl[t][half*2]     = pack_bf16(l0, l1);
                    sfl[t][half*2 + 1] = pack_bf16(l2, l3);
                }
            }

            #pragma unroll
            for (int t = 0; t < 2; t++) {
                int gks = ntb + 2*c + t;
                uint32_t kb = (uint32_t)((gks * 32 + laneK) ^ xorA);
                #pragma unroll
                for (int dn = 0; dn < 4; dn++) {
                    uint32_t vf[4];
                    ldsm_x4(vf, vst + (uint32_t)dn * 4096u + rowbV + kb);
                    mma16816(accO[2*dn],   sfh[t], vf[0], vf[2]);
                    mma16816(accO[2*dn+1], sfh[t], vf[1], vf[3]);
                    mma16816(accO[2*dn],   sfl[t], vf[0], vf[2]);
                    mma16816(accO[2*dn+1], sfl[t], vf[1], vf[3]);
                    uint32_t vl[4];
                    ldsm_x4(vl, vst + 16384u + (uint32_t)dn * 4096u + rowbV + kb);
                    mma16816(accO[2*dn],   sfh[t], vl[0], vl[2]);
                    mma16816(accO[2*dn+1], sfh[t], vl[1], vl[3]);
                }
            }
        }
        __syncthreads();
    }

    // ---- merge key-half partials within CTA, write fp32 partial to P ----
    if (kw == 1) {
        float* red = (float*)(sm + A_RED) + ((size_t)mw * 32 + lane) * 32;
        #pragma unroll
        for (int f = 0; f < 8; f++) {
            red[f*4+0] = accO[f][0]; red[f*4+1] = accO[f][1];
            red[f*4+2] = accO[f][2]; red[f*4+3] = accO[f][3];
        }
    }
    __syncthreads();
    if (kw == 0) {
        const float* red = (const float*)(sm + A_RED) + ((size_t)mw * 32 + lane) * 32;
        #pragma unroll
        for (int dn = 0; dn < 4; dn++) {
            #pragma unroll
            for (int half = 0; half < 2; half++) {
                int f = 2*dn + half;
                float o0 = accO[f][0] + red[f*4+0];
                float o1 = accO[f][1] + red[f*4+1];
                float o2 = accO[f][2] + red[f*4+2];
                float o3 = accO[f][3] + red[f*4+3];
                int col = h*64 + dn*16 + half*8 + tq*2;
                int row = b*SEQ + qt*128 + m0 + group;
                *(float2*)(P + (size_t)row * D_MODEL + col) = make_float2(o0, o1);
                *(float2*)(P + (size_t)(row + 8) * D_MODEL + col) = make_float2(o2, o3);
            }
        }
    }
}

// ---------------- launch ----------------------------------------------------
extern "C" void kernel_launch(void* const* d_in, const int* in_sizes, int n_in,
                              void* d_out, int out_size)
{
    const float* x      = (const float*)d_in[0];
    const float* pb     = (const float*)d_in[2];
    const float* wq     = (const float*)d_in[3];
    const float* bq     = (const float*)d_in[4];
    const float* wk     = (const float*)d_in[5];
    const float* bk_    = (const float*)d_in[6];
    const float* wv     = (const float*)d_in[7];
    const float* bv     = (const float*)d_in[8];
    const float* wu     = (const float*)d_in[9];
    const float* bu     = (const float*)d_in[10];
    const float* g_ams  = (const float*)d_in[11];
    const float* w0     = (const float*)d_in[12];
    const float* b0     = (const float*)d_in[13];
    const float* w1     = (const float*)d_in[14];
    const float* b1     = (const float*)d_in[15];
    const float* w2     = (const float*)d_in[16];
    const float* b2     = (const float*)d_in[17];
    const float* g_mffn = (const float*)d_in[18];
    float* out = (float*)d_out;

    float *Qf, *Kf, *Vf, *Uf, *AOf, *P2f, *Of;
    __nv_bfloat16 *A1h, *A1l, *A2h, *A2l, *WTh, *WTl;
    cudaGetSymbolAddress((void**)&Qf,  g_Q);
    cudaGetSymbolAddress((void**)&Kf,  g_K);
    cudaGetSymbolAddress((void**)&Vf,  g_V);
    cudaGetSymbolAddress((void**)&Uf,  g_U);
    cudaGetSymbolAddress((void**)&AOf, g_AO);
    cudaGetSymbolAddress((void**)&P2f, g_P2);
    cudaGetSymbolAddress((void**)&Of,  g_O);
    cudaGetSymbolAddress((void**)&A1h, g_A1h);
    cudaGetSymbolAddress((void**)&A1l, g_A1l);
    cudaGetSymbolAddress((void**)&A2h, g_A2h);
    cudaGetSymbolAddress((void**)&A2l, g_A2l);
    cudaGetSymbolAddress((void**)&WTh, g_WTh);
    cudaGetSymbolAddress((void**)&WTl, g_WTl);

    const size_t NEL = (size_t)M_ROWS * D_MODEL;
    __nv_bfloat16 *Qhb = (__nv_bfloat16*)Qf,  *Qlb = Qhb + NEL;
    __nv_bfloat16 *Khb = (__nv_bfloat16*)Kf,  *Klb = Khb + NEL;
    __nv_bfloat16 *VTh = (__nv_bfloat16*)Vf,  *VTl = VTh + NEL;

    __nv_bfloat16 *T0_h = WTh + (size_t)4*W1M, *T0_l = WTl + (size_t)4*W1M;
    __nv_bfloat16 *T2_h = WTh + (size_t)5*W1M, *T2_l = WTl + (size_t)5*W1M;
    __nv_bfloat16 *T1_h = WTh + (size_t)6*W1M, *T1_l = WTl + (size_t)6*W1M;

    const int GSM = 2 * STAGE_B;
    cudaFuncSetAttribute(gemm_res,  cudaFuncAttributeMaxDynamicSharedMemorySize, GSM);
    cudaFuncSetAttribute(proj4,     cudaFuncAttributeMaxDynamicSharedMemorySize, GSM);
    cudaFuncSetAttribute(gemm_w1sg, cudaFuncAttributeMaxDynamicSharedMemorySize, 2*STAGE_W);
    cudaFuncSetAttribute(attn_tc,   cudaFuncAttributeMaxDynamicSharedMemorySize, ATT_SMEM);

    wtsplit_all<<<8192, dim3(32, 8)>>>(wq, wk, wv, wu, w0, w2, w1, WTh, WTl);
    rmsnorm_tc<<<M_ROWS, 256>>>(x, g_ams, A1h, A1l);
    proj4<<<dim3(4, 32, 4), 512, GSM>>>(A1h, A1l, WTh, WTl, bq, bk_, bv, bu,
                                        Qhb, Qlb, Khb, Klb, VTh, VTl, Uf);
    // split-K attention: 1024 CTAs, each half the keys, fp32 partials
    attn_tc<<<dim3(SEQ/128, N_HEADS, BATCH*2), 512, ATT_SMEM>>>(Qhb, Qlb, Khb, Klb, VTh, VTl, pb, AOf, P2f);
    // merge partials + ams in one pass
    merge_ams<<<M_ROWS, 256>>>(AOf, P2f, g_ams, Uf, A2h, A2l);
    gemm_res<<<dim3(4, 32), 512, GSM>>>(A2h, A2l, T0_h, T0_l, b0, x, Of, M_ROWS, 1024, 1024);
    rmsnorm_tc<<<M_ROWS, 256>>>(Of, g_mffn, A1h, A1l);
    gemm_w1sg<<<dim3(8, 32), 512, 2*STAGE_W>>>(A1h, A1l, T1_h, T1_l, b1, A2h, A2l);
    gemm_res<<<dim3(4, 32), 512, GSM>>>(A2h, A2l, T2_h, T2_l, b2, Of, out, M_ROWS, 1024, 1024);
}

// round 13
// speedup vs baseline: 1.2645x; 1.0835x over previous
#include <cuda_runtime.h>
#include <cuda_bf16.h>
#include <cuda_fp16.h>
#include <cstdint>
#include <math.h>

#define D_MODEL 1024
#define N_HEADS 16
#define DH      64
#define BATCH   2
#define SEQ     2048
#define M_ROWS  (BATCH*SEQ)   // 4096

// ---------------- scratch (static device globals; no allocations) ----------
__device__ float g_Q  [M_ROWS*D_MODEL];   // aliased: Q fp16 (single)
__device__ float g_K  [M_ROWS*D_MODEL];   // aliased: Kh/Kl fp16
__device__ float g_V  [M_ROWS*D_MODEL];   // aliased: VTh/VTl fp16 (transposed per head)
__device__ float g_U  [M_ROWS*D_MODEL];
__device__ float g_AO [M_ROWS*D_MODEL];   // attention partial 0
__device__ float g_P2 [M_ROWS*D_MODEL];   // attention partial 1
__device__ float g_O  [M_ROWS*D_MODEL];

__device__ __nv_bfloat16 g_A1h[M_ROWS*D_MODEL];
__device__ __nv_bfloat16 g_A1l[M_ROWS*D_MODEL];
__device__ __nv_bfloat16 g_A2h[M_ROWS*D_MODEL];
__device__ __nv_bfloat16 g_A2l[M_ROWS*D_MODEL];

__device__ __nv_bfloat16 g_WTh[8*1024*1024];
__device__ __nv_bfloat16 g_WTl[8*1024*1024];

#define W1M (1024*1024)

__device__ __forceinline__ float siluf(float z) {
    return z * (1.0f / (1.0f + __expf(-z)));
}

__device__ __forceinline__ uint32_t smem_u32(const void* p) {
    uint32_t a;
    asm("{ .reg .u64 t; cvta.to.shared.u64 t, %1; cvt.u32.u64 %0, t; }" : "=r"(a) : "l"(p));
    return a;
}

__device__ __forceinline__ void ldsm_x4(uint32_t* r, uint32_t a) {
    asm volatile("ldmatrix.sync.aligned.m8n8.x4.shared.b16 {%0,%1,%2,%3}, [%4];"
                 : "=r"(r[0]), "=r"(r[1]), "=r"(r[2]), "=r"(r[3]) : "r"(a));
}

__device__ __forceinline__ void mma16816(float* c, const uint32_t* a, uint32_t b0, uint32_t b1) {
    asm volatile("mma.sync.aligned.m16n8k16.row.col.f32.bf16.bf16.f32 "
                 "{%0,%1,%2,%3}, {%4,%5,%6,%7}, {%8,%9}, {%0,%1,%2,%3};"
                 : "+f"(c[0]), "+f"(c[1]), "+f"(c[2]), "+f"(c[3])
                 : "r"(a[0]), "r"(a[1]), "r"(a[2]), "r"(a[3]), "r"(b0), "r"(b1));
}

__device__ __forceinline__ void mma16816h(float* c, const uint32_t* a, uint32_t b0, uint32_t b1) {
    asm volatile("mma.sync.aligned.m16n8k16.row.col.f32.f16.f16.f32 "
                 "{%0,%1,%2,%3}, {%4,%5,%6,%7}, {%8,%9}, {%0,%1,%2,%3};"
                 : "+f"(c[0]), "+f"(c[1]), "+f"(c[2]), "+f"(c[3])
                 : "r"(a[0]), "r"(a[1]), "r"(a[2]), "r"(a[3]), "r"(b0), "r"(b1));
}

__device__ __forceinline__ void cp16(uint32_t dst, const void* src) {
    asm volatile("cp.async.cg.shared.global [%0], [%1], 16;" :: "r"(dst), "l"(src));
}
__device__ __forceinline__ void cp_commit() { asm volatile("cp.async.commit_group;"); }
__device__ __forceinline__ void cp_wait1()  { asm volatile("cp.async.wait_group 1;"); }
__device__ __forceinline__ void cp_wait0()  { asm volatile("cp.async.wait_group 0;"); }

__device__ __forceinline__ void split_bf16(float v, __nv_bfloat16& h, __nv_bfloat16& l) {
    h = __float2bfloat16(v);
    l = __float2bfloat16(v - __bfloat162float(h));
}

__device__ __forceinline__ void split_f16(float v, __half& h, __half& l) {
    h = __float2half_rn(v);
    l = __float2half_rn(v - __half2float(h));
}

__device__ __forceinline__ uint32_t pack_f16(float a, float b) {
    __half2 t = __floats2half2_rn(a, b);
    return *(uint32_t*)&t;
}

// ======= batched weight transpose + bf16 split (all 7 weights, 1 launch) ====
__global__ void __launch_bounds__(256)
wtsplit_all(const float* __restrict__ wq, const float* __restrict__ wk,
            const float* __restrict__ wv, const float* __restrict__ wu,
            const float* __restrict__ w0, const float* __restrict__ w2,
            const float* __restrict__ w1,
            __nv_bfloat16* __restrict__ WTh, __nv_bfloat16* __restrict__ WTl)
{
    __shared__ float t[32][33];
    int bid = blockIdx.x;
    const float* W; __nv_bfloat16 *Th, *Tl;
    int N, nx, ky;
    if (bid < 6144) {
        int w = bid >> 10, local = bid & 1023;
        switch (w) {
            case 0: W = wq; break; case 1: W = wk; break;
            case 2: W = wv; break; case 3: W = wu; break;
            case 4: W = w0; break; default: W = w2; break;
        }
        Th = WTh + (size_t)w * W1M; Tl = WTl + (size_t)w * W1M;
        N = 1024; nx = local & 31; ky = local >> 5;
    } else {
        int local = bid - 6144;
        W = w1; Th = WTh + (size_t)6 * W1M; Tl = WTl + (size_t)6 * W1M;
        N = 2048; nx = local & 63; ky = local >> 6;
    }
    const int K = 1024;
    int tx = threadIdx.x, ty = threadIdx.y;
    int n0 = nx * 32, k0 = ky * 32;
    #pragma unroll
    for (int i = 0; i < 4; i++)
        t[ty + i*8][tx] = W[(size_t)(k0 + ty + i*8) * N + n0 + tx];
    __syncthreads();
    #pragma unroll
    for (int i = 0; i < 4; i++) {
        float v = t[tx][ty + i*8];
        __nv_bfloat16 hi, lo;
        split_bf16(v, hi, lo);
        size_t off = (size_t)(n0 + ty + i*8) * K + k0 + tx;
        Th[off] = hi; Tl[off] = lo;
    }
}

// ---------------- RMSNorm -> bf16 hi/lo -------------------------------------
__global__ void __launch_bounds__(256)
rmsnorm_tc(const float* __restrict__ X, const float* __restrict__ g,
           __nv_bfloat16* __restrict__ Yh, __nv_bfloat16* __restrict__ Yl)
{
    int r = blockIdx.x, t = threadIdx.x;
    float4 v = ((const float4*)(X + (size_t)r * D_MODEL))[t];
    float ss = v.x*v.x + v.y*v.y + v.z*v.z + v.w*v.w;
    #pragma unroll
    for (int o = 16; o; o >>= 1) ss += __shfl_xor_sync(0xffffffffu, ss, o);
    __shared__ float ws[8]; __shared__ float s_inv;
    if ((t & 31) == 0) ws[t >> 5] = ss;
    __syncthreads();
    if (t == 0) {
        float tot = 0.f;
        #pragma unroll
        for (int i = 0; i < 8; i++) tot += ws[i];
        s_inv = rsqrtf(tot * (1.0f / D_MODEL) + 1e-8f);
    }
    __syncthreads();
    float iv = s_inv;
    float4 gv = ((const float4*)g)[t];
    float o[4] = {v.x*iv*gv.x, v.y*iv*gv.y, v.z*iv*gv.z, v.w*iv*gv.w};
    __nv_bfloat16 h[4], l[4];
    #pragma unroll
    for (int i = 0; i < 4; i++) split_bf16(o[i], h[i], l[i]);
    size_t base = (size_t)r * D_MODEL + t*4;
    *(__nv_bfloat162*)(Yh + base)     = __nv_bfloat162(h[0], h[1]);
    *(__nv_bfloat162*)(Yh + base + 2) = __nv_bfloat162(h[2], h[3]);
    *(__nv_bfloat162*)(Yl + base)     = __nv_bfloat162(l[0], l[1]);
    *(__nv_bfloat162*)(Yl + base + 2) = __nv_bfloat162(l[2], l[3]);
}

// -------- merge attention partials + ams: rmsnorm(P0+P1, g) * U -> bf16 -----
__global__ void __launch_bounds__(256)
merge_ams(const float* __restrict__ P0, const float* __restrict__ P1,
          const float* __restrict__ g, const float* __restrict__ U,
          __nv_bfloat16* __restrict__ Yh, __nv_bfloat16* __restrict__ Yl)
{
    int r = blockIdx.x, t = threadIdx.x;
    float4 a = ((const float4*)(P0 + (size_t)r * D_MODEL))[t];
    float4 bb = ((const float4*)(P1 + (size_t)r * D_MODEL))[t];
    float4 v;
    v.x = a.x + bb.x; v.y = a.y + bb.y; v.z = a.z + bb.z; v.w = a.w + bb.w;
    float ss = v.x*v.x + v.y*v.y + v.z*v.z + v.w*v.w;
    #pragma unroll
    for (int o = 16; o; o >>= 1) ss += __shfl_xor_sync(0xffffffffu, ss, o);
    __shared__ float ws[8]; __shared__ float s_inv;
    if ((t & 31) == 0) ws[t >> 5] = ss;
    __syncthreads();
    if (t == 0) {
        float tot = 0.f;
        #pragma unroll
        for (int i = 0; i < 8; i++) tot += ws[i];
        s_inv = rsqrtf(tot * (1.0f / D_MODEL) + 1e-8f);
    }
    __syncthreads();
    float iv = s_inv;
    float4 gv = ((const float4*)g)[t];
    float4 uv = ((const float4*)(U + (size_t)r * D_MODEL))[t];
    float o[4] = {v.x*iv*gv.x*uv.x, v.y*iv*gv.y*uv.y, v.z*iv*gv.z*uv.z, v.w*iv*gv.w*uv.w};
    __nv_bfloat16 h[4], l[4];
    #pragma unroll
    for (int i = 0; i < 4; i++) split_bf16(o[i], h[i], l[i]);
    size_t base = (size_t)r * D_MODEL + t*4;
    *(__nv_bfloat162*)(Yh + base)     = __nv_bfloat162(h[0], h[1]);
    *(__nv_bfloat162*)(Yh + base + 2) = __nv_bfloat162(h[2], h[3]);
    *(__nv_bfloat162*)(Yl + base)     = __nv_bfloat162(l[0], l[1]);
    *(__nv_bfloat162*)(Yl + base + 2) = __nv_bfloat162(l[2], l[3]);
}

// ============== HMMA GEMM (EPI 2 only): C = A@B^T + bias + R ================
#define SM_A_HI 0
#define SM_A_LO 16384
#define SM_B_HI 32768
#define SM_B_LO 65536
#define STAGE_B 98304

__global__ void __launch_bounds__(512, 1)
gemm_res(const __nv_bfloat16* __restrict__ Ah, const __nv_bfloat16* __restrict__ Al,
         const __nv_bfloat16* __restrict__ Bh, const __nv_bfloat16* __restrict__ Bl,
         const float* __restrict__ bias, const float* __restrict__ R,
         float* __restrict__ C, int M, int N, int K)
{
    extern __shared__ __align__(128) char sm[];
    uint32_t sb = smem_u32(sm);
    int tid  = threadIdx.x;
    int wid  = tid >> 5;
    int lane = tid & 31;
    int wm = wid & 1, wn = wid >> 1;
    int bm = blockIdx.y * 128, bn = blockIdx.x * 256;
    int m0 = wm * 64, n0 = wn * 32;

    int laneRow = lane & 15;
    int laneK   = (lane >> 4) * 16;
    uint32_t xorA = (uint32_t)((laneRow & 7) << 4);

    float acc[4][4][4];
    #pragma unroll
    for (int i = 0; i < 4; i++)
        #pragma unroll
        for (int j = 0; j < 4; j++)
            #pragma unroll
            for (int q = 0; q < 4; q++) acc[i][j][q] = 0.f;

    const int NCH = K >> 6;

    auto load_stage = [&](int s, int chunk) {
        uint32_t st = sb + s * STAGE_B;
        int k0 = chunk * 64;
        #pragma unroll
        for (int it = 0; it < 2; it++) {
            int idx = tid + it * 512;
            int row = idx >> 3, c = idx & 7;
            uint32_t d = st + row * 128 + (uint32_t)((c * 16) ^ ((row & 7) << 4));
            size_t go = (size_t)(bm + row) * K + k0 + c * 8;
            cp16(d + SM_A_HI, Ah + go);
            cp16(d + SM_A_LO, Al + go);
        }
        #pragma unroll
        for (int it = 0; it < 4; it++) {
            int idx = tid + it * 512;
            int row = idx >> 3, c = idx & 7;
            uint32_t d = st + row * 128 + (uint32_t)((c * 16) ^ ((row & 7) << 4));
            size_t go = (size_t)(bn + row) * K + k0 + c * 8;
            cp16(d + SM_B_HI, Bh + go);
            cp16(d + SM_B_LO, Bl + go);
        }
    };

    load_stage(0, 0);
    cp_commit();

    for (int chunk = 0; chunk < NCH; chunk++) {
        int s = chunk & 1;
        if (chunk + 1 < NCH) {
            load_stage(s ^ 1, chunk + 1);
            cp_commit();
            cp_wait1();
        } else {
            cp_wait0();
        }
        __syncthreads();

        uint32_t st = sb + s * STAGE_B;
        #pragma unroll
        for (int ks = 0; ks < 4; ks++) {
            uint32_t kb = (uint32_t)((ks * 32 + laneK) ^ xorA);
            uint32_t ah[4][4], bh[2][4];
            #pragma unroll
            for (int i = 0; i < 4; i++)
                ldsm_x4(ah[i], st + SM_A_HI + (uint32_t)(m0 + i*16 + laneRow) * 128 + kb);
            #pragma unroll
            for (int p = 0; p < 2; p++)
                ldsm_x4(bh[p], st + SM_B_HI + (uint32_t)(n0 + p*16 + laneRow) * 128 + kb);
            #pragma unroll
            for (int i = 0; i < 4; i++)
                #pragma unroll
                for (int j = 0; j < 4; j++)
                    mma16816(acc[i][j], ah[i], bh[j>>1][j&1], bh[j>>1][2 + (j&1)]);
            {
                uint32_t al[4][4];
                #pragma unroll
                for (int i = 0; i < 4; i++)
                    ldsm_x4(al[i], st + SM_A_LO + (uint32_t)(m0 + i*16 + laneRow) * 128 + kb);
                #pragma unroll
                for (int i = 0; i < 4; i++)
                    #pragma unroll
                    for (int j = 0; j < 4; j++)
                        mma16816(acc[i][j], al[i], bh[j>>1][j&1], bh[j>>1][2 + (j&1)]);
            }
            {
                uint32_t bl[2][4];
                #pragma unroll
                for (int p = 0; p < 2; p++)
                    ldsm_x4(bl[p], st + SM_B_LO + (uint32_t)(n0 + p*16 + laneRow) * 128 + kb);
                #pragma unroll
                for (int i = 0; i < 4; i++)
                    #pragma unroll
                    for (int j = 0; j < 4; j++)
                        mma16816(acc[i][j], ah[i], bl[j>>1][j&1], bl[j>>1][2 + (j&1)]);
            }
        }
        __syncthreads();
    }

    int group = lane >> 2, tq = lane & 3;
    #pragma unroll
    for (int j = 0; j < 4; j++) {
        int n = bn + n0 + j*8 + tq*2;
        float bv0 = bias[n], bv1 = bias[n+1];
        #pragma unroll
        for (int i = 0; i < 4; i++) {
            int m = bm + m0 + i*16 + group;
            size_t off0 = (size_t)m * N + n;
            size_t off1 = (size_t)(m + 8) * N + n;
            float2 r0 = *(const float2*)(R + off0);
            float2 r1 = *(const float2*)(R + off1);
            *(float2*)(C + off0) = make_float2(acc[i][j][0] + bv0 + r0.x, acc[i][j][1] + bv1 + r0.y);
            *(float2*)(C + off1) = make_float2(acc[i][j][2] + bv0 + r1.x, acc[i][j][3] + bv1 + r1.y);
        }
    }
}

// ====== fused Q/K/V/U projection: one launch, grid.z selects weight ========
// z=0: Q -> fp16 single; z=1: K -> fp16 hi/lo; z=2: V -> VT fp16 hi/lo;
// z=3: U -> silu -> f32
__global__ void __launch_bounds__(512, 1)
proj4(const __nv_bfloat16* __restrict__ Ah, const __nv_bfloat16* __restrict__ Al,
      const __nv_bfloat16* __restrict__ WThG, const __nv_bfloat16* __restrict__ WTlG,
      const float* __restrict__ bq, const float* __restrict__ bk,
      const float* __restrict__ bv, const float* __restrict__ bu,
      __half* __restrict__ Qs,
      __half* __restrict__ Kh, __half* __restrict__ Kl,
      __half* __restrict__ VTh, __half* __restrict__ VTl,
      float* __restrict__ Uf)
{
    extern __shared__ __align__(128) char sm[];
    uint32_t sb = smem_u32(sm);
    int tid  = threadIdx.x;
    int wid  = tid >> 5;
    int lane = tid & 31;
    int wm = wid & 1, wn = wid >> 1;
    int z  = blockIdx.z;
    int bm = blockIdx.y * 128, bn = blockIdx.x * 256;
    int m0 = wm * 64, n0 = wn * 32;
    const int K = 1024, N = 1024;

    const __nv_bfloat16* Bh = WThG + (size_t)z * W1M;
    const __nv_bfloat16* Bl = WTlG + (size_t)z * W1M;
    const float* bias = (z == 0) ? bq : (z == 1) ? bk : (z == 2) ? bv : bu;

    int laneRow = lane & 15;
    int laneK   = (lane >> 4) * 16;
    uint32_t xorA = (uint32_t)((laneRow & 7) << 4);

    float acc[4][4][4];
    #pragma unroll
    for (int i = 0; i < 4; i++)
        #pragma unroll
        for (int j = 0; j < 4; j++)
            #pragma unroll
            for (int q = 0; q < 4; q++) acc[i][j][q] = 0.f;

    const int NCH = K >> 6;

    auto load_stage = [&](int s, int chunk) {
        uint32_t st = sb + s * STAGE_B;
        int k0 = chunk * 64;
        #pragma unroll
        for (int it = 0; it < 2; it++) {
            int idx = tid + it * 512;
            int row = idx >> 3, c = idx & 7;
            uint32_t d = st + row * 128 + (uint32_t)((c * 16) ^ ((row & 7) << 4));
            size_t go = (size_t)(bm + row) * K + k0 + c * 8;
            cp16(d + SM_A_HI, Ah + go);
            cp16(d + SM_A_LO, Al + go);
        }
        #pragma unroll
        for (int it = 0; it < 4; it++) {
            int idx = tid + it * 512;
            int row = idx >> 3, c = idx & 7;
            uint32_t d = st + row * 128 + (uint32_t)((c * 16) ^ ((row & 7) << 4));
            size_t go = (size_t)(bn + row) * K + k0 + c * 8;
            cp16(d + SM_B_HI, Bh + go);
            cp16(d + SM_B_LO, Bl + go);
        }
    };

    load_stage(0, 0);
    cp_commit();

    for (int chunk = 0; chunk < NCH; chunk++) {
        int s = chunk & 1;
        if (chunk + 1 < NCH) {
            load_stage(s ^ 1, chunk + 1);
            cp_commit();
            cp_wait1();
        } else {
            cp_wait0();
        }
        __syncthreads();

        uint32_t st = sb + s * STAGE_B;
        #pragma unroll
        for (int ks = 0; ks < 4; ks++) {
            uint32_t kb = (uint32_t)((ks * 32 + laneK) ^ xorA);
            uint32_t ah[4][4], bh[2][4];
            #pragma unroll
            for (int i = 0; i < 4; i++)
                ldsm_x4(ah[i], st + SM_A_HI + (uint32_t)(m0 + i*16 + laneRow) * 128 + kb);
            #pragma unroll
            for (int p = 0; p < 2; p++)
                ldsm_x4(bh[p], st + SM_B_HI + (uint32_t)(n0 + p*16 + laneRow) * 128 + kb);
            #pragma unroll
            for (int i = 0; i < 4; i++)
                #pragma unroll
                for (int j = 0; j < 4; j++)
                    mma16816(acc[i][j], ah[i], bh[j>>1][j&1], bh[j>>1][2 + (j&1)]);
            {
                uint32_t al[4][4];
                #pragma unroll
                for (int i = 0; i < 4; i++)
                    ldsm_x4(al[i], st + SM_A_LO + (uint32_t)(m0 + i*16 + laneRow) * 128 + kb);
                #pragma unroll
                for (int i = 0; i < 4; i++)
                    #pragma unroll
                    for (int j = 0; j < 4; j++)
                        mma16816(acc[i][j], al[i], bh[j>>1][j&1], bh[j>>1][2 + (j&1)]);
            }
            {
                uint32_t bl[2][4];
                #pragma unroll
                for (int p = 0; p < 2; p++)
                    ldsm_x4(bl[p], st + SM_B_LO + (uint32_t)(n0 + p*16 + laneRow) * 128 + kb);
                #pragma unroll
                for (int i = 0; i < 4; i++)
                    #pragma unroll
                    for (int j = 0; j < 4; j++)
                        mma16816(acc[i][j], ah[i], bl[j>>1][j&1], bl[j>>1][2 + (j&1)]);
            }
        }
        __syncthreads();
    }

    int group = lane >> 2, tq = lane & 3;
    #pragma unroll
    for (int j = 0; j < 4; j++) {
        int n = bn + n0 + j*8 + tq*2;
        float bv0 = bias[n], bv1 = bias[n+1];
        #pragma unroll
        for (int i = 0; i < 4; i++) {
            int m = bm + m0 + i*16 + group;
            float v0 = acc[i][j][0] + bv0, v1 = acc[i][j][1] + bv1;
            float v2 = acc[i][j][2] + bv0, v3 = acc[i][j][3] + bv1;
            size_t off0 = (size_t)m * N + n;
            size_t off1 = (size_t)(m + 8) * N + n;
            if (z == 0) {
                *(__half2*)(Qs + off0) = __floats2half2_rn(v0, v1);
                *(__half2*)(Qs + off1) = __floats2half2_rn(v2, v3);
            } else if (z == 1) {
                __half h0,l0,h1,l1,h2,l2,h3,l3;
                split_f16(v0,h0,l0); split_f16(v1,h1,l1);
                split_f16(v2,h2,l2); split_f16(v3,h3,l3);
                *(__half2*)(Kh + off0) = __half2(h0, h1);
                *(__half2*)(Kl + off0) = __half2(l0, l1);
                *(__half2*)(Kh + off1) = __half2(h2, h3);
                *(__half2*)(Kl + off1) = __half2(l2, l3);
            } else if (z == 2) {
                __half h0,l0,h1,l1,h2,l2,h3,l3;
                split_f16(v0,h0,l0); split_f16(v1,h1,l1);
                split_f16(v2,h2,l2); split_f16(v3,h3,l3);
                int bi = m >> 11, tt = m & 2047;
                int hh = n >> 6,  dd = n & 63;
                size_t vb = ((size_t)((bi*16 + hh)*64 + dd)) * 2048 + tt;
                VTh[vb]        = h0;  VTl[vb]        = l0;
                VTh[vb + 2048] = h1;  VTl[vb + 2048] = l1;
                VTh[vb + 8]    = h2;  VTl[vb + 8]    = l2;
                VTh[vb + 2056] = h3;  VTl[vb + 2056] = l3;
            } else {
                *(float2*)(Uf + off0) = make_float2(siluf(v0), siluf(v1));
                *(float2*)(Uf + off1) = make_float2(siluf(v2), siluf(v3));
            }
        }
    }
}

// ====== w1 GEMM + swiglu fusion ============================================
#define W_A_HI  0
#define W_A_LO  16384
#define W_B1_HI 32768
#define W_B1_LO 49152
#define W_B2_HI 65536
#define W_B2_LO 81920
#define STAGE_W 98304

__global__ void __launch_bounds__(512, 1)
gemm_w1sg(const __nv_bfloat16* __restrict__ Ah, const __nv_bfloat16* __restrict__ Al,
          const __nv_bfloat16* __restrict__ Bh, const __nv_bfloat16* __restrict__ Bl,
          const float* __restrict__ b1,
          __nv_bfloat16* __restrict__ Yh, __nv_bfloat16* __restrict__ Yl)
{
    extern __shared__ __align__(128) char sm[];
    uint32_t sb = smem_u32(sm);
    int tid  = threadIdx.x;
    int wid  = tid >> 5;
    int lane = tid & 31;
    int wm = wid & 1, wn = wid >> 1;
    int bm = blockIdx.y * 128, bn = blockIdx.x * 128;
    int m0 = wm * 64, n0 = wn * 16;
    const int K = 1024;

    int laneRow = lane & 15;
    int laneK   = (lane >> 4) * 16;
    uint32_t xorA = (uint32_t)((laneRow & 7) << 4);

    float acc1[4][2][4], acc2[4][2][4];
    #pragma unroll
    for (int i = 0; i < 4; i++)
        #pragma unroll
        for (int j = 0; j < 2; j++)
            #pragma unroll
            for (int q = 0; q < 4; q++) { acc1[i][j][q] = 0.f; acc2[i][j][q] = 0.f; }

    const int NCH = K >> 6;

    auto load_stage = [&](int s, int chunk) {
        uint32_t st = sb + s * STAGE_W;
        int k0 = chunk * 64;
        #pragma unroll
        for (int it = 0; it < 2; it++) {
            int idx = tid + it * 512;
            int row = idx >> 3, c = idx & 7;
            uint32_t d = st + row * 128 + (uint32_t)((c * 16) ^ ((row & 7) << 4));
            size_t goA  = (size_t)(bm + row) * K + k0 + c * 8;
            size_t goB1 = (size_t)(bn + row) * K + k0 + c * 8;
            size_t goB2 = (size_t)(1024 + bn + row) * K + k0 + c * 8;
            cp16(d + W_A_HI,  Ah + goA);
            cp16(d + W_A_LO,  Al + goA);
            cp16(d + W_B1_HI, Bh + goB1);
            cp16(d + W_B1_LO, Bl + goB1);
            cp16(d + W_B2_HI, Bh + goB2);
            cp16(d + W_B2_LO, Bl + goB2);
        }
    };

    load_stage(0, 0);
    cp_commit();

    for (int chunk = 0; chunk < NCH; chunk++) {
        int s = chunk & 1;
        if (chunk + 1 < NCH) {
            load_stage(s ^ 1, chunk + 1);
            cp_commit();
            cp_wait1();
        } else {
            cp_wait0();
        }
        __syncthreads();

        uint32_t st = sb + s * STAGE_W;
        #pragma unroll
        for (int ks = 0; ks < 4; ks++) {
            uint32_t kb = (uint32_t)((ks * 32 + laneK) ^ xorA);
            uint32_t ah[4][4], b1h[4], b2h[4];
            #pragma unroll
            for (int i = 0; i < 4; i++)
                ldsm_x4(ah[i], st + W_A_HI + (uint32_t)(m0 + i*16 + laneRow) * 128 + kb);
            ldsm_x4(b1h, st + W_B1_HI + (uint32_t)(n0 + laneRow) * 128 + kb);
            ldsm_x4(b2h, st + W_B2_HI + (uint32_t)(n0 + laneRow) * 128 + kb);
            #pragma unroll
            for (int i = 0; i < 4; i++)
                #pragma unroll
                for (int j = 0; j < 2; j++) {
                    mma16816(acc1[i][j], ah[i], b1h[j], b1h[2 + j]);
                    mma16816(acc2[i][j], ah[i], b2h[j], b2h[2 + j]);
                }
            {
                uint32_t al[4][4];
                #pragma unroll
                for (int i = 0; i < 4; i++)
                    ldsm_x4(al[i], st + W_A_LO + (uint32_t)(m0 + i*16 + laneRow) * 128 + kb);
                #pragma unroll
                for (int i = 0; i < 4; i++)
                    #pragma unroll
                    for (int j = 0; j < 2; j++) {
                        mma16816(acc1[i][j], al[i], b1h[j], b1h[2 + j]);
                        mma16816(acc2[i][j], al[i], b2h[j], b2h[2 + j]);
                    }
            }
            {
                uint32_t b1l[4], b2l[4];
                ldsm_x4(b1l, st + W_B1_LO + (uint32_t)(n0 + laneRow) * 128 + kb);
                ldsm_x4(b2l, st + W_B2_LO + (uint32_t)(n0 + laneRow) * 128 + kb);
                #pragma unroll
                for (int i = 0; i < 4; i++)
                    #pragma unroll
                    for (int j = 0; j < 2; j++) {
                        mma16816(acc1[i][j], ah[i], b1l[j], b1l[2 + j]);
                        mma16816(acc2[i][j], ah[i], b2l[j], b2l[2 + j]);
                    }
            }
        }
        __syncthreads();
    }

    int group = lane >> 2, tq = lane & 3;
    #pragma unroll
    for (int j = 0; j < 2; j++) {
        int n = bn + n0 + j*8 + tq*2;
        float c10 = b1[n], c11 = b1[n+1];
        float c20 = b1[1024 + n], c21 = b1[1025 + n];
        #pragma unroll
        for (int i = 0; i < 4; i++) {
            int m = bm + m0 + i*16 + group;
            float y0 = siluf(acc1[i][j][0] + c10) * (acc2[i][j][0] + c20);
            float y1 = siluf(acc1[i][j][1] + c11) * (acc2[i][j][1] + c21);
            float y2 = siluf(acc1[i][j][2] + c10) * (acc2[i][j][2] + c20);
            float y3 = siluf(acc1[i][j][3] + c11) * (acc2[i][j][3] + c21);
            __nv_bfloat16 h0,l0,h1,l1,h2,l2,h3,l3;
            split_bf16(y0,h0,l0); split_bf16(y1,h1,l1);
            split_bf16(y2,h2,l2); split_bf16(y3,h3,l3);
            size_t off0 = (size_t)m * 1024 + n;
            size_t off1 = (size_t)(m + 8) * 1024 + n;
            *(__nv_bfloat162*)(Yh + off0) = __nv_bfloat162(h0, h1);
            *(__nv_bfloat162*)(Yl + off0) = __nv_bfloat162(l0, l1);
            *(__nv_bfloat162*)(Yh + off1) = __nv_bfloat162(h2, h3);
            *(__nv_bfloat162*)(Yl + off1) = __nv_bfloat162(l2, l3);
        }
    }
}

// ===== attention: fp16 2-pass, 16 warps, key-split intra-CTA, kv-split ======
// Q single fp16; K,V fp16 hi/lo. S packed single fp16. grid (16,16,4).
#define A_SQ  0u            // Q: 16KB
#define A_SK  16384u        // + s*32768 : KH, KL(+16384)
#define A_SVT 81920u        // + s*32768 : VTH, VTL(+16384)
#define A_PB  147456u       // + s*512
#define A_RED A_SK          // reduction area reuses K stage 0 (32KB)
#define ATT_SMEM 148480

__global__ void __launch_bounds__(512, 1)
attn_tc(const __half* __restrict__ Qs,
        const __half* __restrict__ Kh, const __half* __restrict__ Kl,
        const __half* __restrict__ VTh, const __half* __restrict__ VTl,
        const float* __restrict__ PB, float* __restrict__ P0, float* __restrict__ P1)
{
    extern __shared__ __align__(128) char sm[];
    uint32_t sb = smem_u32(sm);
    int tid  = threadIdx.x;
    int wid  = tid >> 5;
    int lane = tid & 31;
    int qt = blockIdx.x, h = blockIdx.y;
    int b  = blockIdx.z & 1;
    int kv = blockIdx.z >> 1;
    float* P = kv ? P1 : P0;
    int ktBeg = kv * (SEQ/256);          // 8 iters each
    int mw = wid & 7;
    int kw = wid >> 3;
    int m0 = mw * 16;
    int ntb = kw * 4;

    int laneRow = lane & 15;
    int laneK   = (lane >> 4) * 16;
    uint32_t xorA = (uint32_t)((laneRow & 7) << 4);
    int group = lane >> 2, tq = lane & 3;
    uint32_t rowbK = (uint32_t)laneRow * 128;
    uint32_t rowbV = (uint32_t)laneRow * 256;

    auto load_q = [&]() {
        #pragma unroll
        for (int it = 0; it < 2; it++) {
            int idx = tid + it * 512;   // 0..1023 covers 16KB
            int row = idx >> 3, c = idx & 7;
            uint32_t d = row * 128 + (uint32_t)((c * 16) ^ ((row & 7) << 4));
            size_t go = ((size_t)(b*SEQ + qt*128 + row)) * D_MODEL + h*64 + c*8;
            cp16(sb + A_SQ + d, Qs + go);
        }
    };
    auto load_kv = [&](int s, int kt) {
        uint32_t kbase = sb + A_SK + (uint32_t)s * 32768u;
        #pragma unroll
        for (int it = 0; it < 2; it++) {
            int idx = tid + it * 512;
            int row = idx >> 3, c = idx & 7;
            uint32_t d = row * 128 + (uint32_t)((c * 16) ^ ((row & 7) << 4));
            size_t go = ((size_t)(b*SEQ + kt*128 + row)) * D_MODEL + h*64 + c*8;
            cp16(kbase + d, Kh + go);
            cp16(kbase + 16384u + d, Kl + go);
        }
        uint32_t vbase = sb + A_SVT + (uint32_t)s * 32768u;
        #pragma unroll
        for (int it = 0; it < 2; it++) {
            int idx = tid + it * 512;
            int row = idx >> 4, c = idx & 15;
            uint32_t d = row * 256 + (uint32_t)((c * 16) ^ ((row & 7) << 4));
            size_t go = ((size_t)((b*16 + h)*64 + row)) * 2048 + kt*128 + c*8;
            cp16(vbase + d, VTh + go);
            cp16(vbase + 16384u + d, VTl + go);
        }
        if (tid < 128) {
            float v = PB[(size_t)(kt*128 + tid) * N_HEADS + h];
            *(float*)(sm + A_PB + (uint32_t)s * 512u + tid * 4) = v;
        }
    };

    float accO[8][4];
    #pragma unroll
    for (int f = 0; f < 8; f++)
        #pragma unroll
        for (int q = 0; q < 4; q++) accO[f][q] = 0.f;

    load_q(); cp_commit();
    load_kv(0, ktBeg); cp_commit();
    cp_wait1();
    __syncthreads();

    // hoist Q fragments (single fp16, loop-invariant)
    uint32_t qf[4][4];
    #pragma unroll
    for (int ks = 0; ks < 4; ks++) {
        uint32_t kb = (uint32_t)((ks * 32 + laneK) ^ xorA);
        ldsm_x4(qf[ks], sb + A_SQ + (uint32_t)m0 * 128 + rowbK + kb);
    }

    const int NIT = SEQ/256;   // 8
    for (int it = 0; it < NIT; it++) {
        int kt = ktBeg + it;
        int s = it & 1;
        if (it + 1 < NIT) {
            load_kv(s ^ 1, kt + 1);
            cp_commit();
            cp_wait1();
        } else {
            cp_wait0();
        }
        __syncthreads();

        uint32_t kst = sb + A_SK + (uint32_t)s * 32768u + (uint32_t)ntb * 2048u;
        uint32_t vst = sb + A_SVT + (uint32_t)s * 32768u;
        const float* pbs = (const float*)(sm + A_PB + (uint32_t)s * 512u);

        #pragma unroll
        for (int c = 0; c < 2; c++) {
            // ---- S = Q @ (Kh + Kl)^T : 2 passes ----
            float sc[4][4];
            #pragma unroll
            for (int f = 0; f < 4; f++)
                #pragma unroll
                for (int q = 0; q < 4; q++) sc[f][q] = 0.f;

            #pragma unroll
            for (int ks = 0; ks < 4; ks++) {
                uint32_t kb = (uint32_t)((ks * 32 + laneK) ^ xorA);
                #pragma unroll
                for (int t = 0; t < 2; t++) {
                    int nt = 2*c + t;
                    uint32_t kf[4];
                    ldsm_x4(kf, kst + (uint32_t)nt * 2048u + rowbK + kb);
                    mma16816h(sc[2*t],   qf[ks], kf[0], kf[2]);
                    mma16816h(sc[2*t+1], qf[ks], kf[1], kf[3]);
                    uint32_t klr[4];
                    ldsm_x4(klr, kst + 16384u + (uint32_t)nt * 2048u + rowbK + kb);
                    mma16816h(sc[2*t],   qf[ks], klr[0], klr[2]);
                    mma16816h(sc[2*t+1], qf[ks], klr[1], klr[3]);
                }
            }

            // ---- silu + single-fp16 pack ----
            uint32_t sf[2][4];
            #pragma unroll
            for (int t = 0; t < 2; t++) {
                int nt = 2*c + t;
                #pragma unroll
                for (int half = 0; half < 2; half++) {
                    int f = 2*t + half;
                    int tcol = ntb*16 + nt*16 + half*8 + tq*2;
                    float pb0 = pbs[tcol], pb1 = pbs[tcol + 1];
                    float w0 = siluf(sc[f][0] * 0.125f + pb0);
                    float w1 = siluf(sc[f][1] * 0.125f + pb1);
                    float w2 = siluf(sc[f][2] * 0.125f + pb0);
                    float w3 = siluf(sc[f][3] * 0.125f + pb1);
                    sf[t][half*2]     = pack_f16(w0, w1);
                    sf[t][half*2 + 1] = pack_f16(w2, w3);
                }
            }

            // ---- O += S @ (Vh + Vl) : 2 passes ----
            #pragma unroll
            for (int t = 0; t < 2; t++) {
                int gks = ntb + 2*c + t;
                uint32_t kb = (uint32_t)((gks * 32 + laneK) ^ xorA);
                #pragma unroll
                for (int dn = 0; dn < 4; dn++) {
                    uint32_t vf[4];
                    ldsm_x4(vf, vst + (uint32_t)dn * 4096u + rowbV + kb);
                    mma16816h(accO[2*dn],   sf[t], vf[0], vf[2]);
                    mma16816h(accO[2*dn+1], sf[t], vf[1], vf[3]);
                    uint32_t vl[4];
                    ldsm_x4(vl, vst + 16384u + (uint32_t)dn * 4096u + rowbV + kb);
                    mma16816h(accO[2*dn],   sf[t], vl[0], vl[2]);
                    mma16816h(accO[2*dn+1], sf[t], vl[1], vl[3]);
                }
            }
        }
        __syncthreads();
    }

    // ---- merge key-half partials within CTA, write fp32 partial to P ----
    if (kw == 1) {
        float* red = (float*)(sm + A_RED) + ((size_t)mw * 32 + lane) * 32;
        #pragma unroll
        for (int f = 0; f < 8; f++) {
            red[f*4+0] = accO[f][0]; red[f*4+1] = accO[f][1];
            red[f*4+2] = accO[f][2]; red[f*4+3] = accO[f][3];
        }
    }
    __syncthreads();
    if (kw == 0) {
        const float* red = (const float*)(sm + A_RED) + ((size_t)mw * 32 + lane) * 32;
        #pragma unroll
        for (int dn = 0; dn < 4; dn++) {
            #pragma unroll
            for (int half = 0; half < 2; half++) {
                int f = 2*dn + half;
                float o0 = accO[f][0] + red[f*4+0];
                float o1 = accO[f][1] + red[f*4+1];
                float o2 = accO[f][2] + red[f*4+2];
                float o3 = accO[f][3] + red[f*4+3];
                int col = h*64 + dn*16 + half*8 + tq*2;
                int row = b*SEQ + qt*128 + m0 + group;
                *(float2*)(P + (size_t)row * D_MODEL + col) = make_float2(o0, o1);
                *(float2*)(P + (size_t)(row + 8) * D_MODEL + col) = make_float2(o2, o3);
            }
        }
    }
}

// ---------------- launch ----------------------------------------------------
extern "C" void kernel_launch(void* const* d_in, const int* in_sizes, int n_in,
                              void* d_out, int out_size)
{
    const float* x      = (const float*)d_in[0];
    const float* pb     = (const float*)d_in[2];
    const float* wq     = (const float*)d_in[3];
    const float* bq     = (const float*)d_in[4];
    const float* wk     = (const float*)d_in[5];
    const float* bk_    = (const float*)d_in[6];
    const float* wv     = (const float*)d_in[7];
    const float* bv     = (const float*)d_in[8];
    const float* wu     = (const float*)d_in[9];
    const float* bu     = (const float*)d_in[10];
    const float* g_ams  = (const float*)d_in[11];
    const float* w0     = (const float*)d_in[12];
    const float* b0     = (const float*)d_in[13];
    const float* w1     = (const float*)d_in[14];
    const float* b1     = (const float*)d_in[15];
    const float* w2     = (const float*)d_in[16];
    const float* b2     = (const float*)d_in[17];
    const float* g_mffn = (const float*)d_in[18];
    float* out = (float*)d_out;

    float *Qf, *Kf, *Vf, *Uf, *AOf, *P2f, *Of;
    __nv_bfloat16 *A1h, *A1l, *A2h, *A2l, *WTh, *WTl;
    cudaGetSymbolAddress((void**)&Qf,  g_Q);
    cudaGetSymbolAddress((void**)&Kf,  g_K);
    cudaGetSymbolAddress((void**)&Vf,  g_V);
    cudaGetSymbolAddress((void**)&Uf,  g_U);
    cudaGetSymbolAddress((void**)&AOf, g_AO);
    cudaGetSymbolAddress((void**)&P2f, g_P2);
    cudaGetSymbolAddress((void**)&Of,  g_O);
    cudaGetSymbolAddress((void**)&A1h, g_A1h);
    cudaGetSymbolAddress((void**)&A1l, g_A1l);
    cudaGetSymbolAddress((void**)&A2h, g_A2h);
    cudaGetSymbolAddress((void**)&A2l, g_A2l);
    cudaGetSymbolAddress((void**)&WTh, g_WTh);
    cudaGetSymbolAddress((void**)&WTl, g_WTl);

    const size_t NEL = (size_t)M_ROWS * D_MODEL;
    __half *Qsb = (__half*)Qf;
    __half *Khb = (__half*)Kf,  *Klb = Khb + NEL;
    __half *VTh = (__half*)Vf,  *VTl = VTh + NEL;

    __nv_bfloat16 *T0_h = WTh + (size_t)4*W1M, *T0_l = WTl + (size_t)4*W1M;
    __nv_bfloat16 *T2_h = WTh + (size_t)5*W1M, *T2_l = WTl + (size_t)5*W1M;
    __nv_bfloat16 *T1_h = WTh + (size_t)6*W1M, *T1_l = WTl + (size_t)6*W1M;

    const int GSM = 2 * STAGE_B;
    cudaFuncSetAttribute(gemm_res,  cudaFuncAttributeMaxDynamicSharedMemorySize, GSM);
    cudaFuncSetAttribute(proj4,     cudaFuncAttributeMaxDynamicSharedMemorySize, GSM);
    cudaFuncSetAttribute(gemm_w1sg, cudaFuncAttributeMaxDynamicSharedMemorySize, 2*STAGE_W);
    cudaFuncSetAttribute(attn_tc,   cudaFuncAttributeMaxDynamicSharedMemorySize, ATT_SMEM);

    wtsplit_all<<<8192, dim3(32, 8)>>>(wq, wk, wv, wu, w0, w2, w1, WTh, WTl);
    rmsnorm_tc<<<M_ROWS, 256>>>(x, g_ams, A1h, A1l);
    proj4<<<dim3(4, 32, 4), 512, GSM>>>(A1h, A1l, WTh, WTl, bq, bk_, bv, bu,
                                        Qsb, Khb, Klb, VTh, VTl, Uf);
    attn_tc<<<dim3(SEQ/128, N_HEADS, BATCH*2), 512, ATT_SMEM>>>(Qsb, Khb, Klb, VTh, VTl, pb, AOf, P2f);
    merge_ams<<<M_ROWS, 256>>>(AOf, P2f, g_ams, Uf, A2h, A2l);
    gemm_res<<<dim3(4, 32), 512, GSM>>>(A2h, A2l, T0_h, T0_l, b0, x, Of, M_ROWS, 1024, 1024);
    rmsnorm_tc<<<M_ROWS, 256>>>(Of, g_mffn, A1h, A1l);
    gemm_w1sg<<<dim3(8, 32), 512, 2*STAGE_W>>>(A1h, A1l, T1_h, T1_l, b1, A2h, A2l);
    gemm_res<<<dim3(4, 32), 512, GSM>>>(A2h, A2l, T2_h, T2_l, b2, Of, out, M_ROWS, 1024, 1024);
}

// round 14
// speedup vs baseline: 1.5782x; 1.2481x over previous
#include <cuda_runtime.h>
#include <cuda_bf16.h>
#include <cuda_fp16.h>
#include <cstdint>
#include <math.h>

#define D_MODEL 1024
#define N_HEADS 16
#define DH      64
#define BATCH   2
#define SEQ     2048
#define M_ROWS  (BATCH*SEQ)   // 4096

// ---------------- scratch (static device globals; no allocations) ----------
__device__ float g_Q  [M_ROWS*D_MODEL];   // aliased: Q fp16 (single)
__device__ float g_K  [M_ROWS*D_MODEL];   // aliased: Kh/Kl fp16
__device__ float g_V  [M_ROWS*D_MODEL];   // aliased: VTh/VTl fp16 (transposed per head)
__device__ float g_U  [M_ROWS*D_MODEL];
__device__ float g_AO [M_ROWS*D_MODEL];   // attention partial 0
__device__ float g_P2 [M_ROWS*D_MODEL];   // attention partial 1
__device__ float g_O  [M_ROWS*D_MODEL];

__device__ __half g_A1[M_ROWS*D_MODEL];   // activation fp16 (single)
__device__ __half g_A2[M_ROWS*D_MODEL];

__device__ __half g_WTh[8*1024*1024];     // weights fp16 hi/lo, [N,K]
__device__ __half g_WTl[8*1024*1024];

#define W1M (1024*1024)

__device__ __forceinline__ float siluf(float z) {
    return z * (1.0f / (1.0f + __expf(-z)));
}

__device__ __forceinline__ uint32_t smem_u32(const void* p) {
    uint32_t a;
    asm("{ .reg .u64 t; cvta.to.shared.u64 t, %1; cvt.u32.u64 %0, t; }" : "=r"(a) : "l"(p));
    return a;
}

__device__ __forceinline__ void ldsm_x4(uint32_t* r, uint32_t a) {
    asm volatile("ldmatrix.sync.aligned.m8n8.x4.shared.b16 {%0,%1,%2,%3}, [%4];"
                 : "=r"(r[0]), "=r"(r[1]), "=r"(r[2]), "=r"(r[3]) : "r"(a));
}

__device__ __forceinline__ void mma16816h(float* c, const uint32_t* a, uint32_t b0, uint32_t b1) {
    asm volatile("mma.sync.aligned.m16n8k16.row.col.f32.f16.f16.f32 "
                 "{%0,%1,%2,%3}, {%4,%5,%6,%7}, {%8,%9}, {%0,%1,%2,%3};"
                 : "+f"(c[0]), "+f"(c[1]), "+f"(c[2]), "+f"(c[3])
                 : "r"(a[0]), "r"(a[1]), "r"(a[2]), "r"(a[3]), "r"(b0), "r"(b1));
}

__device__ __forceinline__ void cp16(uint32_t dst, const void* src) {
    asm volatile("cp.async.cg.shared.global [%0], [%1], 16;" :: "r"(dst), "l"(src));
}
__device__ __forceinline__ void cp_commit() { asm volatile("cp.async.commit_group;"); }
__device__ __forceinline__ void cp_wait1()  { asm volatile("cp.async.wait_group 1;"); }
__device__ __forceinline__ void cp_wait0()  { asm volatile("cp.async.wait_group 0;"); }

__device__ __forceinline__ void split_f16(float v, __half& h, __half& l) {
    h = __float2half_rn(v);
    l = __float2half_rn(v - __half2float(h));
}

__device__ __forceinline__ uint32_t pack_f16(float a, float b) {
    __half2 t = __floats2half2_rn(a, b);
    return *(uint32_t*)&t;
}

// ======= batched weight transpose + fp16 split (all 7 weights, 1 launch) ====
__global__ void __launch_bounds__(256)
wtsplit_all(const float* __restrict__ wq, const float* __restrict__ wk,
            const float* __restrict__ wv, const float* __restrict__ wu,
            const float* __restrict__ w0, const float* __restrict__ w2,
            const float* __restrict__ w1,
            __half* __restrict__ WTh, __half* __restrict__ WTl)
{
    __shared__ float t[32][33];
    int bid = blockIdx.x;
    const float* W; __half *Th, *Tl;
    int N, nx, ky;
    if (bid < 6144) {
        int w = bid >> 10, local = bid & 1023;
        switch (w) {
            case 0: W = wq; break; case 1: W = wk; break;
            case 2: W = wv; break; case 3: W = wu; break;
            case 4: W = w0; break; default: W = w2; break;
        }
        Th = WTh + (size_t)w * W1M; Tl = WTl + (size_t)w * W1M;
        N = 1024; nx = local & 31; ky = local >> 5;
    } else {
        int local = bid - 6144;
        W = w1; Th = WTh + (size_t)6 * W1M; Tl = WTl + (size_t)6 * W1M;
        N = 2048; nx = local & 63; ky = local >> 6;
    }
    const int K = 1024;
    int tx = threadIdx.x, ty = threadIdx.y;
    int n0 = nx * 32, k0 = ky * 32;
    #pragma unroll
    for (int i = 0; i < 4; i++)
        t[ty + i*8][tx] = W[(size_t)(k0 + ty + i*8) * N + n0 + tx];
    __syncthreads();
    #pragma unroll
    for (int i = 0; i < 4; i++) {
        float v = t[tx][ty + i*8];
        __half hi, lo;
        split_f16(v, hi, lo);
        size_t off = (size_t)(n0 + ty + i*8) * K + k0 + tx;
        Th[off] = hi; Tl[off] = lo;
    }
}

// ---------------- RMSNorm -> fp16 single ------------------------------------
__global__ void __launch_bounds__(256)
rmsnorm_tc(const float* __restrict__ X, const float* __restrict__ g,
           __half* __restrict__ Y)
{
    int r = blockIdx.x, t = threadIdx.x;
    float4 v = ((const float4*)(X + (size_t)r * D_MODEL))[t];
    float ss = v.x*v.x + v.y*v.y + v.z*v.z + v.w*v.w;
    #pragma unroll
    for (int o = 16; o; o >>= 1) ss += __shfl_xor_sync(0xffffffffu, ss, o);
    __shared__ float ws[8]; __shared__ float s_inv;
    if ((t & 31) == 0) ws[t >> 5] = ss;
    __syncthreads();
    if (t == 0) {
        float tot = 0.f;
        #pragma unroll
        for (int i = 0; i < 8; i++) tot += ws[i];
        s_inv = rsqrtf(tot * (1.0f / D_MODEL) + 1e-8f);
    }
    __syncthreads();
    float iv = s_inv;
    float4 gv = ((const float4*)g)[t];
    size_t base = (size_t)r * D_MODEL + t*4;
    *(__half2*)(Y + base)     = __floats2half2_rn(v.x*iv*gv.x, v.y*iv*gv.y);
    *(__half2*)(Y + base + 2) = __floats2half2_rn(v.z*iv*gv.z, v.w*iv*gv.w);
}

// -------- merge attention partials + ams: rmsnorm(P0+P1, g) * U -> fp16 -----
__global__ void __launch_bounds__(256)
merge_ams(const float* __restrict__ P0, const float* __restrict__ P1,
          const float* __restrict__ g, const float* __restrict__ U,
          __half* __restrict__ Y)
{
    int r = blockIdx.x, t = threadIdx.x;
    float4 a = ((const float4*)(P0 + (size_t)r * D_MODEL))[t];
    float4 bb = ((const float4*)(P1 + (size_t)r * D_MODEL))[t];
    float4 v;
    v.x = a.x + bb.x; v.y = a.y + bb.y; v.z = a.z + bb.z; v.w = a.w + bb.w;
    float ss = v.x*v.x + v.y*v.y + v.z*v.z + v.w*v.w;
    #pragma unroll
    for (int o = 16; o; o >>= 1) ss += __shfl_xor_sync(0xffffffffu, ss, o);
    __shared__ float ws[8]; __shared__ float s_inv;
    if ((t & 31) == 0) ws[t >> 5] = ss;
    __syncthreads();
    if (t == 0) {
        float tot = 0.f;
        #pragma unroll
        for (int i = 0; i < 8; i++) tot += ws[i];
        s_inv = rsqrtf(tot * (1.0f / D_MODEL) + 1e-8f);
    }
    __syncthreads();
    float iv = s_inv;
    float4 gv = ((const float4*)g)[t];
    float4 uv = ((const float4*)(U + (size_t)r * D_MODEL))[t];
    size_t base = (size_t)r * D_MODEL + t*4;
    *(__half2*)(Y + base)     = __floats2half2_rn(v.x*iv*gv.x*uv.x, v.y*iv*gv.y*uv.y);
    *(__half2*)(Y + base + 2) = __floats2half2_rn(v.z*iv*gv.z*uv.z, v.w*iv*gv.w*uv.w);
}

// ===== fp16 2-pass HMMA GEMM (EPI 2): C = A@(Bh+Bl)^T + bias + R ===========
// A: [M,K] fp16 single. B: [N,K] fp16 hi/lo. BM=128 BN=256 BK=64.
#define SM_A    0
#define SM_B_HI 16384
#define SM_B_LO 49152
#define STAGE_B 81920

__global__ void __launch_bounds__(512, 1)
gemm_res(const __half* __restrict__ A,
         const __half* __restrict__ Bh, const __half* __restrict__ Bl,
         const float* __restrict__ bias, const float* __restrict__ R,
         float* __restrict__ C, int M, int N, int K)
{
    extern __shared__ __align__(128) char sm[];
    uint32_t sb = smem_u32(sm);
    int tid  = threadIdx.x;
    int wid  = tid >> 5;
    int lane = tid & 31;
    int wm = wid & 1, wn = wid >> 1;
    int bm = blockIdx.y * 128, bn = blockIdx.x * 256;
    int m0 = wm * 64, n0 = wn * 32;

    int laneRow = lane & 15;
    int laneK   = (lane >> 4) * 16;
    uint32_t xorA = (uint32_t)((laneRow & 7) << 4);

    float acc[4][4][4];
    #pragma unroll
    for (int i = 0; i < 4; i++)
        #pragma unroll
        for (int j = 0; j < 4; j++)
            #pragma unroll
            for (int q = 0; q < 4; q++) acc[i][j][q] = 0.f;

    const int NCH = K >> 6;

    auto load_stage = [&](int s, int chunk) {
        uint32_t st = sb + s * STAGE_B;
        int k0 = chunk * 64;
        #pragma unroll
        for (int it = 0; it < 2; it++) {
            int idx = tid + it * 512;
            int row = idx >> 3, c = idx & 7;
            uint32_t d = st + row * 128 + (uint32_t)((c * 16) ^ ((row & 7) << 4));
            size_t go = (size_t)(bm + row) * K + k0 + c * 8;
            cp16(d + SM_A, A + go);
        }
        #pragma unroll
        for (int it = 0; it < 4; it++) {
            int idx = tid + it * 512;
            int row = idx >> 3, c = idx & 7;
            uint32_t d = st + row * 128 + (uint32_t)((c * 16) ^ ((row & 7) << 4));
            size_t go = (size_t)(bn + row) * K + k0 + c * 8;
            cp16(d + SM_B_HI, Bh + go);
            cp16(d + SM_B_LO, Bl + go);
        }
    };

    load_stage(0, 0);
    cp_commit();

    for (int chunk = 0; chunk < NCH; chunk++) {
        int s = chunk & 1;
        if (chunk + 1 < NCH) {
            load_stage(s ^ 1, chunk + 1);
            cp_commit();
            cp_wait1();
        } else {
            cp_wait0();
        }
        __syncthreads();

        uint32_t st = sb + s * STAGE_B;
        #pragma unroll
        for (int ks = 0; ks < 4; ks++) {
            uint32_t kb = (uint32_t)((ks * 32 + laneK) ^ xorA);
            uint32_t a[4][4], bh[2][4];
            #pragma unroll
            for (int i = 0; i < 4; i++)
                ldsm_x4(a[i], st + SM_A + (uint32_t)(m0 + i*16 + laneRow) * 128 + kb);
            #pragma unroll
            for (int p = 0; p < 2; p++)
                ldsm_x4(bh[p], st + SM_B_HI + (uint32_t)(n0 + p*16 + laneRow) * 128 + kb);
            #pragma unroll
            for (int i = 0; i < 4; i++)
                #pragma unroll
                for (int j = 0; j < 4; j++)
                    mma16816h(acc[i][j], a[i], bh[j>>1][j&1], bh[j>>1][2 + (j&1)]);
            {
                uint32_t bl[2][4];
                #pragma unroll
                for (int p = 0; p < 2; p++)
                    ldsm_x4(bl[p], st + SM_B_LO + (uint32_t)(n0 + p*16 + laneRow) * 128 + kb);
                #pragma unroll
                for (int i = 0; i < 4; i++)
                    #pragma unroll
                    for (int j = 0; j < 4; j++)
                        mma16816h(acc[i][j], a[i], bl[j>>1][j&1], bl[j>>1][2 + (j&1)]);
            }
        }
        __syncthreads();
    }

    int group = lane >> 2, tq = lane & 3;
    #pragma unroll
    for (int j = 0; j < 4; j++) {
        int n = bn + n0 + j*8 + tq*2;
        float bv0 = bias[n], bv1 = bias[n+1];
        #pragma unroll
        for (int i = 0; i < 4; i++) {
            int m = bm + m0 + i*16 + group;
            size_t off0 = (size_t)m * N + n;
            size_t off1 = (size_t)(m + 8) * N + n;
            float2 r0 = *(const float2*)(R + off0);
            float2 r1 = *(const float2*)(R + off1);
            *(float2*)(C + off0) = make_float2(acc[i][j][0] + bv0 + r0.x, acc[i][j][1] + bv1 + r0.y);
            *(float2*)(C + off1) = make_float2(acc[i][j][2] + bv0 + r1.x, acc[i][j][3] + bv1 + r1.y);
        }
    }
}

// ====== fused Q/K/V/U projection: fp16 2-pass, grid.z selects weight =======
__global__ void __launch_bounds__(512, 1)
proj4(const __half* __restrict__ A,
      const __half* __restrict__ WThG, const __half* __restrict__ WTlG,
      const float* __restrict__ bq, const float* __restrict__ bk,
      const float* __restrict__ bv, const float* __restrict__ bu,
      __half* __restrict__ Qs,
      __half* __restrict__ Kh, __half* __restrict__ Kl,
      __half* __restrict__ VTh, __half* __restrict__ VTl,
      float* __restrict__ Uf)
{
    extern __shared__ __align__(128) char sm[];
    uint32_t sb = smem_u32(sm);
    int tid  = threadIdx.x;
    int wid  = tid >> 5;
    int lane = tid & 31;
    int wm = wid & 1, wn = wid >> 1;
    int z  = blockIdx.z;
    int bm = blockIdx.y * 128, bn = blockIdx.x * 256;
    int m0 = wm * 64, n0 = wn * 32;
    const int K = 1024, N = 1024;

    const __half* Bh = WThG + (size_t)z * W1M;
    const __half* Bl = WTlG + (size_t)z * W1M;
    const float* bias = (z == 0) ? bq : (z == 1) ? bk : (z == 2) ? bv : bu;

    int laneRow = lane & 15;
    int laneK   = (lane >> 4) * 16;
    uint32_t xorA = (uint32_t)((laneRow & 7) << 4);

    float acc[4][4][4];
    #pragma unroll
    for (int i = 0; i < 4; i++)
        #pragma unroll
        for (int j = 0; j < 4; j++)
            #pragma unroll
            for (int q = 0; q < 4; q++) acc[i][j][q] = 0.f;

    const int NCH = K >> 6;

    auto load_stage = [&](int s, int chunk) {
        uint32_t st = sb + s * STAGE_B;
        int k0 = chunk * 64;
        #pragma unroll
        for (int it = 0; it < 2; it++) {
            int idx = tid + it * 512;
            int row = idx >> 3, c = idx & 7;
            uint32_t d = st + row * 128 + (uint32_t)((c * 16) ^ ((row & 7) << 4));
            size_t go = (size_t)(bm + row) * K + k0 + c * 8;
            cp16(d + SM_A, A + go);
        }
        #pragma unroll
        for (int it = 0; it < 4; it++) {
            int idx = tid + it * 512;
            int row = idx >> 3, c = idx & 7;
            uint32_t d = st + row * 128 + (uint32_t)((c * 16) ^ ((row & 7) << 4));
            size_t go = (size_t)(bn + row) * K + k0 + c * 8;
            cp16(d + SM_B_HI, Bh + go);
            cp16(d + SM_B_LO, Bl + go);
        }
    };

    load_stage(0, 0);
    cp_commit();

    for (int chunk = 0; chunk < NCH; chunk++) {
        int s = chunk & 1;
        if (chunk + 1 < NCH) {
            load_stage(s ^ 1, chunk + 1);
            cp_commit();
            cp_wait1();
        } else {
            cp_wait0();
        }
        __syncthreads();

        uint32_t st = sb + s * STAGE_B;
        #pragma unroll
        for (int ks = 0; ks < 4; ks++) {
            uint32_t kb = (uint32_t)((ks * 32 + laneK) ^ xorA);
            uint32_t a[4][4], bh[2][4];
            #pragma unroll
            for (int i = 0; i < 4; i++)
                ldsm_x4(a[i], st + SM_A + (uint32_t)(m0 + i*16 + laneRow) * 128 + kb);
            #pragma unroll
            for (int p = 0; p < 2; p++)
                ldsm_x4(bh[p], st + SM_B_HI + (uint32_t)(n0 + p*16 + laneRow) * 128 + kb);
            #pragma unroll
            for (int i = 0; i < 4; i++)
                #pragma unroll
                for (int j = 0; j < 4; j++)
                    mma16816h(acc[i][j], a[i], bh[j>>1][j&1], bh[j>>1][2 + (j&1)]);
            {
                uint32_t bl[2][4];
                #pragma unroll
                for (int p = 0; p < 2; p++)
                    ldsm_x4(bl[p], st + SM_B_LO + (uint32_t)(n0 + p*16 + laneRow) * 128 + kb);
                #pragma unroll
                for (int i = 0; i < 4; i++)
                    #pragma unroll
                    for (int j = 0; j < 4; j++)
                        mma16816h(acc[i][j], a[i], bl[j>>1][j&1], bl[j>>1][2 + (j&1)]);
            }
        }
        __syncthreads();
    }

    int group = lane >> 2, tq = lane & 3;
    #pragma unroll
    for (int j = 0; j < 4; j++) {
        int n = bn + n0 + j*8 + tq*2;
        float bv0 = bias[n], bv1 = bias[n+1];
        #pragma unroll
        for (int i = 0; i < 4; i++) {
            int m = bm + m0 + i*16 + group;
            float v0 = acc[i][j][0] + bv0, v1 = acc[i][j][1] + bv1;
            float v2 = acc[i][j][2] + bv0, v3 = acc[i][j][3] + bv1;
            size_t off0 = (size_t)m * N + n;
            size_t off1 = (size_t)(m + 8) * N + n;
            if (z == 0) {
                *(__half2*)(Qs + off0) = __floats2half2_rn(v0, v1);
                *(__half2*)(Qs + off1) = __floats2half2_rn(v2, v3);
            } else if (z == 1) {
                __half h0,l0,h1,l1,h2,l2,h3,l3;
                split_f16(v0,h0,l0); split_f16(v1,h1,l1);
                split_f16(v2,h2,l2); split_f16(v3,h3,l3);
                *(__half2*)(Kh + off0) = __half2(h0, h1);
                *(__half2*)(Kl + off0) = __half2(l0, l1);
                *(__half2*)(Kh + off1) = __half2(h2, h3);
                *(__half2*)(Kl + off1) = __half2(l2, l3);
            } else if (z == 2) {
                __half h0,l0,h1,l1,h2,l2,h3,l3;
                split_f16(v0,h0,l0); split_f16(v1,h1,l1);
                split_f16(v2,h2,l2); split_f16(v3,h3,l3);
                int bi = m >> 11, tt = m & 2047;
                int hh = n >> 6,  dd = n & 63;
                size_t vb = ((size_t)((bi*16 + hh)*64 + dd)) * 2048 + tt;
                VTh[vb]        = h0;  VTl[vb]        = l0;
                VTh[vb + 2048] = h1;  VTl[vb + 2048] = l1;
                VTh[vb + 8]    = h2;  VTl[vb + 8]    = l2;
                VTh[vb + 2056] = h3;  VTl[vb + 2056] = l3;
            } else {
                *(float2*)(Uf + off0) = make_float2(siluf(v0), siluf(v1));
                *(float2*)(Uf + off1) = make_float2(siluf(v2), siluf(v3));
            }
        }
    }
}

// ====== w1 GEMM + swiglu fusion: fp16 2-pass ================================
#define W_A    0
#define W_B1_HI 16384
#define W_B1_LO 32768
#define W_B2_HI 49152
#define W_B2_LO 65536
#define STAGE_W 81920

__global__ void __launch_bounds__(512, 1)
gemm_w1sg(const __half* __restrict__ A,
          const __half* __restrict__ Bh, const __half* __restrict__ Bl,
          const float* __restrict__ b1, __half* __restrict__ Y)
{
    extern __shared__ __align__(128) char sm[];
    uint32_t sb = smem_u32(sm);
    int tid  = threadIdx.x;
    int wid  = tid >> 5;
    int lane = tid & 31;
    int wm = wid & 1, wn = wid >> 1;
    int bm = blockIdx.y * 128, bn = blockIdx.x * 128;
    int m0 = wm * 64, n0 = wn * 16;
    const int K = 1024;

    int laneRow = lane & 15;
    int laneK   = (lane >> 4) * 16;
    uint32_t xorA = (uint32_t)((laneRow & 7) << 4);

    float acc1[4][2][4], acc2[4][2][4];
    #pragma unroll
    for (int i = 0; i < 4; i++)
        #pragma unroll
        for (int j = 0; j < 2; j++)
            #pragma unroll
            for (int q = 0; q < 4; q++) { acc1[i][j][q] = 0.f; acc2[i][j][q] = 0.f; }

    const int NCH = K >> 6;

    auto load_stage = [&](int s, int chunk) {
        uint32_t st = sb + s * STAGE_W;
        int k0 = chunk * 64;
        #pragma unroll
        for (int it = 0; it < 2; it++) {
            int idx = tid + it * 512;
            int row = idx >> 3, c = idx & 7;
            uint32_t d = st + row * 128 + (uint32_t)((c * 16) ^ ((row & 7) << 4));
            size_t goA  = (size_t)(bm + row) * K + k0 + c * 8;
            size_t goB1 = (size_t)(bn + row) * K + k0 + c * 8;
            size_t goB2 = (size_t)(1024 + bn + row) * K + k0 + c * 8;
            cp16(d + W_A,     A + goA);
            cp16(d + W_B1_HI, Bh + goB1);
            cp16(d + W_B1_LO, Bl + goB1);
            cp16(d + W_B2_HI, Bh + goB2);
            cp16(d + W_B2_LO, Bl + goB2);
        }
    };

    load_stage(0, 0);
    cp_commit();

    for (int chunk = 0; chunk < NCH; chunk++) {
        int s = chunk & 1;
        if (chunk + 1 < NCH) {
            load_stage(s ^ 1, chunk + 1);
            cp_commit();
            cp_wait1();
        } else {
            cp_wait0();
        }
        __syncthreads();

        uint32_t st = sb + s * STAGE_W;
        #pragma unroll
        for (int ks = 0; ks < 4; ks++) {
            uint32_t kb = (uint32_t)((ks * 32 + laneK) ^ xorA);
            uint32_t a[4][4], b1h[4], b2h[4];
            #pragma unroll
            for (int i = 0; i < 4; i++)
                ldsm_x4(a[i], st + W_A + (uint32_t)(m0 + i*16 + laneRow) * 128 + kb);
            ldsm_x4(b1h, st + W_B1_HI + (uint32_t)(n0 + laneRow) * 128 + kb);
            ldsm_x4(b2h, st + W_B2_HI + (uint32_t)(n0 + laneRow) * 128 + kb);
            #pragma unroll
            for (int i = 0; i < 4; i++)
                #pragma unroll
                for (int j = 0; j < 2; j++) {
                    mma16816h(acc1[i][j], a[i], b1h[j], b1h[2 + j]);
                    mma16816h(acc2[i][j], a[i], b2h[j], b2h[2 + j]);
                }
            {
                uint32_t b1l[4], b2l[4];
                ldsm_x4(b1l, st + W_B1_LO + (uint32_t)(n0 + laneRow) * 128 + kb);
                ldsm_x4(b2l, st + W_B2_LO + (uint32_t)(n0 + laneRow) * 128 + kb);
                #pragma unroll
                for (int i = 0; i < 4; i++)
                    #pragma unroll
                    for (int j = 0; j < 2; j++) {
                        mma16816h(acc1[i][j], a[i], b1l[j], b1l[2 + j]);
                        mma16816h(acc2[i][j], a[i], b2l[j], b2l[2 + j]);
                    }
            }
        }
        __syncthreads();
    }

    int group = lane >> 2, tq = lane & 3;
    #pragma unroll
    for (int j = 0; j < 2; j++) {
        int n = bn + n0 + j*8 + tq*2;
        float c10 = b1[n], c11 = b1[n+1];
        float c20 = b1[1024 + n], c21 = b1[1025 + n];
        #pragma unroll
        for (int i = 0; i < 4; i++) {
            int m = bm + m0 + i*16 + group;
            float y0 = siluf(acc1[i][j][0] + c10) * (acc2[i][j][0] + c20);
            float y1 = siluf(acc1[i][j][1] + c11) * (acc2[i][j][1] + c21);
            float y2 = siluf(acc1[i][j][2] + c10) * (acc2[i][j][2] + c20);
            float y3 = siluf(acc1[i][j][3] + c11) * (acc2[i][j][3] + c21);
            size_t off0 = (size_t)m * 1024 + n;
            size_t off1 = (size_t)(m + 8) * 1024 + n;
            *(__half2*)(Y + off0) = __floats2half2_rn(y0, y1);
            *(__half2*)(Y + off1) = __floats2half2_rn(y2, y3);
        }
    }
}

// ===== attention: fp16 2-pass, 16 warps, key-split intra-CTA, kv-split ======
#define A_SQ  0u
#define A_SK  16384u
#define A_SVT 81920u
#define A_PB  147456u
#define A_RED A_SK
#define ATT_SMEM 148480

__global__ void __launch_bounds__(512, 1)
attn_tc(const __half* __restrict__ Qs,
        const __half* __restrict__ Kh, const __half* __restrict__ Kl,
        const __half* __restrict__ VTh, const __half* __restrict__ VTl,
        const float* __restrict__ PB, float* __restrict__ P0, float* __restrict__ P1)
{
    extern __shared__ __align__(128) char sm[];
    uint32_t sb = smem_u32(sm);
    int tid  = threadIdx.x;
    int wid  = tid >> 5;
    int lane = tid & 31;
    int qt = blockIdx.x, h = blockIdx.y;
    int b  = blockIdx.z & 1;
    int kv = blockIdx.z >> 1;
    float* P = kv ? P1 : P0;
    int ktBeg = kv * (SEQ/256);
    int mw = wid & 7;
    int kw = wid >> 3;
    int m0 = mw * 16;
    int ntb = kw * 4;

    int laneRow = lane & 15;
    int laneK   = (lane >> 4) * 16;
    uint32_t xorA = (uint32_t)((laneRow & 7) << 4);
    int group = lane >> 2, tq = lane & 3;
    uint32_t rowbK = (uint32_t)laneRow * 128;
    uint32_t rowbV = (uint32_t)laneRow * 256;

    auto load_q = [&]() {
        #pragma unroll
        for (int it = 0; it < 2; it++) {
            int idx = tid + it * 512;
            int row = idx >> 3, c = idx & 7;
            uint32_t d = row * 128 + (uint32_t)((c * 16) ^ ((row & 7) << 4));
            size_t go = ((size_t)(b*SEQ + qt*128 + row)) * D_MODEL + h*64 + c*8;
            cp16(sb + A_SQ + d, Qs + go);
        }
    };
    auto load_kv = [&](int s, int kt) {
        uint32_t kbase = sb + A_SK + (uint32_t)s * 32768u;
        #pragma unroll
        for (int it = 0; it < 2; it++) {
            int idx = tid + it * 512;
            int row = idx >> 3, c = idx & 7;
            uint32_t d = row * 128 + (uint32_t)((c * 16) ^ ((row & 7) << 4));
            size_t go = ((size_t)(b*SEQ + kt*128 + row)) * D_MODEL + h*64 + c*8;
            cp16(kbase + d, Kh + go);
            cp16(kbase + 16384u + d, Kl + go);
        }
        uint32_t vbase = sb + A_SVT + (uint32_t)s * 32768u;
        #pragma unroll
        for (int it = 0; it < 2; it++) {
            int idx = tid + it * 512;
            int row = idx >> 4, c = idx & 15;
            uint32_t d = row * 256 + (uint32_t)((c * 16) ^ ((row & 7) << 4));
            size_t go = ((size_t)((b*16 + h)*64 + row)) * 2048 + kt*128 + c*8;
            cp16(vbase + d, VTh + go);
            cp16(vbase + 16384u + d, VTl + go);
        }
        if (tid < 128) {
            float v = PB[(size_t)(kt*128 + tid) * N_HEADS + h];
            *(float*)(sm + A_PB + (uint32_t)s * 512u + tid * 4) = v;
        }
    };

    float accO[8][4];
    #pragma unroll
    for (int f = 0; f < 8; f++)
        #pragma unroll
        for (int q = 0; q < 4; q++) accO[f][q] = 0.f;

    load_q(); cp_commit();
    load_kv(0, ktBeg); cp_commit();
    cp_wait1();
    __syncthreads();

    uint32_t qf[4][4];
    #pragma unroll
    for (int ks = 0; ks < 4; ks++) {
        uint32_t kb = (uint32_t)((ks * 32 + laneK) ^ xorA);
        ldsm_x4(qf[ks], sb + A_SQ + (uint32_t)m0 * 128 + rowbK + kb);
    }

    const int NIT = SEQ/256;
    for (int it = 0; it < NIT; it++) {
        int kt = ktBeg + it;
        int s = it & 1;
        if (it + 1 < NIT) {
            load_kv(s ^ 1, kt + 1);
            cp_commit();
            cp_wait1();
        } else {
            cp_wait0();
        }
        __syncthreads();

        uint32_t kst = sb + A_SK + (uint32_t)s * 32768u + (uint32_t)ntb * 2048u;
        uint32_t vst = sb + A_SVT + (uint32_t)s * 32768u;
        const float* pbs = (const float*)(sm + A_PB + (uint32_t)s * 512u);

        #pragma unroll
        for (int c = 0; c < 2; c++) {
            float sc[4][4];
            #pragma unroll
            for (int f = 0; f < 4; f++)
                #pragma unroll
                for (int q = 0; q < 4; q++) sc[f][q] = 0.f;

            #pragma unroll
            for (int ks = 0; ks < 4; ks++) {
                uint32_t kb = (uint32_t)((ks * 32 + laneK) ^ xorA);
                #pragma unroll
                for (int t = 0; t < 2; t++) {
                    int nt = 2*c + t;
                    uint32_t kf[4];
                    ldsm_x4(kf, kst + (uint32_t)nt * 2048u + rowbK + kb);
                    mma16816h(sc[2*t],   qf[ks], kf[0], kf[2]);
                    mma16816h(sc[2*t+1], qf[ks], kf[1], kf[3]);
                    uint32_t klr[4];
                    ldsm_x4(klr, kst + 16384u + (uint32_t)nt * 2048u + rowbK + kb);
                    mma16816h(sc[2*t],   qf[ks], klr[0], klr[2]);
                    mma16816h(sc[2*t+1], qf[ks], klr[1], klr[3]);
                }
            }

            uint32_t sf[2][4];
            #pragma unroll
            for (int t = 0; t < 2; t++) {
                int nt = 2*c + t;
                #pragma unroll
                for (int half = 0; half < 2; half++) {
                    int f = 2*t + half;
                    int tcol = ntb*16 + nt*16 + half*8 + tq*2;
                    float pb0 = pbs[tcol], pb1 = pbs[tcol + 1];
                    float w0 = siluf(sc[f][0] * 0.125f + pb0);
                    float w1 = siluf(sc[f][1] * 0.125f + pb1);
                    float w2 = siluf(sc[f][2] * 0.125f + pb0);
                    float w3 = siluf(sc[f][3] * 0.125f + pb1);
                    sf[t][half*2]     = pack_f16(w0, w1);
                    sf[t][half*2 + 1] = pack_f16(w2, w3);
                }
            }

            #pragma unroll
            for (int t = 0; t < 2; t++) {
                int gks = ntb + 2*c + t;
                uint32_t kb = (uint32_t)((gks * 32 + laneK) ^ xorA);
                #pragma unroll
                for (int dn = 0; dn < 4; dn++) {
                    uint32_t vf[4];
                    ldsm_x4(vf, vst + (uint32_t)dn * 4096u + rowbV + kb);
                    mma16816h(accO[2*dn],   sf[t], vf[0], vf[2]);
                    mma16816h(accO[2*dn+1], sf[t], vf[1], vf[3]);
                    uint32_t vl[4];
                    ldsm_x4(vl, vst + 16384u + (uint32_t)dn * 4096u + rowbV + kb);
                    mma16816h(accO[2*dn],   sf[t], vl[0], vl[2]);
                    mma16816h(accO[2*dn+1], sf[t], vl[1], vl[3]);
                }
            }
        }
        __syncthreads();
    }

    if (kw == 1) {
        float* red = (float*)(sm + A_RED) + ((size_t)mw * 32 + lane) * 32;
        #pragma unroll
        for (int f = 0; f < 8; f++) {
            red[f*4+0] = accO[f][0]; red[f*4+1] = accO[f][1];
            red[f*4+2] = accO[f][2]; red[f*4+3] = accO[f][3];
        }
    }
    __syncthreads();
    if (kw == 0) {
        const float* red = (const float*)(sm + A_RED) + ((size_t)mw * 32 + lane) * 32;
        #pragma unroll
        for (int dn = 0; dn < 4; dn++) {
            #pragma unroll
            for (int half = 0; half < 2; half++) {
                int f = 2*dn + half;
                float o0 = accO[f][0] + red[f*4+0];
                float o1 = accO[f][1] + red[f*4+1];
                float o2 = accO[f][2] + red[f*4+2];
                float o3 = accO[f][3] + red[f*4+3];
                int col = h*64 + dn*16 + half*8 + tq*2;
                int row = b*SEQ + qt*128 + m0 + group;
                *(float2*)(P + (size_t)row * D_MODEL + col) = make_float2(o0, o1);
                *(float2*)(P + (size_t)(row + 8) * D_MODEL + col) = make_float2(o2, o3);
            }
        }
    }
}

// ---------------- launch ----------------------------------------------------
extern "C" void kernel_launch(void* const* d_in, const int* in_sizes, int n_in,
                              void* d_out, int out_size)
{
    const float* x      = (const float*)d_in[0];
    const float* pb     = (const float*)d_in[2];
    const float* wq     = (const float*)d_in[3];
    const float* bq     = (const float*)d_in[4];
    const float* wk     = (const float*)d_in[5];
    const float* bk_    = (const float*)d_in[6];
    const float* wv     = (const float*)d_in[7];
    const float* bv     = (const float*)d_in[8];
    const float* wu     = (const float*)d_in[9];
    const float* bu     = (const float*)d_in[10];
    const float* g_ams  = (const float*)d_in[11];
    const float* w0     = (const float*)d_in[12];
    const float* b0     = (const float*)d_in[13];
    const float* w1     = (const float*)d_in[14];
    const float* b1     = (const float*)d_in[15];
    const float* w2     = (const float*)d_in[16];
    const float* b2     = (const float*)d_in[17];
    const float* g_mffn = (const float*)d_in[18];
    float* out = (float*)d_out;

    float *Qf, *Kf, *Vf, *Uf, *AOf, *P2f, *Of;
    __half *A1, *A2, *WTh, *WTl;
    cudaGetSymbolAddress((void**)&Qf,  g_Q);
    cudaGetSymbolAddress((void**)&Kf,  g_K);
    cudaGetSymbolAddress((void**)&Vf,  g_V);
    cudaGetSymbolAddress((void**)&Uf,  g_U);
    cudaGetSymbolAddress((void**)&AOf, g_AO);
    cudaGetSymbolAddress((void**)&P2f, g_P2);
    cudaGetSymbolAddress((void**)&Of,  g_O);
    cudaGetSymbolAddress((void**)&A1,  g_A1);
    cudaGetSymbolAddress((void**)&A2,  g_A2);
    cudaGetSymbolAddress((void**)&WTh, g_WTh);
    cudaGetSymbolAddress((void**)&WTl, g_WTl);

    const size_t NEL = (size_t)M_ROWS * D_MODEL;
    __half *Qsb = (__half*)Qf;
    __half *Khb = (__half*)Kf,  *Klb = Khb + NEL;
    __half *VTh = (__half*)Vf,  *VTl = VTh + NEL;

    __half *T0_h = WTh + (size_t)4*W1M, *T0_l = WTl + (size_t)4*W1M;
    __half *T2_h = WTh + (size_t)5*W1M, *T2_l = WTl + (size_t)5*W1M;
    __half *T1_h = WTh + (size_t)6*W1M, *T1_l = WTl + (size_t)6*W1M;

    const int GSM = 2 * STAGE_B;   // 163840
    cudaFuncSetAttribute(gemm_res,  cudaFuncAttributeMaxDynamicSharedMemorySize, GSM);
    cudaFuncSetAttribute(proj4,     cudaFuncAttributeMaxDynamicSharedMemorySize, GSM);
    cudaFuncSetAttribute(gemm_w1sg, cudaFuncAttributeMaxDynamicSharedMemorySize, 2*STAGE_W);
    cudaFuncSetAttribute(attn_tc,   cudaFuncAttributeMaxDynamicSharedMemorySize, ATT_SMEM);

    wtsplit_all<<<8192, dim3(32, 8)>>>(wq, wk, wv, wu, w0, w2, w1, WTh, WTl);
    rmsnorm_tc<<<M_ROWS, 256>>>(x, g_ams, A1);
    proj4<<<dim3(4, 32, 4), 512, GSM>>>(A1, WTh, WTl, bq, bk_, bv, bu,
                                        Qsb, Khb, Klb, VTh, VTl, Uf);
    attn_tc<<<dim3(SEQ/128, N_HEADS, BATCH*2), 512, ATT_SMEM>>>(Qsb, Khb, Klb, VTh, VTl, pb, AOf, P2f);
    merge_ams<<<M_ROWS, 256>>>(AOf, P2f, g_ams, Uf, A2);
    gemm_res<<<dim3(4, 32), 512, GSM>>>(A2, T0_h, T0_l, b0, x, Of, M_ROWS, 1024, 1024);
    rmsnorm_tc<<<M_ROWS, 256>>>(Of, g_mffn, A1);
    gemm_w1sg<<<dim3(8, 32), 512, 2*STAGE_W>>>(A1, T1_h, T1_l, b1, A2);
    gemm_res<<<dim3(4, 32), 512, GSM>>>(A2, T2_h, T2_l, b2, Of, out, M_ROWS, 1024, 1024);
}

// round 15
// speedup vs baseline: 2.3833x; 1.5102x over previous
#include <cuda_runtime.h>
#include <cuda_fp16.h>
#include <cstdint>
#include <math.h>

#define D_MODEL 1024
#define N_HEADS 16
#define DH      64
#define BATCH   2
#define SEQ     2048
#define M_ROWS  (BATCH*SEQ)   // 4096

// ---------------- scratch (static device globals; no allocations) ----------
__device__ float g_Q  [M_ROWS*D_MODEL];   // aliased: Q fp16
__device__ float g_K  [M_ROWS*D_MODEL];   // aliased: K fp16
__device__ float g_V  [M_ROWS*D_MODEL];   // aliased: VT fp16 (transposed per head)
__device__ float g_U  [M_ROWS*D_MODEL];
__device__ float g_AO [M_ROWS*D_MODEL];   // attention partial 0
__device__ float g_P2 [M_ROWS*D_MODEL];   // attention partial 1
__device__ float g_O  [M_ROWS*D_MODEL];

__device__ __half g_A1[M_ROWS*D_MODEL];   // activation fp16
__device__ __half g_A2[M_ROWS*D_MODEL];

__device__ __half g_WT[8*1024*1024];      // weights fp16, [N,K]

#define W1M (1024*1024)

__device__ __forceinline__ float siluf(float z) {
    return z * (1.0f / (1.0f + __expf(-z)));
}

__device__ __forceinline__ uint32_t smem_u32(const void* p) {
    uint32_t a;
    asm("{ .reg .u64 t; cvta.to.shared.u64 t, %1; cvt.u32.u64 %0, t; }" : "=r"(a) : "l"(p));
    return a;
}

__device__ __forceinline__ void ldsm_x4(uint32_t* r, uint32_t a) {
    asm volatile("ldmatrix.sync.aligned.m8n8.x4.shared.b16 {%0,%1,%2,%3}, [%4];"
                 : "=r"(r[0]), "=r"(r[1]), "=r"(r[2]), "=r"(r[3]) : "r"(a));
}

__device__ __forceinline__ void mma16816h(float* c, const uint32_t* a, uint32_t b0, uint32_t b1) {
    asm volatile("mma.sync.aligned.m16n8k16.row.col.f32.f16.f16.f32 "
                 "{%0,%1,%2,%3}, {%4,%5,%6,%7}, {%8,%9}, {%0,%1,%2,%3};"
                 : "+f"(c[0]), "+f"(c[1]), "+f"(c[2]), "+f"(c[3])
                 : "r"(a[0]), "r"(a[1]), "r"(a[2]), "r"(a[3]), "r"(b0), "r"(b1));
}

__device__ __forceinline__ void cp16(uint32_t dst, const void* src) {
    asm volatile("cp.async.cg.shared.global [%0], [%1], 16;" :: "r"(dst), "l"(src));
}
__device__ __forceinline__ void cp_commit() { asm volatile("cp.async.commit_group;"); }
__device__ __forceinline__ void cp_wait1()  { asm volatile("cp.async.wait_group 1;"); }
__device__ __forceinline__ void cp_wait0()  { asm volatile("cp.async.wait_group 0;"); }

__device__ __forceinline__ uint32_t pack_f16(float a, float b) {
    __half2 t = __floats2half2_rn(a, b);
    return *(uint32_t*)&t;
}

// ======= batched weight transpose + fp16 convert (all 7 weights) ============
__global__ void __launch_bounds__(256)
wtcvt_all(const float* __restrict__ wq, const float* __restrict__ wk,
          const float* __restrict__ wv, const float* __restrict__ wu,
          const float* __restrict__ w0, const float* __restrict__ w2,
          const float* __restrict__ w1, __half* __restrict__ WT)
{
    __shared__ float t[32][33];
    int bid = blockIdx.x;
    const float* W; __half* T;
    int N, nx, ky;
    if (bid < 6144) {
        int w = bid >> 10, local = bid & 1023;
        switch (w) {
            case 0: W = wq; break; case 1: W = wk; break;
            case 2: W = wv; break; case 3: W = wu; break;
            case 4: W = w0; break; default: W = w2; break;
        }
        T = WT + (size_t)w * W1M;
        N = 1024; nx = local & 31; ky = local >> 5;
    } else {
        int local = bid - 6144;
        W = w1; T = WT + (size_t)6 * W1M;
        N = 2048; nx = local & 63; ky = local >> 6;
    }
    const int K = 1024;
    int tx = threadIdx.x, ty = threadIdx.y;
    int n0 = nx * 32, k0 = ky * 32;
    #pragma unroll
    for (int i = 0; i < 4; i++)
        t[ty + i*8][tx] = W[(size_t)(k0 + ty + i*8) * N + n0 + tx];
    __syncthreads();
    #pragma unroll
    for (int i = 0; i < 4; i++) {
        size_t off = (size_t)(n0 + ty + i*8) * K + k0 + tx;
        T[off] = __float2half_rn(t[tx][ty + i*8]);
    }
}

// ---------------- RMSNorm -> fp16 -------------------------------------------
__global__ void __launch_bounds__(256)
rmsnorm_tc(const float* __restrict__ X, const float* __restrict__ g,
           __half* __restrict__ Y)
{
    int r = blockIdx.x, t = threadIdx.x;
    float4 v = ((const float4*)(X + (size_t)r * D_MODEL))[t];
    float ss = v.x*v.x + v.y*v.y + v.z*v.z + v.w*v.w;
    #pragma unroll
    for (int o = 16; o; o >>= 1) ss += __shfl_xor_sync(0xffffffffu, ss, o);
    __shared__ float ws[8]; __shared__ float s_inv;
    if ((t & 31) == 0) ws[t >> 5] = ss;
    __syncthreads();
    if (t == 0) {
        float tot = 0.f;
        #pragma unroll
        for (int i = 0; i < 8; i++) tot += ws[i];
        s_inv = rsqrtf(tot * (1.0f / D_MODEL) + 1e-8f);
    }
    __syncthreads();
    float iv = s_inv;
    float4 gv = ((const float4*)g)[t];
    size_t base = (size_t)r * D_MODEL + t*4;
    *(__half2*)(Y + base)     = __floats2half2_rn(v.x*iv*gv.x, v.y*iv*gv.y);
    *(__half2*)(Y + base + 2) = __floats2half2_rn(v.z*iv*gv.z, v.w*iv*gv.w);
}

// -------- merge attention partials + ams: rmsnorm(P0+P1, g) * U -> fp16 -----
__global__ void __launch_bounds__(256)
merge_ams(const float* __restrict__ P0, const float* __restrict__ P1,
          const float* __restrict__ g, const float* __restrict__ U,
          __half* __restrict__ Y)
{
    int r = blockIdx.x, t = threadIdx.x;
    float4 a = ((const float4*)(P0 + (size_t)r * D_MODEL))[t];
    float4 bb = ((const float4*)(P1 + (size_t)r * D_MODEL))[t];
    float4 v;
    v.x = a.x + bb.x; v.y = a.y + bb.y; v.z = a.z + bb.z; v.w = a.w + bb.w;
    float ss = v.x*v.x + v.y*v.y + v.z*v.z + v.w*v.w;
    #pragma unroll
    for (int o = 16; o; o >>= 1) ss += __shfl_xor_sync(0xffffffffu, ss, o);
    __shared__ float ws[8]; __shared__ float s_inv;
    if ((t & 31) == 0) ws[t >> 5] = ss;
    __syncthreads();
    if (t == 0) {
        float tot = 0.f;
        #pragma unroll
        for (int i = 0; i < 8; i++) tot += ws[i];
        s_inv = rsqrtf(tot * (1.0f / D_MODEL) + 1e-8f);
    }
    __syncthreads();
    float iv = s_inv;
    float4 gv = ((const float4*)g)[t];
    float4 uv = ((const float4*)(U + (size_t)r * D_MODEL))[t];
    size_t base = (size_t)r * D_MODEL + t*4;
    *(__half2*)(Y + base)     = __floats2half2_rn(v.x*iv*gv.x*uv.x, v.y*iv*gv.y*uv.y);
    *(__half2*)(Y + base + 2) = __floats2half2_rn(v.z*iv*gv.z*uv.z, v.w*iv*gv.w*uv.w);
}

// ===== fp16 1-pass HMMA GEMM (EPI 2): C = A@B^T + bias + R ================
#define SM_A    0
#define SM_B    16384
#define STAGE_B 49152

__global__ void __launch_bounds__(512, 1)
gemm_res(const __half* __restrict__ A, const __half* __restrict__ B,
         const float* __restrict__ bias, const float* __restrict__ R,
         float* __restrict__ C, int M, int N, int K)
{
    extern __shared__ __align__(128) char sm[];
    uint32_t sb = smem_u32(sm);
    int tid  = threadIdx.x;
    int wid  = tid >> 5;
    int lane = tid & 31;
    int wm = wid & 1, wn = wid >> 1;
    int bm = blockIdx.y * 128, bn = blockIdx.x * 256;
    int m0 = wm * 64, n0 = wn * 32;

    int laneRow = lane & 15;
    int laneK   = (lane >> 4) * 16;
    uint32_t xorA = (uint32_t)((laneRow & 7) << 4);

    float acc[4][4][4];
    #pragma unroll
    for (int i = 0; i < 4; i++)
        #pragma unroll
        for (int j = 0; j < 4; j++)
            #pragma unroll
            for (int q = 0; q < 4; q++) acc[i][j][q] = 0.f;

    const int NCH = K >> 6;

    auto load_stage = [&](int s, int chunk) {
        uint32_t st = sb + s * STAGE_B;
        int k0 = chunk * 64;
        #pragma unroll
        for (int it = 0; it < 2; it++) {
            int idx = tid + it * 512;
            int row = idx >> 3, c = idx & 7;
            uint32_t d = st + row * 128 + (uint32_t)((c * 16) ^ ((row & 7) << 4));
            size_t go = (size_t)(bm + row) * K + k0 + c * 8;
            cp16(d + SM_A, A + go);
        }
        #pragma unroll
        for (int it = 0; it < 4; it++) {
            int idx = tid + it * 512;
            int row = idx >> 3, c = idx & 7;
            uint32_t d = st + row * 128 + (uint32_t)((c * 16) ^ ((row & 7) << 4));
            size_t go = (size_t)(bn + row) * K + k0 + c * 8;
            cp16(d + SM_B, B + go);
        }
    };

    load_stage(0, 0);
    cp_commit();

    for (int chunk = 0; chunk < NCH; chunk++) {
        int s = chunk & 1;
        if (chunk + 1 < NCH) {
            load_stage(s ^ 1, chunk + 1);
            cp_commit();
            cp_wait1();
        } else {
            cp_wait0();
        }
        __syncthreads();

        uint32_t st = sb + s * STAGE_B;
        #pragma unroll
        for (int ks = 0; ks < 4; ks++) {
            uint32_t kb = (uint32_t)((ks * 32 + laneK) ^ xorA);
            uint32_t a[4][4], bf[2][4];
            #pragma unroll
            for (int i = 0; i < 4; i++)
                ldsm_x4(a[i], st + SM_A + (uint32_t)(m0 + i*16 + laneRow) * 128 + kb);
            #pragma unroll
            for (int p = 0; p < 2; p++)
                ldsm_x4(bf[p], st + SM_B + (uint32_t)(n0 + p*16 + laneRow) * 128 + kb);
            #pragma unroll
            for (int i = 0; i < 4; i++)
                #pragma unroll
                for (int j = 0; j < 4; j++)
                    mma16816h(acc[i][j], a[i], bf[j>>1][j&1], bf[j>>1][2 + (j&1)]);
        }
        __syncthreads();
    }

    int group = lane >> 2, tq = lane & 3;
    #pragma unroll
    for (int j = 0; j < 4; j++) {
        int n = bn + n0 + j*8 + tq*2;
        float bv0 = bias[n], bv1 = bias[n+1];
        #pragma unroll
        for (int i = 0; i < 4; i++) {
            int m = bm + m0 + i*16 + group;
            size_t off0 = (size_t)m * N + n;
            size_t off1 = (size_t)(m + 8) * N + n;
            float2 r0 = *(const float2*)(R + off0);
            float2 r1 = *(const float2*)(R + off1);
            *(float2*)(C + off0) = make_float2(acc[i][j][0] + bv0 + r0.x, acc[i][j][1] + bv1 + r0.y);
            *(float2*)(C + off1) = make_float2(acc[i][j][2] + bv0 + r1.x, acc[i][j][3] + bv1 + r1.y);
        }
    }
}

// ====== fused Q/K/V/U projection: fp16 1-pass, grid.z selects weight =======
__global__ void __launch_bounds__(512, 1)
proj4(const __half* __restrict__ A, const __half* __restrict__ WTG,
      const float* __restrict__ bq, const float* __restrict__ bk,
      const float* __restrict__ bv, const float* __restrict__ bu,
      __half* __restrict__ Qs, __half* __restrict__ Ks,
      __half* __restrict__ VT, float* __restrict__ Uf)
{
    extern __shared__ __align__(128) char sm[];
    uint32_t sb = smem_u32(sm);
    int tid  = threadIdx.x;
    int wid  = tid >> 5;
    int lane = tid & 31;
    int wm = wid & 1, wn = wid >> 1;
    int z  = blockIdx.z;
    int bm = blockIdx.y * 128, bn = blockIdx.x * 256;
    int m0 = wm * 64, n0 = wn * 32;
    const int K = 1024, N = 1024;

    const __half* B = WTG + (size_t)z * W1M;
    const float* bias = (z == 0) ? bq : (z == 1) ? bk : (z == 2) ? bv : bu;

    int laneRow = lane & 15;
    int laneK   = (lane >> 4) * 16;
    uint32_t xorA = (uint32_t)((laneRow & 7) << 4);

    float acc[4][4][4];
    #pragma unroll
    for (int i = 0; i < 4; i++)
        #pragma unroll
        for (int j = 0; j < 4; j++)
            #pragma unroll
            for (int q = 0; q < 4; q++) acc[i][j][q] = 0.f;

    const int NCH = K >> 6;

    auto load_stage = [&](int s, int chunk) {
        uint32_t st = sb + s * STAGE_B;
        int k0 = chunk * 64;
        #pragma unroll
        for (int it = 0; it < 2; it++) {
            int idx = tid + it * 512;
            int row = idx >> 3, c = idx & 7;
            uint32_t d = st + row * 128 + (uint32_t)((c * 16) ^ ((row & 7) << 4));
            size_t go = (size_t)(bm + row) * K + k0 + c * 8;
            cp16(d + SM_A, A + go);
        }
        #pragma unroll
        for (int it = 0; it < 4; it++) {
            int idx = tid + it * 512;
            int row = idx >> 3, c = idx & 7;
            uint32_t d = st + row * 128 + (uint32_t)((c * 16) ^ ((row & 7) << 4));
            size_t go = (size_t)(bn + row) * K + k0 + c * 8;
            cp16(d + SM_B, B + go);
        }
    };

    load_stage(0, 0);
    cp_commit();

    for (int chunk = 0; chunk < NCH; chunk++) {
        int s = chunk & 1;
        if (chunk + 1 < NCH) {
            load_stage(s ^ 1, chunk + 1);
            cp_commit();
            cp_wait1();
        } else {
            cp_wait0();
        }
        __syncthreads();

        uint32_t st = sb + s * STAGE_B;
        #pragma unroll
        for (int ks = 0; ks < 4; ks++) {
            uint32_t kb = (uint32_t)((ks * 32 + laneK) ^ xorA);
            uint32_t a[4][4], bf[2][4];
            #pragma unroll
            for (int i = 0; i < 4; i++)
                ldsm_x4(a[i], st + SM_A + (uint32_t)(m0 + i*16 + laneRow) * 128 + kb);
            #pragma unroll
            for (int p = 0; p < 2; p++)
                ldsm_x4(bf[p], st + SM_B + (uint32_t)(n0 + p*16 + laneRow) * 128 + kb);
            #pragma unroll
            for (int i = 0; i < 4; i++)
                #pragma unroll
                for (int j = 0; j < 4; j++)
                    mma16816h(acc[i][j], a[i], bf[j>>1][j&1], bf[j>>1][2 + (j&1)]);
        }
        __syncthreads();
    }

    int group = lane >> 2, tq = lane & 3;
    #pragma unroll
    for (int j = 0; j < 4; j++) {
        int n = bn + n0 + j*8 + tq*2;
        float bv0 = bias[n], bv1 = bias[n+1];
        #pragma unroll
        for (int i = 0; i < 4; i++) {
            int m = bm + m0 + i*16 + group;
            float v0 = acc[i][j][0] + bv0, v1 = acc[i][j][1] + bv1;
            float v2 = acc[i][j][2] + bv0, v3 = acc[i][j][3] + bv1;
            size_t off0 = (size_t)m * N + n;
            size_t off1 = (size_t)(m + 8) * N + n;
            if (z == 0) {
                *(__half2*)(Qs + off0) = __floats2half2_rn(v0, v1);
                *(__half2*)(Qs + off1) = __floats2half2_rn(v2, v3);
            } else if (z == 1) {
                *(__half2*)(Ks + off0) = __floats2half2_rn(v0, v1);
                *(__half2*)(Ks + off1) = __floats2half2_rn(v2, v3);
            } else if (z == 2) {
                int bi = m >> 11, tt = m & 2047;
                int hh = n >> 6,  dd = n & 63;
                size_t vb = ((size_t)((bi*16 + hh)*64 + dd)) * 2048 + tt;
                VT[vb]        = __float2half_rn(v0);
                VT[vb + 2048] = __float2half_rn(v1);
                VT[vb + 8]    = __float2half_rn(v2);
                VT[vb + 2056] = __float2half_rn(v3);
            } else {
                *(float2*)(Uf + off0) = make_float2(siluf(v0), siluf(v1));
                *(float2*)(Uf + off1) = make_float2(siluf(v2), siluf(v3));
            }
        }
    }
}

// ====== w1 GEMM + swiglu fusion: fp16 1-pass ================================
#define W_A   0
#define W_B1  16384
#define W_B2  32768
#define STAGE_W 49152

__global__ void __launch_bounds__(512, 1)
gemm_w1sg(const __half* __restrict__ A, const __half* __restrict__ B,
          const float* __restrict__ b1, __half* __restrict__ Y)
{
    extern __shared__ __align__(128) char sm[];
    uint32_t sb = smem_u32(sm);
    int tid  = threadIdx.x;
    int wid  = tid >> 5;
    int lane = tid & 31;
    int wm = wid & 1, wn = wid >> 1;
    int bm = blockIdx.y * 128, bn = blockIdx.x * 128;
    int m0 = wm * 64, n0 = wn * 16;
    const int K = 1024;

    int laneRow = lane & 15;
    int laneK   = (lane >> 4) * 16;
    uint32_t xorA = (uint32_t)((laneRow & 7) << 4);

    float acc1[4][2][4], acc2[4][2][4];
    #pragma unroll
    for (int i = 0; i < 4; i++)
        #pragma unroll
        for (int j = 0; j < 2; j++)
            #pragma unroll
            for (int q = 0; q < 4; q++) { acc1[i][j][q] = 0.f; acc2[i][j][q] = 0.f; }

    const int NCH = K >> 6;

    auto load_stage = [&](int s, int chunk) {
        uint32_t st = sb + s * STAGE_W;
        int k0 = chunk * 64;
        #pragma unroll
        for (int it = 0; it < 2; it++) {
            int idx = tid + it * 512;
            int row = idx >> 3, c = idx & 7;
            uint32_t d = st + row * 128 + (uint32_t)((c * 16) ^ ((row & 7) << 4));
            size_t goA  = (size_t)(bm + row) * K + k0 + c * 8;
            size_t goB1 = (size_t)(bn + row) * K + k0 + c * 8;
            size_t goB2 = (size_t)(1024 + bn + row) * K + k0 + c * 8;
            cp16(d + W_A,  A + goA);
            cp16(d + W_B1, B + goB1);
            cp16(d + W_B2, B + goB2);
        }
    };

    load_stage(0, 0);
    cp_commit();

    for (int chunk = 0; chunk < NCH; chunk++) {
        int s = chunk & 1;
        if (chunk + 1 < NCH) {
            load_stage(s ^ 1, chunk + 1);
            cp_commit();
            cp_wait1();
        } else {
            cp_wait0();
        }
        __syncthreads();

        uint32_t st = sb + s * STAGE_W;
        #pragma unroll
        for (int ks = 0; ks < 4; ks++) {
            uint32_t kb = (uint32_t)((ks * 32 + laneK) ^ xorA);
            uint32_t a[4][4], b1f[4], b2f[4];
            #pragma unroll
            for (int i = 0; i < 4; i++)
                ldsm_x4(a[i], st + W_A + (uint32_t)(m0 + i*16 + laneRow) * 128 + kb);
            ldsm_x4(b1f, st + W_B1 + (uint32_t)(n0 + laneRow) * 128 + kb);
            ldsm_x4(b2f, st + W_B2 + (uint32_t)(n0 + laneRow) * 128 + kb);
            #pragma unroll
            for (int i = 0; i < 4; i++)
                #pragma unroll
                for (int j = 0; j < 2; j++) {
                    mma16816h(acc1[i][j], a[i], b1f[j], b1f[2 + j]);
                    mma16816h(acc2[i][j], a[i], b2f[j], b2f[2 + j]);
                }
        }
        __syncthreads();
    }

    int group = lane >> 2, tq = lane & 3;
    #pragma unroll
    for (int j = 0; j < 2; j++) {
        int n = bn + n0 + j*8 + tq*2;
        float c10 = b1[n], c11 = b1[n+1];
        float c20 = b1[1024 + n], c21 = b1[1025 + n];
        #pragma unroll
        for (int i = 0; i < 4; i++) {
            int m = bm + m0 + i*16 + group;
            float y0 = siluf(acc1[i][j][0] + c10) * (acc2[i][j][0] + c20);
            float y1 = siluf(acc1[i][j][1] + c11) * (acc2[i][j][1] + c21);
            float y2 = siluf(acc1[i][j][2] + c10) * (acc2[i][j][2] + c20);
            float y3 = siluf(acc1[i][j][3] + c11) * (acc2[i][j][3] + c21);
            size_t off0 = (size_t)m * 1024 + n;
            size_t off1 = (size_t)(m + 8) * 1024 + n;
            *(__half2*)(Y + off0) = __floats2half2_rn(y0, y1);
            *(__half2*)(Y + off1) = __floats2half2_rn(y2, y3);
        }
    }
}

// ===== attention: fp16 1-pass, 16 warps, key-split intra-CTA, kv-split ======
#define A_SQ  0u
#define A_SK  16384u       // + s*16384
#define A_SVT 49152u       // + s*16384
#define A_PB  81920u       // + s*512
#define A_RED A_SK         // reduction spans both K stages (32KB)
#define ATT_SMEM 82944

__global__ void __launch_bounds__(512, 1)
attn_tc(const __half* __restrict__ Qs, const __half* __restrict__ Ks,
        const __half* __restrict__ VT,
        const float* __restrict__ PB, float* __restrict__ P0, float* __restrict__ P1)
{
    extern __shared__ __align__(128) char sm[];
    uint32_t sb = smem_u32(sm);
    int tid  = threadIdx.x;
    int wid  = tid >> 5;
    int lane = tid & 31;
    int qt = blockIdx.x, h = blockIdx.y;
    int b  = blockIdx.z & 1;
    int kv = blockIdx.z >> 1;
    float* P = kv ? P1 : P0;
    int ktBeg = kv * (SEQ/256);
    int mw = wid & 7;
    int kw = wid >> 3;
    int m0 = mw * 16;
    int ntb = kw * 4;

    int laneRow = lane & 15;
    int laneK   = (lane >> 4) * 16;
    uint32_t xorA = (uint32_t)((laneRow & 7) << 4);
    int group = lane >> 2, tq = lane & 3;
    uint32_t rowbK = (uint32_t)laneRow * 128;
    uint32_t rowbV = (uint32_t)laneRow * 256;

    auto load_q = [&]() {
        #pragma unroll
        for (int it = 0; it < 2; it++) {
            int idx = tid + it * 512;
            int row = idx >> 3, c = idx & 7;
            uint32_t d = row * 128 + (uint32_t)((c * 16) ^ ((row & 7) << 4));
            size_t go = ((size_t)(b*SEQ + qt*128 + row)) * D_MODEL + h*64 + c*8;
            cp16(sb + A_SQ + d, Qs + go);
        }
    };
    auto load_kv = [&](int s, int kt) {
        uint32_t kbase = sb + A_SK + (uint32_t)s * 16384u;
        {
            int idx = tid;              // 512 threads cover 8KB? no: 128 rows x 8 chunks = 1024
            #pragma unroll
            for (int it = 0; it < 2; it++) {
                int ix = idx + it * 512;
                int row = ix >> 3, c = ix & 7;
                uint32_t d = row * 128 + (uint32_t)((c * 16) ^ ((row & 7) << 4));
                size_t go = ((size_t)(b*SEQ + kt*128 + row)) * D_MODEL + h*64 + c*8;
                cp16(kbase + d, Ks + go);
            }
        }
        uint32_t vbase = sb + A_SVT + (uint32_t)s * 16384u;
        {
            #pragma unroll
            for (int it = 0; it < 2; it++) {
                int ix = tid + it * 512;
                int row = ix >> 4, c = ix & 15;
                uint32_t d = row * 256 + (uint32_t)((c * 16) ^ ((row & 7) << 4));
                size_t go = ((size_t)((b*16 + h)*64 + row)) * 2048 + kt*128 + c*8;
                cp16(vbase + d, VT + go);
            }
        }
        if (tid < 128) {
            float v = PB[(size_t)(kt*128 + tid) * N_HEADS + h];
            *(float*)(sm + A_PB + (uint32_t)s * 512u + tid * 4) = v;
        }
    };

    float accO[8][4];
    #pragma unroll
    for (int f = 0; f < 8; f++)
        #pragma unroll
        for (int q = 0; q < 4; q++) accO[f][q] = 0.f;

    load_q(); cp_commit();
    load_kv(0, ktBeg); cp_commit();
    cp_wait1();
    __syncthreads();

    uint32_t qf[4][4];
    #pragma unroll
    for (int ks = 0; ks < 4; ks++) {
        uint32_t kb = (uint32_t)((ks * 32 + laneK) ^ xorA);
        ldsm_x4(qf[ks], sb + A_SQ + (uint32_t)m0 * 128 + rowbK + kb);
    }

    const int NIT = SEQ/256;
    for (int it = 0; it < NIT; it++) {
        int kt = ktBeg + it;
        int s = it & 1;
        if (it + 1 < NIT) {
            load_kv(s ^ 1, kt + 1);
            cp_commit();
            cp_wait1();
        } else {
            cp_wait0();
        }
        __syncthreads();

        uint32_t kst = sb + A_SK + (uint32_t)s * 16384u + (uint32_t)ntb * 2048u;
        uint32_t vst = sb + A_SVT + (uint32_t)s * 16384u;
        const float* pbs = (const float*)(sm + A_PB + (uint32_t)s * 512u);

        #pragma unroll
        for (int c = 0; c < 2; c++) {
            float sc[4][4];
            #pragma unroll
            for (int f = 0; f < 4; f++)
                #pragma unroll
                for (int q = 0; q < 4; q++) sc[f][q] = 0.f;

            #pragma unroll
            for (int ks = 0; ks < 4; ks++) {
                uint32_t kb = (uint32_t)((ks * 32 + laneK) ^ xorA);
                #pragma unroll
                for (int t = 0; t < 2; t++) {
                    int nt = 2*c + t;
                    uint32_t kf[4];
                    ldsm_x4(kf, kst + (uint32_t)nt * 2048u + rowbK + kb);
                    mma16816h(sc[2*t],   qf[ks], kf[0], kf[2]);
                    mma16816h(sc[2*t+1], qf[ks], kf[1], kf[3]);
                }
            }

            uint32_t sf[2][4];
            #pragma unroll
            for (int t = 0; t < 2; t++) {
                int nt = 2*c + t;
                #pragma unroll
                for (int half = 0; half < 2; half++) {
                    int f = 2*t + half;
                    int tcol = ntb*16 + nt*16 + half*8 + tq*2;
                    float pb0 = pbs[tcol], pb1 = pbs[tcol + 1];
                    float w0 = siluf(sc[f][0] * 0.125f + pb0);
                    float w1 = siluf(sc[f][1] * 0.125f + pb1);
                    float w2 = siluf(sc[f][2] * 0.125f + pb0);
                    float w3 = siluf(sc[f][3] * 0.125f + pb1);
                    sf[t][half*2]     = pack_f16(w0, w1);
                    sf[t][half*2 + 1] = pack_f16(w2, w3);
                }
            }

            #pragma unroll
            for (int t = 0; t < 2; t++) {
                int gks = ntb + 2*c + t;
                uint32_t kb = (uint32_t)((gks * 32 + laneK) ^ xorA);
                #pragma unroll
                for (int dn = 0; dn < 4; dn++) {
                    uint32_t vf[4];
                    ldsm_x4(vf, vst + (uint32_t)dn * 4096u + rowbV + kb);
                    mma16816h(accO[2*dn],   sf[t], vf[0], vf[2]);
                    mma16816h(accO[2*dn+1], sf[t], vf[1], vf[3]);
                }
            }
        }
        __syncthreads();
    }

    if (kw == 1) {
        float* red = (float*)(sm + A_RED) + ((size_t)mw * 32 + lane) * 32;
        #pragma unroll
        for (int f = 0; f < 8; f++) {
            red[f*4+0] = accO[f][0]; red[f*4+1] = accO[f][1];
            red[f*4+2] = accO[f][2]; red[f*4+3] = accO[f][3];
        }
    }
    __syncthreads();
    if (kw == 0) {
        const float* red = (const float*)(sm + A_RED) + ((size_t)mw * 32 + lane) * 32;
        #pragma unroll
        for (int dn = 0; dn < 4; dn++) {
            #pragma unroll
            for (int half = 0; half < 2; half++) {
                int f = 2*dn + half;
                float o0 = accO[f][0] + red[f*4+0];
                float o1 = accO[f][1] + red[f*4+1];
                float o2 = accO[f][2] + red[f*4+2];
                float o3 = accO[f][3] + red[f*4+3];
                int col = h*64 + dn*16 + half*8 + tq*2;
                int row = b*SEQ + qt*128 + m0 + group;
                *(float2*)(P + (size_t)row * D_MODEL + col) = make_float2(o0, o1);
                *(float2*)(P + (size_t)(row + 8) * D_MODEL + col) = make_float2(o2, o3);
            }
        }
    }
}

// ---------------- launch ----------------------------------------------------
extern "C" void kernel_launch(void* const* d_in, const int* in_sizes, int n_in,
                              void* d_out, int out_size)
{
    const float* x      = (const float*)d_in[0];
    const float* pb     = (const float*)d_in[2];
    const float* wq     = (const float*)d_in[3];
    const float* bq     = (const float*)d_in[4];
    const float* wk     = (const float*)d_in[5];
    const float* bk_    = (const float*)d_in[6];
    const float* wv     = (const float*)d_in[7];
    const float* bv     = (const float*)d_in[8];
    const float* wu     = (const float*)d_in[9];
    const float* bu     = (const float*)d_in[10];
    const float* g_ams  = (const float*)d_in[11];
    const float* w0     = (const float*)d_in[12];
    const float* b0     = (const float*)d_in[13];
    const float* w1     = (const float*)d_in[14];
    const float* b1     = (const float*)d_in[15];
    const float* w2     = (const float*)d_in[16];
    const float* b2     = (const float*)d_in[17];
    const float* g_mffn = (const float*)d_in[18];
    float* out = (float*)d_out;

    float *Qf, *Kf, *Vf, *Uf, *AOf, *P2f, *Of;
    __half *A1, *A2, *WT;
    cudaGetSymbolAddress((void**)&Qf,  g_Q);
    cudaGetSymbolAddress((void**)&Kf,  g_K);
    cudaGetSymbolAddress((void**)&Vf,  g_V);
    cudaGetSymbolAddress((void**)&Uf,  g_U);
    cudaGetSymbolAddress((void**)&AOf, g_AO);
    cudaGetSymbolAddress((void**)&P2f, g_P2);
    cudaGetSymbolAddress((void**)&Of,  g_O);
    cudaGetSymbolAddress((void**)&A1,  g_A1);
    cudaGetSymbolAddress((void**)&A2,  g_A2);
    cudaGetSymbolAddress((void**)&WT,  g_WT);

    __half *Qsb = (__half*)Qf;
    __half *Ksb = (__half*)Kf;
    __half *VTb = (__half*)Vf;

    __half *T0 = WT + (size_t)4*W1M;
    __half *T2 = WT + (size_t)5*W1M;
    __half *T1 = WT + (size_t)6*W1M;

    const int GSM = 2 * STAGE_B;   // 98304
    cudaFuncSetAttribute(gemm_res,  cudaFuncAttributeMaxDynamicSharedMemorySize, GSM);
    cudaFuncSetAttribute(proj4,     cudaFuncAttributeMaxDynamicSharedMemorySize, GSM);
    cudaFuncSetAttribute(gemm_w1sg, cudaFuncAttributeMaxDynamicSharedMemorySize, 2*STAGE_W);
    cudaFuncSetAttribute(attn_tc,   cudaFuncAttributeMaxDynamicSharedMemorySize, ATT_SMEM);

    wtcvt_all<<<8192, dim3(32, 8)>>>(wq, wk, wv, wu, w0, w2, w1, WT);
    rmsnorm_tc<<<M_ROWS, 256>>>(x, g_ams, A1);
    proj4<<<dim3(4, 32, 4), 512, GSM>>>(A1, WT, bq, bk_, bv, bu, Qsb, Ksb, VTb, Uf);
    attn_tc<<<dim3(SEQ/128, N_HEADS, BATCH*2), 512, ATT_SMEM>>>(Qsb, Ksb, VTb, pb, AOf, P2f);
    merge_ams<<<M_ROWS, 256>>>(AOf, P2f, g_ams, Uf, A2);
    gemm_res<<<dim3(4, 32), 512, GSM>>>(A2, T0, b0, x, Of, M_ROWS, 1024, 1024);
    rmsnorm_tc<<<M_ROWS, 256>>>(Of, g_mffn, A1);
    gemm_w1sg<<<dim3(8, 32), 512, 2*STAGE_W>>>(A1, T1, b1, A2);
    gemm_res<<<dim3(4, 32), 512, GSM>>>(A2, T2, b2, Of, out, M_ROWS, 1024, 1024);
}

// round 16
// speedup vs baseline: 2.4645x; 1.0341x over previous
#include <cuda_runtime.h>
#include <cuda_fp16.h>
#include <cstdint>
#include <math.h>

#define D_MODEL 1024
#define N_HEADS 16
#define DH      64
#define BATCH   2
#define SEQ     2048
#define M_ROWS  (BATCH*SEQ)   // 4096

// ---------------- scratch (static device globals; no allocations) ----------
__device__ float g_Q  [M_ROWS*D_MODEL];   // aliased: Q fp16
__device__ float g_K  [M_ROWS*D_MODEL];   // aliased: K fp16
__device__ float g_V  [M_ROWS*D_MODEL];   // aliased: VT fp16 (transposed per head)
__device__ float g_U  [M_ROWS*D_MODEL];
__device__ float g_AO [M_ROWS*D_MODEL];   // attention partial 0
__device__ float g_P2 [M_ROWS*D_MODEL];   // attention partial 1
__device__ float g_O  [M_ROWS*D_MODEL];

__device__ __half g_A1[M_ROWS*D_MODEL];   // activation fp16
__device__ __half g_A2[M_ROWS*D_MODEL];

__device__ __half g_WT[8*1024*1024];      // weights fp16, [N,K]

#define W1M (1024*1024)

__device__ __forceinline__ float siluf(float z) {
    return z * (1.0f / (1.0f + __expf(-z)));
}

__device__ __forceinline__ uint32_t smem_u32(const void* p) {
    uint32_t a;
    asm("{ .reg .u64 t; cvta.to.shared.u64 t, %1; cvt.u32.u64 %0, t; }" : "=r"(a) : "l"(p));
    return a;
}

__device__ __forceinline__ void ldsm_x4(uint32_t* r, uint32_t a) {
    asm volatile("ldmatrix.sync.aligned.m8n8.x4.shared.b16 {%0,%1,%2,%3}, [%4];"
                 : "=r"(r[0]), "=r"(r[1]), "=r"(r[2]), "=r"(r[3]) : "r"(a));
}

__device__ __forceinline__ void mma16816h(float* c, const uint32_t* a, uint32_t b0, uint32_t b1) {
    asm volatile("mma.sync.aligned.m16n8k16.row.col.f32.f16.f16.f32 "
                 "{%0,%1,%2,%3}, {%4,%5,%6,%7}, {%8,%9}, {%0,%1,%2,%3};"
                 : "+f"(c[0]), "+f"(c[1]), "+f"(c[2]), "+f"(c[3])
                 : "r"(a[0]), "r"(a[1]), "r"(a[2]), "r"(a[3]), "r"(b0), "r"(b1));
}

__device__ __forceinline__ void cp16(uint32_t dst, const void* src) {
    asm volatile("cp.async.cg.shared.global [%0], [%1], 16;" :: "r"(dst), "l"(src));
}
__device__ __forceinline__ void cp_commit() { asm volatile("cp.async.commit_group;"); }
__device__ __forceinline__ void cp_wait1()  { asm volatile("cp.async.wait_group 1;"); }
__device__ __forceinline__ void cp_wait0()  { asm volatile("cp.async.wait_group 0;"); }

__device__ __forceinline__ uint32_t pack_f16(float a, float b) {
    __half2 t = __floats2half2_rn(a, b);
    return *(uint32_t*)&t;
}

// ======= batched weight transpose + fp16 convert (all 7 weights) ============
__global__ void __launch_bounds__(256)
wtcvt_all(const float* __restrict__ wq, const float* __restrict__ wk,
          const float* __restrict__ wv, const float* __restrict__ wu,
          const float* __restrict__ w0, const float* __restrict__ w2,
          const float* __restrict__ w1, __half* __restrict__ WT)
{
    __shared__ float t[32][33];
    int bid = blockIdx.x;
    const float* W; __half* T;
    int N, nx, ky;
    if (bid < 6144) {
        int w = bid >> 10, local = bid & 1023;
        switch (w) {
            case 0: W = wq; break; case 1: W = wk; break;
            case 2: W = wv; break; case 3: W = wu; break;
            case 4: W = w0; break; default: W = w2; break;
        }
        T = WT + (size_t)w * W1M;
        N = 1024; nx = local & 31; ky = local >> 5;
    } else {
        int local = bid - 6144;
        W = w1; T = WT + (size_t)6 * W1M;
        N = 2048; nx = local & 63; ky = local >> 6;
    }
    const int K = 1024;
    int tx = threadIdx.x, ty = threadIdx.y;
    int n0 = nx * 32, k0 = ky * 32;
    #pragma unroll
    for (int i = 0; i < 4; i++)
        t[ty + i*8][tx] = W[(size_t)(k0 + ty + i*8) * N + n0 + tx];
    __syncthreads();
    #pragma unroll
    for (int i = 0; i < 4; i++) {
        size_t off = (size_t)(n0 + ty + i*8) * K + k0 + tx;
        T[off] = __float2half_rn(t[tx][ty + i*8]);
    }
}

// ---------------- RMSNorm -> fp16 -------------------------------------------
__global__ void __launch_bounds__(256)
rmsnorm_tc(const float* __restrict__ X, const float* __restrict__ g,
           __half* __restrict__ Y)
{
    int r = blockIdx.x, t = threadIdx.x;
    float4 v = ((const float4*)(X + (size_t)r * D_MODEL))[t];
    float ss = v.x*v.x + v.y*v.y + v.z*v.z + v.w*v.w;
    #pragma unroll
    for (int o = 16; o; o >>= 1) ss += __shfl_xor_sync(0xffffffffu, ss, o);
    __shared__ float ws[8]; __shared__ float s_inv;
    if ((t & 31) == 0) ws[t >> 5] = ss;
    __syncthreads();
    if (t == 0) {
        float tot = 0.f;
        #pragma unroll
        for (int i = 0; i < 8; i++) tot += ws[i];
        s_inv = rsqrtf(tot * (1.0f / D_MODEL) + 1e-8f);
    }
    __syncthreads();
    float iv = s_inv;
    float4 gv = ((const float4*)g)[t];
    size_t base = (size_t)r * D_MODEL + t*4;
    *(__half2*)(Y + base)     = __floats2half2_rn(v.x*iv*gv.x, v.y*iv*gv.y);
    *(__half2*)(Y + base + 2) = __floats2half2_rn(v.z*iv*gv.z, v.w*iv*gv.w);
}

// -------- merge attention partials + ams: rmsnorm(P0+P1, g) * U -> fp16 -----
__global__ void __launch_bounds__(256)
merge_ams(const float* __restrict__ P0, const float* __restrict__ P1,
          const float* __restrict__ g, const float* __restrict__ U,
          __half* __restrict__ Y)
{
    int r = blockIdx.x, t = threadIdx.x;
    float4 a = ((const float4*)(P0 + (size_t)r * D_MODEL))[t];
    float4 bb = ((const float4*)(P1 + (size_t)r * D_MODEL))[t];
    float4 v;
    v.x = a.x + bb.x; v.y = a.y + bb.y; v.z = a.z + bb.z; v.w = a.w + bb.w;
    float ss = v.x*v.x + v.y*v.y + v.z*v.z + v.w*v.w;
    #pragma unroll
    for (int o = 16; o; o >>= 1) ss += __shfl_xor_sync(0xffffffffu, ss, o);
    __shared__ float ws[8]; __shared__ float s_inv;
    if ((t & 31) == 0) ws[t >> 5] = ss;
    __syncthreads();
    if (t == 0) {
        float tot = 0.f;
        #pragma unroll
        for (int i = 0; i < 8; i++) tot += ws[i];
        s_inv = rsqrtf(tot * (1.0f / D_MODEL) + 1e-8f);
    }
    __syncthreads();
    float iv = s_inv;
    float4 gv = ((const float4*)g)[t];
    float4 uv = ((const float4*)(U + (size_t)r * D_MODEL))[t];
    size_t base = (size_t)r * D_MODEL + t*4;
    *(__half2*)(Y + base)     = __floats2half2_rn(v.x*iv*gv.x*uv.x, v.y*iv*gv.y*uv.y);
    *(__half2*)(Y + base + 2) = __floats2half2_rn(v.z*iv*gv.z*uv.z, v.w*iv*gv.w*uv.w);
}

// ===== fp16 1-pass HMMA GEMM (EPI 2): C = A@B^T + bias + R ================
#define SM_A    0
#define SM_B    16384
#define STAGE_B 49152

__global__ void __launch_bounds__(512, 1)
gemm_res(const __half* __restrict__ A, const __half* __restrict__ B,
         const float* __restrict__ bias, const float* __restrict__ R,
         float* __restrict__ C, int M, int N, int K)
{
    extern __shared__ __align__(128) char sm[];
    uint32_t sb = smem_u32(sm);
    int tid  = threadIdx.x;
    int wid  = tid >> 5;
    int lane = tid & 31;
    int wm = wid & 1, wn = wid >> 1;
    int bm = blockIdx.y * 128, bn = blockIdx.x * 256;
    int m0 = wm * 64, n0 = wn * 32;

    int laneRow = lane & 15;
    int laneK   = (lane >> 4) * 16;
    uint32_t xorA = (uint32_t)((laneRow & 7) << 4);

    float acc[4][4][4];
    #pragma unroll
    for (int i = 0; i < 4; i++)
        #pragma unroll
        for (int j = 0; j < 4; j++)
            #pragma unroll
            for (int q = 0; q < 4; q++) acc[i][j][q] = 0.f;

    const int NCH = K >> 6;

    auto load_stage = [&](int s, int chunk) {
        uint32_t st = sb + s * STAGE_B;
        int k0 = chunk * 64;
        #pragma unroll
        for (int it = 0; it < 2; it++) {
            int idx = tid + it * 512;
            int row = idx >> 3, c = idx & 7;
            uint32_t d = st + row * 128 + (uint32_t)((c * 16) ^ ((row & 7) << 4));
            size_t go = (size_t)(bm + row) * K + k0 + c * 8;
            cp16(d + SM_A, A + go);
        }
        #pragma unroll
        for (int it = 0; it < 4; it++) {
            int idx = tid + it * 512;
            int row = idx >> 3, c = idx & 7;
            uint32_t d = st + row * 128 + (uint32_t)((c * 16) ^ ((row & 7) << 4));
            size_t go = (size_t)(bn + row) * K + k0 + c * 8;
            cp16(d + SM_B, B + go);
        }
    };

    load_stage(0, 0);
    cp_commit();

    for (int chunk = 0; chunk < NCH; chunk++) {
        int s = chunk & 1;
        if (chunk + 1 < NCH) {
            load_stage(s ^ 1, chunk + 1);
            cp_commit();
            cp_wait1();
        } else {
            cp_wait0();
        }
        __syncthreads();

        uint32_t st = sb + s * STAGE_B;
        #pragma unroll
        for (int ks = 0; ks < 4; ks++) {
            uint32_t kb = (uint32_t)((ks * 32 + laneK) ^ xorA);
            uint32_t a[4][4], bf[2][4];
            #pragma unroll
            for (int i = 0; i < 4; i++)
                ldsm_x4(a[i], st + SM_A + (uint32_t)(m0 + i*16 + laneRow) * 128 + kb);
            #pragma unroll
            for (int p = 0; p < 2; p++)
                ldsm_x4(bf[p], st + SM_B + (uint32_t)(n0 + p*16 + laneRow) * 128 + kb);
            #pragma unroll
            for (int i = 0; i < 4; i++)
                #pragma unroll
                for (int j = 0; j < 4; j++)
                    mma16816h(acc[i][j], a[i], bf[j>>1][j&1], bf[j>>1][2 + (j&1)]);
        }
        __syncthreads();
    }

    int group = lane >> 2, tq = lane & 3;
    #pragma unroll
    for (int j = 0; j < 4; j++) {
        int n = bn + n0 + j*8 + tq*2;
        float bv0 = bias[n], bv1 = bias[n+1];
        #pragma unroll
        for (int i = 0; i < 4; i++) {
            int m = bm + m0 + i*16 + group;
            size_t off0 = (size_t)m * N + n;
            size_t off1 = (size_t)(m + 8) * N + n;
            float2 r0 = *(const float2*)(R + off0);
            float2 r1 = *(const float2*)(R + off1);
            *(float2*)(C + off0) = make_float2(acc[i][j][0] + bv0 + r0.x, acc[i][j][1] + bv1 + r0.y);
            *(float2*)(C + off1) = make_float2(acc[i][j][2] + bv0 + r1.x, acc[i][j][3] + bv1 + r1.y);
        }
    }
}

// ====== fused Q/K/V/U projection: fp16 1-pass, grid.z selects weight =======
__global__ void __launch_bounds__(512, 1)
proj4(const __half* __restrict__ A, const __half* __restrict__ WTG,
      const float* __restrict__ bq, const float* __restrict__ bk,
      const float* __restrict__ bv, const float* __restrict__ bu,
      __half* __restrict__ Qs, __half* __restrict__ Ks,
      __half* __restrict__ VT, float* __restrict__ Uf)
{
    extern __shared__ __align__(128) char sm[];
    uint32_t sb = smem_u32(sm);
    int tid  = threadIdx.x;
    int wid  = tid >> 5;
    int lane = tid & 31;
    int wm = wid & 1, wn = wid >> 1;
    int z  = blockIdx.z;
    int bm = blockIdx.y * 128, bn = blockIdx.x * 256;
    int m0 = wm * 64, n0 = wn * 32;
    const int K = 1024, N = 1024;

    const __half* B = WTG + (size_t)z * W1M;
    const float* bias = (z == 0) ? bq : (z == 1) ? bk : (z == 2) ? bv : bu;

    int laneRow = lane & 15;
    int laneK   = (lane >> 4) * 16;
    uint32_t xorA = (uint32_t)((laneRow & 7) << 4);

    float acc[4][4][4];
    #pragma unroll
    for (int i = 0; i < 4; i++)
        #pragma unroll
        for (int j = 0; j < 4; j++)
            #pragma unroll
            for (int q = 0; q < 4; q++) acc[i][j][q] = 0.f;

    const int NCH = K >> 6;

    auto load_stage = [&](int s, int chunk) {
        uint32_t st = sb + s * STAGE_B;
        int k0 = chunk * 64;
        #pragma unroll
        for (int it = 0; it < 2; it++) {
            int idx = tid + it * 512;
            int row = idx >> 3, c = idx & 7;
            uint32_t d = st + row * 128 + (uint32_t)((c * 16) ^ ((row & 7) << 4));
            size_t go = (size_t)(bm + row) * K + k0 + c * 8;
            cp16(d + SM_A, A + go);
        }
        #pragma unroll
        for (int it = 0; it < 4; it++) {
            int idx = tid + it * 512;
            int row = idx >> 3, c = idx & 7;
            uint32_t d = st + row * 128 + (uint32_t)((c * 16) ^ ((row & 7) << 4));
            size_t go = (size_t)(bn + row) * K + k0 + c * 8;
            cp16(d + SM_B, B + go);
        }
    };

    load_stage(0, 0);
    cp_commit();

    for (int chunk = 0; chunk < NCH; chunk++) {
        int s = chunk & 1;
        if (chunk + 1 < NCH) {
            load_stage(s ^ 1, chunk + 1);
            cp_commit();
            cp_wait1();
        } else {
            cp_wait0();
        }
        __syncthreads();

        uint32_t st = sb + s * STAGE_B;
        #pragma unroll
        for (int ks = 0; ks < 4; ks++) {
            uint32_t kb = (uint32_t)((ks * 32 + laneK) ^ xorA);
            uint32_t a[4][4], bf[2][4];
            #pragma unroll
            for (int i = 0; i < 4; i++)
                ldsm_x4(a[i], st + SM_A + (uint32_t)(m0 + i*16 + laneRow) * 128 + kb);
            #pragma unroll
            for (int p = 0; p < 2; p++)
                ldsm_x4(bf[p], st + SM_B + (uint32_t)(n0 + p*16 + laneRow) * 128 + kb);
            #pragma unroll
            for (int i = 0; i < 4; i++)
                #pragma unroll
                for (int j = 0; j < 4; j++)
                    mma16816h(acc[i][j], a[i], bf[j>>1][j&1], bf[j>>1][2 + (j&1)]);
        }
        __syncthreads();
    }

    int group = lane >> 2, tq = lane & 3;
    #pragma unroll
    for (int j = 0; j < 4; j++) {
        int n = bn + n0 + j*8 + tq*2;
        float bv0 = bias[n], bv1 = bias[n+1];
        #pragma unroll
        for (int i = 0; i < 4; i++) {
            int m = bm + m0 + i*16 + group;
            float v0 = acc[i][j][0] + bv0, v1 = acc[i][j][1] + bv1;
            float v2 = acc[i][j][2] + bv0, v3 = acc[i][j][3] + bv1;
            size_t off0 = (size_t)m * N + n;
            size_t off1 = (size_t)(m + 8) * N + n;
            if (z == 0) {
                *(__half2*)(Qs + off0) = __floats2half2_rn(v0, v1);
                *(__half2*)(Qs + off1) = __floats2half2_rn(v2, v3);
            } else if (z == 1) {
                *(__half2*)(Ks + off0) = __floats2half2_rn(v0, v1);
                *(__half2*)(Ks + off1) = __floats2half2_rn(v2, v3);
            } else if (z == 2) {
                int bi = m >> 11, tt = m & 2047;
                int hh = n >> 6,  dd = n & 63;
                size_t vb = ((size_t)((bi*16 + hh)*64 + dd)) * 2048 + tt;
                VT[vb]        = __float2half_rn(v0);
                VT[vb + 2048] = __float2half_rn(v1);
                VT[vb + 8]    = __float2half_rn(v2);
                VT[vb + 2056] = __float2half_rn(v3);
            } else {
                *(float2*)(Uf + off0) = make_float2(siluf(v0), siluf(v1));
                *(float2*)(Uf + off1) = make_float2(siluf(v2), siluf(v3));
            }
        }
    }
}

// ====== w1 GEMM + swiglu fusion: fp16 1-pass ================================
#define W_A   0
#define W_B1  16384
#define W_B2  32768
#define STAGE_W 49152

__global__ void __launch_bounds__(512, 1)
gemm_w1sg(const __half* __restrict__ A, const __half* __restrict__ B,
          const float* __restrict__ b1, __half* __restrict__ Y)
{
    extern __shared__ __align__(128) char sm[];
    uint32_t sb = smem_u32(sm);
    int tid  = threadIdx.x;
    int wid  = tid >> 5;
    int lane = tid & 31;
    int wm = wid & 1, wn = wid >> 1;
    int bm = blockIdx.y * 128, bn = blockIdx.x * 128;
    int m0 = wm * 64, n0 = wn * 16;
    const int K = 1024;

    int laneRow = lane & 15;
    int laneK   = (lane >> 4) * 16;
    uint32_t xorA = (uint32_t)((laneRow & 7) << 4);

    float acc1[4][2][4], acc2[4][2][4];
    #pragma unroll
    for (int i = 0; i < 4; i++)
        #pragma unroll
        for (int j = 0; j < 2; j++)
            #pragma unroll
            for (int q = 0; q < 4; q++) { acc1[i][j][q] = 0.f; acc2[i][j][q] = 0.f; }

    const int NCH = K >> 6;

    auto load_stage = [&](int s, int chunk) {
        uint32_t st = sb + s * STAGE_W;
        int k0 = chunk * 64;
        #pragma unroll
        for (int it = 0; it < 2; it++) {
            int idx = tid + it * 512;
            int row = idx >> 3, c = idx & 7;
            uint32_t d = st + row * 128 + (uint32_t)((c * 16) ^ ((row & 7) << 4));
            size_t goA  = (size_t)(bm + row) * K + k0 + c * 8;
            size_t goB1 = (size_t)(bn + row) * K + k0 + c * 8;
            size_t goB2 = (size_t)(1024 + bn + row) * K + k0 + c * 8;
            cp16(d + W_A,  A + goA);
            cp16(d + W_B1, B + goB1);
            cp16(d + W_B2, B + goB2);
        }
    };

    load_stage(0, 0);
    cp_commit();

    for (int chunk = 0; chunk < NCH; chunk++) {
        int s = chunk & 1;
        if (chunk + 1 < NCH) {
            load_stage(s ^ 1, chunk + 1);
            cp_commit();
            cp_wait1();
        } else {
            cp_wait0();
        }
        __syncthreads();

        uint32_t st = sb + s * STAGE_W;
        #pragma unroll
        for (int ks = 0; ks < 4; ks++) {
            uint32_t kb = (uint32_t)((ks * 32 + laneK) ^ xorA);
            uint32_t a[4][4], b1f[4], b2f[4];
            #pragma unroll
            for (int i = 0; i < 4; i++)
                ldsm_x4(a[i], st + W_A + (uint32_t)(m0 + i*16 + laneRow) * 128 + kb);
            ldsm_x4(b1f, st + W_B1 + (uint32_t)(n0 + laneRow) * 128 + kb);
            ldsm_x4(b2f, st + W_B2 + (uint32_t)(n0 + laneRow) * 128 + kb);
            #pragma unroll
            for (int i = 0; i < 4; i++)
                #pragma unroll
                for (int j = 0; j < 2; j++) {
                    mma16816h(acc1[i][j], a[i], b1f[j], b1f[2 + j]);
                    mma16816h(acc2[i][j], a[i], b2f[j], b2f[2 + j]);
                }
        }
        __syncthreads();
    }

    int group = lane >> 2, tq = lane & 3;
    #pragma unroll
    for (int j = 0; j < 2; j++) {
        int n = bn + n0 + j*8 + tq*2;
        float c10 = b1[n], c11 = b1[n+1];
        float c20 = b1[1024 + n], c21 = b1[1025 + n];
        #pragma unroll
        for (int i = 0; i < 4; i++) {
            int m = bm + m0 + i*16 + group;
            float y0 = siluf(acc1[i][j][0] + c10) * (acc2[i][j][0] + c20);
            float y1 = siluf(acc1[i][j][1] + c11) * (acc2[i][j][1] + c21);
            float y2 = siluf(acc1[i][j][2] + c10) * (acc2[i][j][2] + c20);
            float y3 = siluf(acc1[i][j][3] + c11) * (acc2[i][j][3] + c21);
            size_t off0 = (size_t)m * 1024 + n;
            size_t off1 = (size_t)(m + 8) * 1024 + n;
            *(__half2*)(Y + off0) = __floats2half2_rn(y0, y1);
            *(__half2*)(Y + off1) = __floats2half2_rn(y2, y3);
        }
    }
}

// ===== attention: fp16 1-pass, 256 thr / 64 q-rows, 2 CTAs per SM ===========
// Warps: 4 m-tiles (16 rows) x 2 key-halves. grid (32, 16, 4).
#define A_SQ  0u            // 8KB
#define A_SK  8192u         // + s*16384 (2 stages, 32KB)
#define A_SVT 40960u        // + s*16384 (2 stages, 32KB)
#define A_PB  73728u        // + s*512
#define A_RED A_SK          // reduction (16KB) reuses K area
#define ATT_SMEM 74752

__global__ void __launch_bounds__(256, 2)
attn_tc(const __half* __restrict__ Qs, const __half* __restrict__ Ks,
        const __half* __restrict__ VT,
        const float* __restrict__ PB, float* __restrict__ P0, float* __restrict__ P1)
{
    extern __shared__ __align__(128) char sm[];
    uint32_t sb = smem_u32(sm);
    int tid  = threadIdx.x;
    int wid  = tid >> 5;
    int lane = tid & 31;
    int qt = blockIdx.x, h = blockIdx.y;
    int b  = blockIdx.z & 1;
    int kv = blockIdx.z >> 1;
    float* P = kv ? P1 : P0;
    int ktBeg = kv * (SEQ/256);
    int mw = wid & 3;
    int kw = wid >> 2;
    int m0 = mw * 16;
    int ntb = kw * 4;

    int laneRow = lane & 15;
    int laneK   = (lane >> 4) * 16;
    uint32_t xorA = (uint32_t)((laneRow & 7) << 4);
    int group = lane >> 2, tq = lane & 3;
    uint32_t rowbK = (uint32_t)laneRow * 128;
    uint32_t rowbV = (uint32_t)laneRow * 256;

    auto load_q = [&]() {
        #pragma unroll
        for (int it = 0; it < 2; it++) {
            int idx = tid + it * 256;   // 512 chunks = 64 rows x 8
            int row = idx >> 3, c = idx & 7;
            uint32_t d = row * 128 + (uint32_t)((c * 16) ^ ((row & 7) << 4));
            size_t go = ((size_t)(b*SEQ + qt*64 + row)) * D_MODEL + h*64 + c*8;
            cp16(sb + A_SQ + d, Qs + go);
        }
    };
    auto load_kv = [&](int s, int kt) {
        uint32_t kbase = sb + A_SK + (uint32_t)s * 16384u;
        #pragma unroll
        for (int it = 0; it < 4; it++) {
            int ix = tid + it * 256;    // 1024 chunks = 128 rows x 8
            int row = ix >> 3, c = ix & 7;
            uint32_t d = row * 128 + (uint32_t)((c * 16) ^ ((row & 7) << 4));
            size_t go = ((size_t)(b*SEQ + kt*128 + row)) * D_MODEL + h*64 + c*8;
            cp16(kbase + d, Ks + go);
        }
        uint32_t vbase = sb + A_SVT + (uint32_t)s * 16384u;
        #pragma unroll
        for (int it = 0; it < 4; it++) {
            int ix = tid + it * 256;    // 1024 chunks = 64 rows x 16
            int row = ix >> 4, c = ix & 15;
            uint32_t d = row * 256 + (uint32_t)((c * 16) ^ ((row & 7) << 4));
            size_t go = ((size_t)((b*16 + h)*64 + row)) * 2048 + kt*128 + c*8;
            cp16(vbase + d, VT + go);
        }
        if (tid < 128) {
            float v = PB[(size_t)(kt*128 + tid) * N_HEADS + h];
            *(float*)(sm + A_PB + (uint32_t)s * 512u + tid * 4) = v;
        }
    };

    float accO[8][4];
    #pragma unroll
    for (int f = 0; f < 8; f++)
        #pragma unroll
        for (int q = 0; q < 4; q++) accO[f][q] = 0.f;

    load_q(); cp_commit();
    load_kv(0, ktBeg); cp_commit();
    cp_wait1();
    __syncthreads();

    uint32_t qf[4][4];
    #pragma unroll
    for (int ks = 0; ks < 4; ks++) {
        uint32_t kb = (uint32_t)((ks * 32 + laneK) ^ xorA);
        ldsm_x4(qf[ks], sb + A_SQ + (uint32_t)m0 * 128 + rowbK + kb);
    }

    const int NIT = SEQ/256;
    for (int it = 0; it < NIT; it++) {
        int kt = ktBeg + it;
        int s = it & 1;
        if (it + 1 < NIT) {
            load_kv(s ^ 1, kt + 1);
            cp_commit();
            cp_wait1();
        } else {
            cp_wait0();
        }
        __syncthreads();

        uint32_t kst = sb + A_SK + (uint32_t)s * 16384u + (uint32_t)ntb * 2048u;
        uint32_t vst = sb + A_SVT + (uint32_t)s * 16384u;
        const float* pbs = (const float*)(sm + A_PB + (uint32_t)s * 512u);

        #pragma unroll
        for (int c = 0; c < 2; c++) {
            float sc[4][4];
            #pragma unroll
            for (int f = 0; f < 4; f++)
                #pragma unroll
                for (int q = 0; q < 4; q++) sc[f][q] = 0.f;

            #pragma unroll
            for (int ks = 0; ks < 4; ks++) {
                uint32_t kb = (uint32_t)((ks * 32 + laneK) ^ xorA);
                #pragma unroll
                for (int t = 0; t < 2; t++) {
                    int nt = 2*c + t;
                    uint32_t kf[4];
                    ldsm_x4(kf, kst + (uint32_t)nt * 2048u + rowbK + kb);
                    mma16816h(sc[2*t],   qf[ks], kf[0], kf[2]);
                    mma16816h(sc[2*t+1], qf[ks], kf[1], kf[3]);
                }
            }

            uint32_t sf[2][4];
            #pragma unroll
            for (int t = 0; t < 2; t++) {
                int nt = 2*c + t;
                #pragma unroll
                for (int half = 0; half < 2; half++) {
                    int f = 2*t + half;
                    int tcol = ntb*16 + nt*16 + half*8 + tq*2;
                    float pb0 = pbs[tcol], pb1 = pbs[tcol + 1];
                    float w0 = siluf(sc[f][0] * 0.125f + pb0);
                    float w1 = siluf(sc[f][1] * 0.125f + pb1);
                    float w2 = siluf(sc[f][2] * 0.125f + pb0);
                    float w3 = siluf(sc[f][3] * 0.125f + pb1);
                    sf[t][half*2]     = pack_f16(w0, w1);
                    sf[t][half*2 + 1] = pack_f16(w2, w3);
                }
            }

            #pragma unroll
            for (int t = 0; t < 2; t++) {
                int gks = ntb + 2*c + t;
                uint32_t kb = (uint32_t)((gks * 32 + laneK) ^ xorA);
                #pragma unroll
                for (int dn = 0; dn < 4; dn++) {
                    uint32_t vf[4];
                    ldsm_x4(vf, vst + (uint32_t)dn * 4096u + rowbV + kb);
                    mma16816h(accO[2*dn],   sf[t], vf[0], vf[2]);
                    mma16816h(accO[2*dn+1], sf[t], vf[1], vf[3]);
                }
            }
        }
        __syncthreads();
    }

    // ---- merge key-half partials within CTA, write fp32 partial to P ----
    if (kw == 1) {
        float* red = (float*)(sm + A_RED) + ((size_t)mw * 32 + lane) * 32;
        #pragma unroll
        for (int f = 0; f < 8; f++) {
            red[f*4+0] = accO[f][0]; red[f*4+1] = accO[f][1];
            red[f*4+2] = accO[f][2]; red[f*4+3] = accO[f][3];
        }
    }
    __syncthreads();
    if (kw == 0) {
        const float* red = (const float*)(sm + A_RED) + ((size_t)mw * 32 + lane) * 32;
        #pragma unroll
        for (int dn = 0; dn < 4; dn++) {
            #pragma unroll
            for (int half = 0; half < 2; half++) {
                int f = 2*dn + half;
                float o0 = accO[f][0] + red[f*4+0];
                float o1 = accO[f][1] + red[f*4+1];
                float o2 = accO[f][2] + red[f*4+2];
                float o3 = accO[f][3] + red[f*4+3];
                int col = h*64 + dn*16 + half*8 + tq*2;
                int row = b*SEQ + qt*64 + m0 + group;
                *(float2*)(P + (size_t)row * D_MODEL + col) = make_float2(o0, o1);
                *(float2*)(P + (size_t)(row + 8) * D_MODEL + col) = make_float2(o2, o3);
            }
        }
    }
}

// ---------------- launch ----------------------------------------------------
extern "C" void kernel_launch(void* const* d_in, const int* in_sizes, int n_in,
                              void* d_out, int out_size)
{
    const float* x      = (const float*)d_in[0];
    const float* pb     = (const float*)d_in[2];
    const float* wq     = (const float*)d_in[3];
    const float* bq     = (const float*)d_in[4];
    const float* wk     = (const float*)d_in[5];
    const float* bk_    = (const float*)d_in[6];
    const float* wv     = (const float*)d_in[7];
    const float* bv     = (const float*)d_in[8];
    const float* wu     = (const float*)d_in[9];
    const float* bu     = (const float*)d_in[10];
    const float* g_ams  = (const float*)d_in[11];
    const float* w0     = (const float*)d_in[12];
    const float* b0     = (const float*)d_in[13];
    const float* w1     = (const float*)d_in[14];
    const float* b1     = (const float*)d_in[15];
    const float* w2     = (const float*)d_in[16];
    const float* b2     = (const float*)d_in[17];
    const float* g_mffn = (const float*)d_in[18];
    float* out = (float*)d_out;

    float *Qf, *Kf, *Vf, *Uf, *AOf, *P2f, *Of;
    __half *A1, *A2, *WT;
    cudaGetSymbolAddress((void**)&Qf,  g_Q);
    cudaGetSymbolAddress((void**)&Kf,  g_K);
    cudaGetSymbolAddress((void**)&Vf,  g_V);
    cudaGetSymbolAddress((void**)&Uf,  g_U);
    cudaGetSymbolAddress((void**)&AOf, g_AO);
    cudaGetSymbolAddress((void**)&P2f, g_P2);
    cudaGetSymbolAddress((void**)&Of,  g_O);
    cudaGetSymbolAddress((void**)&A1,  g_A1);
    cudaGetSymbolAddress((void**)&A2,  g_A2);
    cudaGetSymbolAddress((void**)&WT,  g_WT);

    __half *Qsb = (__half*)Qf;
    __half *Ksb = (__half*)Kf;
    __half *VTb = (__half*)Vf;

    __half *T0 = WT + (size_t)4*W1M;
    __half *T2 = WT + (size_t)5*W1M;
    __half *T1 = WT + (size_t)6*W1M;

    const int GSM = 2 * STAGE_B;   // 98304
    cudaFuncSetAttribute(gemm_res,  cudaFuncAttributeMaxDynamicSharedMemorySize, GSM);
    cudaFuncSetAttribute(proj4,     cudaFuncAttributeMaxDynamicSharedMemorySize, GSM);
    cudaFuncSetAttribute(gemm_w1sg, cudaFuncAttributeMaxDynamicSharedMemorySize, 2*STAGE_W);
    cudaFuncSetAttribute(attn_tc,   cudaFuncAttributeMaxDynamicSharedMemorySize, ATT_SMEM);

    wtcvt_all<<<8192, dim3(32, 8)>>>(wq, wk, wv, wu, w0, w2, w1, WT);
    rmsnorm_tc<<<M_ROWS, 256>>>(x, g_ams, A1);
    proj4<<<dim3(4, 32, 4), 512, GSM>>>(A1, WT, bq, bk_, bv, bu, Qsb, Ksb, VTb, Uf);
    attn_tc<<<dim3(SEQ/64, N_HEADS, BATCH*2), 256, ATT_SMEM>>>(Qsb, Ksb, VTb, pb, AOf, P2f);
    merge_ams<<<M_ROWS, 256>>>(AOf, P2f, g_ams, Uf, A2);
    gemm_res<<<dim3(4, 32), 512, GSM>>>(A2, T0, b0, x, Of, M_ROWS, 1024, 1024);
    rmsnorm_tc<<<M_ROWS, 256>>>(Of, g_mffn, A1);
    gemm_w1sg<<<dim3(8, 32), 512, 2*STAGE_W>>>(A1, T1, b1, A2);
    gemm_res<<<dim3(4, 32), 512, GSM>>>(A2, T2, b2, Of, out, M_ROWS, 1024, 1024);
}